// round 11
// baseline (speedup 1.0000x reference)
#include <cuda_runtime.h>
#include <cuda_fp16.h>
#include <cstddef>
#include <cstdint>

// Problem constants
#define BB   256
#define SS   100
#define II   128
#define HH   1024
#define OO   128
#define LL   2
#define UU   1344
#define KK   4
#define NTOK (BB * SS)          // 25600
#define H4   (4 * HH)           // 4096
#define U2   (2 * UU)           // 2688

// ---------------------------------------------------------------------------
// Scratch layout (identical to round 10).
#define W_IFS  ((size_t)LL * 2 * HH * HH)   // 4,194,304
#define W_RT   ((size_t)LL * H4 * HH)       // 8,388,608 (transposed [l][n][k])
#define W_UP   ((size_t)LL * U2 * HH)       // 5,505,024 (g/v row-interleaved)
#define W_DN   ((size_t)LL * HH * UU)       // 2,752,512
#define W_EMB  ((size_t)HH * II)            // 131,072
#define W_TOT  (2 * W_IFS + W_RT + W_UP + W_DN + W_EMB)
#define PREP_N (W_TOT + (size_t)NTOK * II)  // + x conversion
#define SCRATCH_FLOATS 146000000ULL
__device__ float g_scratch[SCRATCH_FLOATS];

// monotonic grid-barrier counter (never reset; race-free).
__device__ unsigned g_bar_cnt = 0;

// ---------------------------------------------------------------------------
__device__ __forceinline__ void cp16(void* s, const void* g)
{
    uint32_t sa = (uint32_t)__cvta_generic_to_shared(s);
    asm volatile("cp.async.cg.shared.global [%0], [%1], 16;\n" :: "r"(sa), "l"(g));
}
__device__ __forceinline__ void cp_commit()
{
    asm volatile("cp.async.commit_group;\n" ::);
}
template<int N>
__device__ __forceinline__ void cp_wait()
{
    asm volatile("cp.async.wait_group %0;\n" :: "n"(N));
}

__device__ __forceinline__ void mma_f16(float* d, const uint32_t* a, const uint32_t* b)
{
    asm volatile(
        "mma.sync.aligned.m16n8k16.row.col.f32.f16.f16.f32 "
        "{%0,%1,%2,%3},{%4,%5,%6,%7},{%8,%9},{%0,%1,%2,%3};"
        : "+f"(d[0]), "+f"(d[1]), "+f"(d[2]), "+f"(d[3])
        : "r"(a[0]), "r"(a[1]), "r"(a[2]), "r"(a[3]),
          "r"(b[0]), "r"(b[1]));
}

#define LDSM4(r0, r1, r2, r3, addr) \
    asm volatile("ldmatrix.sync.aligned.m8n8.x4.shared.b16 {%0,%1,%2,%3}, [%4];" \
                 : "=r"(r0), "=r"(r1), "=r"(r2), "=r"(r3) : "r"(addr))

__device__ __forceinline__ float gelu_exact(float g)
{
    return 0.5f * g * (1.f + erff(g * 0.7071067811865476f));
}

// ---------------------------------------------------------------------------
// fp16 tensor-core GEMM.  C[M,N] = A[M,K] * B^T, B stored [N,K] (halfs).
// 128x128x32 tiles, 256 threads, 3-stage cp.async pipeline (61,440 B smem ->
// 3 CTAs/SM; launch_bounds(256,3) caps regs so RF also fits 3 CTAs).
// OUTH: C is half. GELU (implies OUTH): adjacent col pairs (g,v) ->
//   gelu(g)*v into half-width C (ldc = N/2). BIAS/ACC: fp32 C paths.
template<bool OUTH, bool ACC, bool BIAS, bool GELU>
__global__ void __launch_bounds__(256, 3)
gemm_f16_kernel(const __half* __restrict__ A, int lda,
                const __half* __restrict__ B, int ldb,
                void* __restrict__ Cv, int ldc,
                const float* __restrict__ bias, int K)
{
    constexpr int BM = 128, BK = 32, STR = 40, S = 3;
    extern __shared__ __half smh[];
    __half* As = smh;                     // [S][128][40]
    __half* Bs = smh + S * BM * STR;      // [S][128][40]

    const int tid  = threadIdx.x;
    const int lane = tid & 31;
    const int warp = tid >> 5;
    const int wm = (warp >> 2) * 64;
    const int wn = (warp & 3) * 32;
    const int lr = lane >> 2;
    const int lc = lane & 3;
    const long bm0 = (long)blockIdx.y * BM;
    const long bn0 = (long)blockIdx.x * 128;

    const int q_row = (lane & 7) + ((lane >> 3) & 1) * 8;
    const int q_col = (lane >> 4) * 8;    // halfs
    const uint32_t as_base = (uint32_t)__cvta_generic_to_shared(As);
    const uint32_t bs_base = (uint32_t)__cvta_generic_to_shared(Bs);

    float acc[4][4][4];
#pragma unroll
    for (int mi = 0; mi < 4; mi++)
#pragma unroll
        for (int ni = 0; ni < 4; ni++)
#pragma unroll
            for (int t = 0; t < 4; t++) acc[mi][ni][t] = 0.f;

    auto prefetch = [&](int s, int k0) {
        __half* as = As + s * BM * STR;
        __half* bs = Bs + s * BM * STR;
#pragma unroll
        for (int j = 0; j < 2; j++) {
            int i = tid + j * 256;
            int row = i >> 2, off = (i & 3) * 8;
            cp16(as + row * STR + off, A + (bm0 + row) * (long)lda + k0 + off);
        }
#pragma unroll
        for (int j = 0; j < 2; j++) {
            int i = tid + j * 256;
            int row = i >> 2, off = (i & 3) * 8;
            cp16(bs + row * STR + off, B + (bn0 + row) * (long)ldb + k0 + off);
        }
    };

    auto compute = [&](int s) {
#pragma unroll
        for (int kk = 0; kk < BK; kk += 16) {
            uint32_t a[4][4], b[4][2];
#pragma unroll
            for (int mi = 0; mi < 4; mi++) {
                uint32_t addr = as_base +
                    ((s * BM + wm + mi * 16 + q_row) * STR + kk + q_col) * 2;
                LDSM4(a[mi][0], a[mi][1], a[mi][2], a[mi][3], addr);
            }
#pragma unroll
            for (int np = 0; np < 2; np++) {
                uint32_t r0, r1, r2, r3;
                uint32_t addr = bs_base +
                    ((s * BM + wn + np * 16 + q_row) * STR + kk + q_col) * 2;
                LDSM4(r0, r1, r2, r3, addr);
                b[2 * np][0] = r0; b[2 * np + 1][0] = r1;
                b[2 * np][1] = r2; b[2 * np + 1][1] = r3;
            }
#pragma unroll
            for (int mi = 0; mi < 4; mi++)
#pragma unroll
                for (int ni = 0; ni < 4; ni++)
                    mma_f16(acc[mi][ni], a[mi], b[ni]);
        }
    };

    const int NIT = K / BK;
#pragma unroll
    for (int s = 0; s < S - 1; s++) {
        if (s < NIT) prefetch(s, s * BK);
        cp_commit();
    }
    for (int it = 0; it < NIT; ++it) {
        cp_wait<S - 2>();
        __syncthreads();
        int nf = it + S - 1;
        if (nf < NIT) prefetch(nf % S, nf * BK);
        cp_commit();
        compute(it % S);
    }

    // Epilogue
#pragma unroll
    for (int mi = 0; mi < 4; mi++) {
        long r0 = bm0 + wm + mi * 16 + lr;
#pragma unroll
        for (int ni = 0; ni < 4; ni++) {
            long c0 = bn0 + wn + ni * 8 + lc * 2;
            if (GELU) {
                __half* C = (__half*)Cv;
                long j = c0 >> 1;
                C[r0 * (long)ldc + j] =
                    __float2half(gelu_exact(acc[mi][ni][0]) * acc[mi][ni][1]);
                C[(r0 + 8) * (long)ldc + j] =
                    __float2half(gelu_exact(acc[mi][ni][2]) * acc[mi][ni][3]);
            } else if (OUTH) {
                __half* C = (__half*)Cv;
                *(__half2*)(C + r0 * (long)ldc + c0) =
                    __floats2half2_rn(acc[mi][ni][0], acc[mi][ni][1]);
                *(__half2*)(C + (r0 + 8) * (long)ldc + c0) =
                    __floats2half2_rn(acc[mi][ni][2], acc[mi][ni][3]);
            } else {
                float* C = (float*)Cv;
                float2* p0 = (float2*)(C + r0 * (long)ldc + c0);
                float2* p1 = (float2*)(C + (r0 + 8) * (long)ldc + c0);
                float b0 = 0.f, b1 = 0.f;
                if (BIAS) { b0 = bias[c0]; b1 = bias[c0 + 1]; }
                if (ACC) {
                    float2 v0 = *p0, v1 = *p1;
                    v0.x += acc[mi][ni][0] + b0; v0.y += acc[mi][ni][1] + b1;
                    v1.x += acc[mi][ni][2] + b0; v1.y += acc[mi][ni][3] + b1;
                    *p0 = v0; *p1 = v1;
                } else {
                    *p0 = make_float2(acc[mi][ni][0] + b0, acc[mi][ni][1] + b1);
                    *p1 = make_float2(acc[mi][ni][2] + b0, acc[mi][ni][3] + b1);
                }
            }
        }
    }
}

// ---------------------------------------------------------------------------
// Persistent fused sLSTM scan kernel, fp16 GEMM (m16n8k16), BK=64.
// 128 CTAs: (mt = bid>>5 in [0,4): 64 batch rows; ht = bid&31: 32 h).
// B = Rt [n][k] rows gathered per ht. State (c,n,m) fp32 in registers;
// y fp16 double-buffered in scratch.
#define SC_CTAS 128

// Race-free monotonic grid barrier (ticket / epoch; no reset, no phase word).
__device__ __forceinline__ void grid_bar()
{
    __syncthreads();
    __threadfence();
    if (threadIdx.x == 0) {
        unsigned my = atomicAdd(&g_bar_cnt, 1u);
        unsigned target = (my / SC_CTAS + 1u) * SC_CTAS;
        while (*((volatile unsigned*)&g_bar_cnt) < target) { }
    }
    __syncthreads();
    __threadfence();
}

__global__ void __launch_bounds__(256)
scan_kernel(const __half* __restrict__ Wx, const __half* __restrict__ Rt,
            const float* __restrict__ cb,
            __half* __restrict__ yb0, __half* __restrict__ yb1,
            float* __restrict__ yseq)
{
    extern __shared__ __half smh[];
    constexpr int STR = 72, BK = 64, RSTR = 132;
    __half* As = smh;                     // [2][64][72]  =  9,216 halfs
    __half* Bs = smh + 2 * 64 * STR;      // [2][128][72] = 18,432 halfs
    float*  rawS = (float*)smh;           // [64][132] fp32 = 33,792 B (aliases
                                          //  As/Bs after GEMM; smem covers both)

    const int tid  = threadIdx.x;
    const int lane = tid & 31;
    const int warp = tid >> 5;
    const int wm = (warp >> 2) * 32;      // 2 m-warps x 32
    const int wn = (warp & 3) * 32;       // 4 n-warps x 32
    const int lr = lane >> 2;
    const int lc = lane & 3;
    const int mt = blockIdx.x >> 5;
    const int ht = blockIdx.x & 31;

    const int q_row = (lane & 7) + ((lane >> 3) & 1) * 8;
    const int q_col = (lane >> 4) * 8;
    const uint32_t as_base = (uint32_t)__cvta_generic_to_shared(As);
    const uint32_t bs_base = (uint32_t)__cvta_generic_to_shared(Bs);

    const int hl = tid & 31;
    const int rg = tid >> 5;
    const int h  = ht * 32 + hl;
    const long acol = (long)mt * 64;

    float cbv[4];
#pragma unroll
    for (int g = 0; g < 4; g++) cbv[g] = cb[g * 1024 + h];

    float stc[8], stn[8], stm[8];
#pragma unroll
    for (int j = 0; j < 8; j++) { stc[j] = 0.f; stn[j] = 0.f; stm[j] = 0.f; }

    // zero this CTA's slice of yb0 (2048 halfs = 256 threads x 16B)
    {
        uint4 z = make_uint4(0u, 0u, 0u, 0u);
        *(uint4*)(yb0 + (size_t)blockIdx.x * 2048 + tid * 8) = z;
    }
    grid_bar();

    for (int s = 0; s < SS; s++) {
        const __half* ycur = (s & 1) ? yb1 : yb0;
        __half*       ynxt = (s & 1) ? yb0 : yb1;

        float acc[2][4][4];
#pragma unroll
        for (int mi = 0; mi < 2; mi++)
#pragma unroll
            for (int ni = 0; ni < 4; ni++)
#pragma unroll
                for (int t = 0; t < 4; t++) acc[mi][ni][t] = 0.f;

        auto prefetch = [&](int buf, int k0) {
            // A: 64 rows x 64 halfs = 512 chunks (2/thread)
#pragma unroll
            for (int j = 0; j < 2; j++) {
                int i = tid + j * 256;
                int row = i >> 3, off = (i & 7) * 8;
                cp16(&As[(buf * 64 + row) * STR + off],
                     ycur + (acol + row) * 1024 + k0 + off);
            }
            // B: 128 gathered n-rows x 64 halfs = 1024 chunks (4/thread)
#pragma unroll
            for (int j = 0; j < 4; j++) {
                int i = tid + j * 256;
                int nt = i >> 3, off = (i & 7) * 8;
                long nglob = (long)(nt >> 5) * 1024 + ht * 32 + (nt & 31);
                cp16(&Bs[(buf * 128 + nt) * STR + off],
                     Rt + nglob * 1024 + k0 + off);
            }
        };

        auto compute = [&](int buf) {
#pragma unroll
            for (int kk = 0; kk < BK; kk += 16) {
                uint32_t a[2][4], b[4][2];
#pragma unroll
                for (int mi = 0; mi < 2; mi++) {
                    uint32_t addr = as_base +
                        ((buf * 64 + wm + mi * 16 + q_row) * STR + kk + q_col) * 2;
                    LDSM4(a[mi][0], a[mi][1], a[mi][2], a[mi][3], addr);
                }
#pragma unroll
                for (int np = 0; np < 2; np++) {
                    uint32_t r0, r1, r2, r3;
                    uint32_t addr = bs_base +
                        ((buf * 128 + wn + np * 16 + q_row) * STR + kk + q_col) * 2;
                    LDSM4(r0, r1, r2, r3, addr);
                    b[2 * np][0] = r0; b[2 * np + 1][0] = r1;
                    b[2 * np][1] = r2; b[2 * np + 1][1] = r3;
                }
#pragma unroll
                for (int mi = 0; mi < 2; mi++)
#pragma unroll
                    for (int ni = 0; ni < 4; ni++)
                        mma_f16(acc[mi][ni], a[mi], b[ni]);
            }
        };

        constexpr int NIT = 1024 / BK;   // 16
        prefetch(0, 0);
        cp_commit();
        for (int it = 0; it < NIT; ++it) {
            if (it + 1 < NIT) {
                prefetch((it + 1) & 1, (it + 1) * BK);
                cp_commit();
                cp_wait<1>();
            } else {
                cp_wait<0>();
            }
            __syncthreads();
            compute(it & 1);
            __syncthreads();
        }

        // stage raw tile to smem (aliases As/Bs; GEMM done)
#pragma unroll
        for (int mi = 0; mi < 2; mi++) {
            int r0 = wm + mi * 16 + lr;
#pragma unroll
            for (int ni = 0; ni < 4; ni++) {
                int c0 = wn + ni * 8 + lc * 2;
                *(float2*)&rawS[r0 * RSTR + c0] =
                    make_float2(acc[mi][ni][0], acc[mi][ni][1]);
                *(float2*)&rawS[(r0 + 8) * RSTR + c0] =
                    make_float2(acc[mi][ni][2], acc[mi][ni][3]);
            }
        }
        __syncthreads();

        // fused gate update: 8 (b,h) pairs per thread, state in registers
#pragma unroll
        for (int j = 0; j < 8; j++) {
            int row = rg * 8 + j;
            long bb = acol + row;
            const __half* wx = Wx + ((bb * SS + s) << 12) + h;

            float ir  = rawS[row * RSTR + hl]      + __half2float(wx[0])    + cbv[0];
            float fr  = rawS[row * RSTR + 32 + hl] + __half2float(wx[1024]) + cbv[1];
            float zr  = rawS[row * RSTR + 64 + hl] + __half2float(wx[2048]) + cbv[2];
            float orr = rawS[row * RSTR + 96 + hl] + __half2float(wx[3072]) + cbv[3];

            float logsig = (fr >= 0.f) ? -log1pf(__expf(-fr))
                                       : (fr - log1pf(__expf(fr)));
            float lfm  = stm[j] + logsig;
            float mnew = (stn[j] == 0.f) ? ir : fmaxf(ir, lfm);
            float ig   = __expf(ir  - mnew);
            float fg   = __expf(lfm - mnew);
            float ez   = __expf(-2.f * fabsf(zr));
            float tz   = copysignf((1.f - ez) / (1.f + ez), zr);
            float cnew = fg * stc[j] + ig * tz;
            float nnew = fg * stn[j] + ig;
            float og   = 1.f / (1.f + __expf(-orr));
            float ynew = og * cnew / nnew;

            stc[j] = cnew;
            stn[j] = nnew;
            stm[j] = mnew;
            ynxt[bb * 1024 + h] = __float2half(ynew);
            yseq[(bb * SS + s) * 1024 + h] = ynew;
        }

        grid_bar();
    }
}

// ---------------------------------------------------------------------------
// fp32 SIMT GEMM (fc only).
template<int BM, int BN, int BK, int TM, int TN>
__global__ void __launch_bounds__(256)
gemm_fc_kernel(const float* __restrict__ A, int lda,
               const float* __restrict__ B, int ldb,
               float* __restrict__ C, int ldc,
               const float* __restrict__ bias, int K)
{
    constexpr int TX = BN / TN;
    constexpr int TY = BM / TM;
    constexpr int NT = TX * TY;

    __shared__ float As[BK][BM + 4];
    __shared__ float Bs[BK][BN + 4];

    const int tid = threadIdx.x;
    const int tx = tid % TX;
    const int ty = tid / TX;
    const long bm0 = (long)blockIdx.y * BM;
    const long bn0 = (long)blockIdx.x * BN;

    float acc[TM][TN];
#pragma unroll
    for (int i = 0; i < TM; i++)
#pragma unroll
        for (int j = 0; j < TN; j++) acc[i][j] = 0.f;

    for (int k0 = 0; k0 < K; k0 += BK) {
#pragma unroll
        for (int i = tid * 4; i < BM * BK; i += NT * 4) {
            int r = i / BK, kk = i % BK;
            float4 v = *(const float4*)(A + (bm0 + r) * (long)lda + (k0 + kk));
            As[kk + 0][r] = v.x; As[kk + 1][r] = v.y;
            As[kk + 2][r] = v.z; As[kk + 3][r] = v.w;
        }
#pragma unroll
        for (int i = tid * 4; i < BN * BK; i += NT * 4) {
            int r = i / BK, kk = i % BK;
            float4 v = *(const float4*)(B + (bn0 + r) * (long)ldb + (k0 + kk));
            Bs[kk + 0][r] = v.x; Bs[kk + 1][r] = v.y;
            Bs[kk + 2][r] = v.z; Bs[kk + 3][r] = v.w;
        }
        __syncthreads();

#pragma unroll
        for (int kk = 0; kk < BK; kk++) {
            float a[TM], b[TN];
#pragma unroll
            for (int i = 0; i < TM; i += 4)
                *(float4*)&a[i] = *(const float4*)&As[kk][ty * TM + i];
#pragma unroll
            for (int j = 0; j < TN; j += 4)
                *(float4*)&b[j] = *(const float4*)&Bs[kk][tx * TN + j];
#pragma unroll
            for (int i = 0; i < TM; i++)
#pragma unroll
                for (int j = 0; j < TN; j++)
                    acc[i][j] = fmaf(a[i], b[j], acc[i][j]);
        }
        __syncthreads();
    }

#pragma unroll
    for (int i = 0; i < TM; i++) {
        long row = bm0 + ty * TM + i;
#pragma unroll
        for (int j = 0; j < TN; j++) {
            long col = bn0 + tx * TN + j;
            C[row * (long)ldc + col] = acc[i][j] + bias[col];
        }
    }
}

// ---------------------------------------------------------------------------
__device__ __forceinline__ void warp_reduce2(float& s, float& ss)
{
#pragma unroll
    for (int o = 16; o > 0; o >>= 1) {
        s  += __shfl_xor_sync(0xFFFFFFFFu, s,  o);
        ss += __shfl_xor_sync(0xFFFFFFFFu, ss, o);
    }
}

// out = LN(x)*w ; OUTH: write halfs, else floats. Warp-per-row (1024 wide).
template<bool OUTH>
__global__ void ln_warp_kernel(const float* __restrict__ x, size_t xs,
                               const float* __restrict__ w,
                               void* __restrict__ outv, size_t os)
{
    int warp = threadIdx.x >> 5, lane = threadIdx.x & 31;
    size_t row = (size_t)blockIdx.x * 8 + warp;
    const float* xr = x + row * xs;
    float4 v[8];
    float s = 0.f, ss = 0.f;
#pragma unroll
    for (int i = 0; i < 8; i++) {
        v[i] = *(const float4*)(xr + i * 128 + lane * 4);
        s  += v[i].x + v[i].y + v[i].z + v[i].w;
        ss += v[i].x * v[i].x + v[i].y * v[i].y + v[i].z * v[i].z + v[i].w * v[i].w;
    }
    warp_reduce2(s, ss);
    float mu  = s * (1.f / 1024.f);
    float var = fmaxf(ss * (1.f / 1024.f) - mu * mu, 0.f);
    float rs  = rsqrtf(var + 1e-5f);
#pragma unroll
    for (int i = 0; i < 8; i++) {
        int c = i * 128 + lane * 4;
        float4 wv = *(const float4*)(w + c);
        float o0 = (v[i].x - mu) * rs * wv.x;
        float o1 = (v[i].y - mu) * rs * wv.y;
        float o2 = (v[i].z - mu) * rs * wv.z;
        float o3 = (v[i].w - mu) * rs * wv.w;
        if (OUTH) {
            __half2* op = (__half2*)((__half*)outv + row * os + c);
            op[0] = __floats2half2_rn(o0, o1);
            op[1] = __floats2half2_rn(o2, o3);
        } else {
            *(float4*)((float*)outv + row * os + c) = make_float4(o0, o1, o2, o3);
        }
    }
}

// Fused: h += LN(yseq)*gn ; fn = LN(h_new)*ln2 (half out). Warp-per-row.
__global__ void lnadd_ln2_kernel(const float* __restrict__ yseq,
                                 const float* __restrict__ gn,
                                 const float* __restrict__ ln2,
                                 float* __restrict__ h,
                                 __half* __restrict__ fn)
{
    int warp = threadIdx.x >> 5, lane = threadIdx.x & 31;
    size_t row = (size_t)blockIdx.x * 8 + warp;
    const float* yr = yseq + row * HH;
    float* hr = h + row * HH;
    float4 v[8], hv[8];
    float s = 0.f, ss = 0.f;
#pragma unroll
    for (int i = 0; i < 8; i++) {
        v[i] = *(const float4*)(yr + i * 128 + lane * 4);
        s  += v[i].x + v[i].y + v[i].z + v[i].w;
        ss += v[i].x * v[i].x + v[i].y * v[i].y + v[i].z * v[i].z + v[i].w * v[i].w;
    }
    warp_reduce2(s, ss);
    float mu  = s * (1.f / 1024.f);
    float var = fmaxf(ss * (1.f / 1024.f) - mu * mu, 0.f);
    float rs  = rsqrtf(var + 1e-5f);
    float s2 = 0.f, ss2 = 0.f;
#pragma unroll
    for (int i = 0; i < 8; i++) {
        int c = i * 128 + lane * 4;
        float4 gv = *(const float4*)(gn + c);
        hv[i] = *(float4*)(hr + c);
        hv[i].x += (v[i].x - mu) * rs * gv.x;
        hv[i].y += (v[i].y - mu) * rs * gv.y;
        hv[i].z += (v[i].z - mu) * rs * gv.z;
        hv[i].w += (v[i].w - mu) * rs * gv.w;
        *(float4*)(hr + c) = hv[i];
        s2  += hv[i].x + hv[i].y + hv[i].z + hv[i].w;
        ss2 += hv[i].x * hv[i].x + hv[i].y * hv[i].y
             + hv[i].z * hv[i].z + hv[i].w * hv[i].w;
    }
    warp_reduce2(s2, ss2);
    float mu2  = s2 * (1.f / 1024.f);
    float var2 = fmaxf(ss2 * (1.f / 1024.f) - mu2 * mu2, 0.f);
    float rs2  = rsqrtf(var2 + 1e-5f);
#pragma unroll
    for (int i = 0; i < 8; i++) {
        int c = i * 128 + lane * 4;
        float4 wv = *(const float4*)(ln2 + c);
        __half2* op = (__half2*)(fn + row * HH + c);
        op[0] = __floats2half2_rn((hv[i].x - mu2) * rs2 * wv.x,
                                  (hv[i].y - mu2) * rs2 * wv.y);
        op[1] = __floats2half2_rn((hv[i].z - mu2) * rs2 * wv.z,
                                  (hv[i].w - mu2) * rs2 * wv.w);
    }
}

// ---------------------------------------------------------------------------
// Depthwise causal conv (K=4) + SiLU; fp16 in/out, fp32 math.
__global__ void conv_silu_kernel(const __half* __restrict__ xn,
                                 const float* __restrict__ cw,
                                 const float* __restrict__ cb,
                                 __half* __restrict__ xc)
{
    size_t q = (size_t)blockIdx.x * blockDim.x + threadIdx.x; // < NTOK*H/4
    int hq = (int)(q & 255);
    size_t t = q >> 8;
    int s = (int)(t % SS);
    int h = hq * 4;
    size_t base = t * HH + h;

    float4 w0 = *(const float4*)(cw + (size_t)h * 4);
    float4 w1 = *(const float4*)(cw + (size_t)(h + 1) * 4);
    float4 w2 = *(const float4*)(cw + (size_t)(h + 2) * 4);
    float4 w3 = *(const float4*)(cw + (size_t)(h + 3) * 4);
    float4 bv = *(const float4*)(cb + h);
    float a0 = bv.x, a1 = bv.y, a2 = bv.z, a3 = bv.w;

#pragma unroll
    for (int k = 0; k < 4; k++) {
        int sp = s - 3 + k;
        if (sp >= 0) {
            const __half2* xp = (const __half2*)(xn + base + (long)(k - 3) * HH);
            float2 x01 = __half22float2(xp[0]);
            float2 x23 = __half22float2(xp[1]);
            a0 = fmaf(x01.x, ((const float*)&w0)[k], a0);
            a1 = fmaf(x01.y, ((const float*)&w1)[k], a1);
            a2 = fmaf(x23.x, ((const float*)&w2)[k], a2);
            a3 = fmaf(x23.y, ((const float*)&w3)[k], a3);
        }
    }
    __half2* op = (__half2*)(xc + base);
    op[0] = __floats2half2_rn(a0 / (1.f + __expf(-a0)), a1 / (1.f + __expf(-a1)));
    op[1] = __floats2half2_rn(a2 / (1.f + __expf(-a2)), a3 / (1.f + __expf(-a3)));
}

// ---------------------------------------------------------------------------
// One-shot prep: convert all weights to fp16 (stack i/f and z/o, transpose R
// to [n][k], interleave ff_up g/v rows, copy emb_w) and convert x to fp16.
__global__ void prep_kernel(const float* __restrict__ Wi,
                            const float* __restrict__ Wf,
                            const float* __restrict__ Wz,
                            const float* __restrict__ Wo,
                            const float* __restrict__ R,
                            const float* __restrict__ up,
                            const float* __restrict__ dn,
                            const float* __restrict__ embw,
                            const float* __restrict__ x,
                            __half* __restrict__ wdst,
                            __half* __restrict__ xdst)
{
    size_t i = (size_t)blockIdx.x * 256 + threadIdx.x;
    if (i >= PREP_N) return;
    const size_t HHHH = (size_t)HH * HH;
    if (i >= W_TOT) {                      // x conversion
        size_t j = i - W_TOT;
        xdst[j] = __float2half(x[j]);
        return;
    }
    float v;
    if (i < W_IFS) {
        size_t l = i / (2 * HHHH), r = i % (2 * HHHH);
        v = (r < HHHH ? Wi : Wf)[l * HHHH + (r % HHHH)];
    } else if (i < 2 * W_IFS) {
        size_t j = i - W_IFS;
        size_t l = j / (2 * HHHH), r = j % (2 * HHHH);
        v = (r < HHHH ? Wz : Wo)[l * HHHH + (r % HHHH)];
    } else if (i < 2 * W_IFS + W_RT) {
        size_t j = i - 2 * W_IFS;
        size_t l = j / ((size_t)H4 * HH);
        size_t rem = j % ((size_t)H4 * HH);
        size_t n = rem / HH, k = rem % HH;       // dst [n][k]
        v = R[l * (size_t)HH * H4 + k * H4 + n]; // src [k][n]
    } else if (i < 2 * W_IFS + W_RT + W_UP) {
        size_t j = i - 2 * W_IFS - W_RT;
        size_t l = j / ((size_t)U2 * HH);
        size_t rem = j % ((size_t)U2 * HH);
        size_t row = rem / HH, col = rem % HH;
        size_t u = row >> 1, half = row & 1;     // even rows = g, odd = v
        v = up[l * (size_t)U2 * HH + (half * UU + u) * HH + col];
    } else if (i < 2 * W_IFS + W_RT + W_UP + W_DN) {
        v = dn[i - 2 * W_IFS - W_RT - W_UP];
    } else {
        v = embw[i - 2 * W_IFS - W_RT - W_UP - W_DN];
    }
    wdst[i] = __float2half(v);
}

// ---------------------------------------------------------------------------
extern "C" void kernel_launch(void* const* d_in, const int* in_sizes, int n_in,
                              void* d_out, int out_size)
{
    (void)in_sizes; (void)n_in; (void)out_size;

    const float* x      = (const float*)d_in[0];
    const float* emb_w  = (const float*)d_in[1];
    const float* emb_b  = (const float*)d_in[2];
    const float* conv_w = (const float*)d_in[3];
    const float* conv_b = (const float*)d_in[4];
    const float* Wi     = (const float*)d_in[5];
    const float* Wf     = (const float*)d_in[6];
    const float* Wz     = (const float*)d_in[7];
    const float* Wo     = (const float*)d_in[8];
    const float* R      = (const float*)d_in[9];
    const float* cell_b = (const float*)d_in[10];
    const float* gn_w   = (const float*)d_in[11];
    const float* ln1_w  = (const float*)d_in[12];
    const float* ln2_w  = (const float*)d_in[13];
    const float* ff_up  = (const float*)d_in[14];
    const float* ff_dn  = (const float*)d_in[15];
    const float* post_w = (const float*)d_in[16];
    const float* fc_w   = (const float*)d_in[17];
    const float* fc_b   = (const float*)d_in[18];
    float* out = (float*)d_out;

    float* S_;
    cudaGetSymbolAddress((void**)&S_, g_scratch);
    float* g_h    = S_;
    float* g_yseq = g_h    + (size_t)NTOK * HH;
    float* g_last = g_yseq + (size_t)NTOK * HH;
    __half* H_    = (__half*)(g_last + (size_t)BB * HH);

    __half* x_h  = H_;
    __half* xn_h = x_h  + (size_t)NTOK * II;
    __half* xc_h = xn_h + (size_t)NTOK * HH;
    __half* Wx_h = xc_h + (size_t)NTOK * HH;    // act_h aliases
    __half* yb0  = Wx_h + (size_t)NTOK * H4;
    __half* yb1  = yb0  + (size_t)BB * HH;
    __half* w_h  = yb1  + (size_t)BB * HH;

    __half* w_if  = w_h;
    __half* w_zo  = w_if + W_IFS;
    __half* w_rt  = w_zo + W_IFS;
    __half* w_up  = w_rt + W_RT;
    __half* w_dn  = w_up + W_UP;
    __half* w_emb = w_dn + W_DN;
    __half* act_h = Wx_h;   // alias

    // scan smem: max(fp16 GEMM tiles (2*64*72 + 2*128*72)*2 = 55,296 B,
    //                fp32 rawS [64][132]*4 = 33,792 B)
    const int SCAN_SMEM = (2 * 64 * 72 + 2 * 128 * 72) * 2;  // 55,296 B
    const int GEMM_SMEM = 2 * 3 * 128 * 40 * 2;              // 61,440 B (3 stages)
    cudaFuncSetAttribute(scan_kernel,
                         cudaFuncAttributeMaxDynamicSharedMemorySize, SCAN_SMEM);
    cudaFuncSetAttribute(gemm_f16_kernel<true,false,false,false>,
                         cudaFuncAttributeMaxDynamicSharedMemorySize, GEMM_SMEM);
    cudaFuncSetAttribute(gemm_f16_kernel<true,false,false,true>,
                         cudaFuncAttributeMaxDynamicSharedMemorySize, GEMM_SMEM);
    cudaFuncSetAttribute(gemm_f16_kernel<false,false,true,false>,
                         cudaFuncAttributeMaxDynamicSharedMemorySize, GEMM_SMEM);
    cudaFuncSetAttribute(gemm_f16_kernel<false,true,false,false>,
                         cudaFuncAttributeMaxDynamicSharedMemorySize, GEMM_SMEM);

    // 0: one-shot conversions
    prep_kernel<<<(unsigned)((PREP_N + 255) / 256), 256>>>(
        Wi, Wf, Wz, Wo, R, ff_up, ff_dn, emb_w, x, w_h, x_h);

    // 1: h = x_h @ emb_w^T + emb_b (fp32 out)
    gemm_f16_kernel<false,false,true,false>
        <<<dim3(HH/128, NTOK/128), 256, GEMM_SMEM>>>(x_h, II, w_emb, II,
                                                     g_h, HH, emb_b, II);

    for (int l = 0; l < LL; l++) {
        // xn = LN(h)*ln1_w  (half out)
        ln_warp_kernel<true><<<NTOK/8, 256>>>(g_h, HH, ln1_w + (size_t)l*HH,
                                              xn_h, HH);
        // Wx cols [2048,4096) = [z|o] = xn @ [Wz;Wo]^T
        gemm_f16_kernel<true,false,false,false>
            <<<dim3(16, 200), 256, GEMM_SMEM>>>(xn_h, HH,
                                                w_zo + (size_t)l*2*HH*HH, HH,
                                                Wx_h + 2048, H4, nullptr, HH);
        // xc = silu(causal_conv(xn))
        conv_silu_kernel<<<(NTOK*HH/4)/256, 256>>>(xn_h,
            conv_w + (size_t)l*HH*KK, conv_b + (size_t)l*HH, xc_h);
        // Wx cols [0,2048) = [i|f] = xc @ [Wi;Wf]^T
        gemm_f16_kernel<true,false,false,false>
            <<<dim3(16, 200), 256, GEMM_SMEM>>>(xc_h, HH,
                                                w_if + (size_t)l*2*HH*HH, HH,
                                                Wx_h, H4, nullptr, HH);

        // persistent fused scan: all 100 steps in one launch
        scan_kernel<<<SC_CTAS, 256, SCAN_SMEM>>>(
            Wx_h, w_rt + (size_t)l*H4*HH, cell_b + (size_t)l*H4,
            yb0, yb1, g_yseq);

        // fused: h += LN(yseq)*gn ; fn = LN(h)*ln2 (half out, into xn_h)
        lnadd_ln2_kernel<<<NTOK/8, 256>>>(g_yseq, gn_w + (size_t)l*HH,
                                          ln2_w + (size_t)l*HH, g_h, xn_h);

        // FFN: act = gelu(g)*v fused in up-GEMM epilogue ; h += act @ ff_dn^T
        gemm_f16_kernel<true,false,false,true>
            <<<dim3(U2/128, 200), 256, GEMM_SMEM>>>(xn_h, HH,
                                                    w_up + (size_t)l*U2*HH, HH,
                                                    act_h, UU, nullptr, HH);
        gemm_f16_kernel<false,true,false,false>
            <<<dim3(8, 200), 256, GEMM_SMEM>>>(act_h, UU,
                                               w_dn + (size_t)l*HH*UU, UU,
                                               g_h, HH, nullptr, UU);
    }

    // post-LN only needed for last timestep (fp32 out)
    ln_warp_kernel<false><<<BB/8, 256>>>(g_h + (size_t)(SS-1)*HH, (size_t)SS*HH,
                                         post_w, g_last, HH);
    // out = last @ fc_w^T + fc_b
    gemm_fc_kernel<64,128,16,4,8>
        <<<dim3(OO/128, BB/64), 256>>>(g_last, HH, fc_w, HH,
                                       out, OO, fc_b, HH);
}

// round 12
// speedup vs baseline: 1.1863x; 1.1863x over previous
#include <cuda_runtime.h>
#include <cuda_fp16.h>
#include <cstddef>
#include <cstdint>

// Problem constants
#define BB   256
#define SS   100
#define II   128
#define HH   1024
#define OO   128
#define LL   2
#define UU   1344
#define KK   4
#define NTOK (BB * SS)          // 25600
#define H4   (4 * HH)           // 4096
#define U2   (2 * UU)           // 2688

// ---------------------------------------------------------------------------
// Scratch layout (identical to round 10).
#define W_IFS  ((size_t)LL * 2 * HH * HH)   // 4,194,304
#define W_RT   ((size_t)LL * H4 * HH)       // 8,388,608 (transposed [l][n][k])
#define W_UP   ((size_t)LL * U2 * HH)       // 5,505,024 (g/v row-interleaved)
#define W_DN   ((size_t)LL * HH * UU)       // 2,752,512
#define W_EMB  ((size_t)HH * II)            // 131,072
#define W_TOT  (2 * W_IFS + W_RT + W_UP + W_DN + W_EMB)
#define PREP_N (W_TOT + (size_t)NTOK * II)  // + x conversion
#define SCRATCH_FLOATS 146000000ULL
__device__ float g_scratch[SCRATCH_FLOATS];

// monotonic grid-barrier counter (never reset; race-free).
__device__ unsigned g_bar_cnt = 0;

// ---------------------------------------------------------------------------
__device__ __forceinline__ void cp16(void* s, const void* g)
{
    uint32_t sa = (uint32_t)__cvta_generic_to_shared(s);
    asm volatile("cp.async.cg.shared.global [%0], [%1], 16;\n" :: "r"(sa), "l"(g));
}
__device__ __forceinline__ void cp_commit()
{
    asm volatile("cp.async.commit_group;\n" ::);
}
template<int N>
__device__ __forceinline__ void cp_wait()
{
    asm volatile("cp.async.wait_group %0;\n" :: "n"(N));
}

__device__ __forceinline__ void mma_f16(float* d, const uint32_t* a, const uint32_t* b)
{
    asm volatile(
        "mma.sync.aligned.m16n8k16.row.col.f32.f16.f16.f32 "
        "{%0,%1,%2,%3},{%4,%5,%6,%7},{%8,%9},{%0,%1,%2,%3};"
        : "+f"(d[0]), "+f"(d[1]), "+f"(d[2]), "+f"(d[3])
        : "r"(a[0]), "r"(a[1]), "r"(a[2]), "r"(a[3]),
          "r"(b[0]), "r"(b[1]));
}

#define LDSM4(r0, r1, r2, r3, addr) \
    asm volatile("ldmatrix.sync.aligned.m8n8.x4.shared.b16 {%0,%1,%2,%3}, [%4];" \
                 : "=r"(r0), "=r"(r1), "=r"(r2), "=r"(r3) : "r"(addr))

__device__ __forceinline__ float gelu_exact(float g)
{
    return 0.5f * g * (1.f + erff(g * 0.7071067811865476f));
}

// ---------------------------------------------------------------------------
// fp16 tensor-core GEMM.  C[M,N] = A[M,K] * B^T, B stored [N,K] (halfs).
// 128x128x32 tiles, 256 threads, 4-stage cp.async pipeline, ldmatrix m16n8k16.
// (Round-10 measured-best config: no min-blocks cap — 95 regs, 2 CTAs/SM.
//  Round 11 showed launch_bounds(256,3) spills accumulators and regresses.)
// OUTH: C is half. GELU (implies OUTH): adjacent col pairs (g,v) ->
//   gelu(g)*v into half-width C (ldc = N/2). BIAS/ACC: fp32 C paths.
template<bool OUTH, bool ACC, bool BIAS, bool GELU>
__global__ void __launch_bounds__(256)
gemm_f16_kernel(const __half* __restrict__ A, int lda,
                const __half* __restrict__ B, int ldb,
                void* __restrict__ Cv, int ldc,
                const float* __restrict__ bias, int K)
{
    constexpr int BM = 128, BK = 32, STR = 40, S = 4;
    extern __shared__ __half smh[];
    __half* As = smh;                     // [S][128][40]
    __half* Bs = smh + S * BM * STR;      // [S][128][40]

    const int tid  = threadIdx.x;
    const int lane = tid & 31;
    const int warp = tid >> 5;
    const int wm = (warp >> 2) * 64;
    const int wn = (warp & 3) * 32;
    const int lr = lane >> 2;
    const int lc = lane & 3;
    const long bm0 = (long)blockIdx.y * BM;
    const long bn0 = (long)blockIdx.x * 128;

    const int q_row = (lane & 7) + ((lane >> 3) & 1) * 8;
    const int q_col = (lane >> 4) * 8;    // halfs
    const uint32_t as_base = (uint32_t)__cvta_generic_to_shared(As);
    const uint32_t bs_base = (uint32_t)__cvta_generic_to_shared(Bs);

    float acc[4][4][4];
#pragma unroll
    for (int mi = 0; mi < 4; mi++)
#pragma unroll
        for (int ni = 0; ni < 4; ni++)
#pragma unroll
            for (int t = 0; t < 4; t++) acc[mi][ni][t] = 0.f;

    auto prefetch = [&](int s, int k0) {
        __half* as = As + s * BM * STR;
        __half* bs = Bs + s * BM * STR;
#pragma unroll
        for (int j = 0; j < 2; j++) {
            int i = tid + j * 256;
            int row = i >> 2, off = (i & 3) * 8;
            cp16(as + row * STR + off, A + (bm0 + row) * (long)lda + k0 + off);
        }
#pragma unroll
        for (int j = 0; j < 2; j++) {
            int i = tid + j * 256;
            int row = i >> 2, off = (i & 3) * 8;
            cp16(bs + row * STR + off, B + (bn0 + row) * (long)ldb + k0 + off);
        }
    };

    auto compute = [&](int s) {
#pragma unroll
        for (int kk = 0; kk < BK; kk += 16) {
            uint32_t a[4][4], b[4][2];
#pragma unroll
            for (int mi = 0; mi < 4; mi++) {
                uint32_t addr = as_base +
                    ((s * BM + wm + mi * 16 + q_row) * STR + kk + q_col) * 2;
                LDSM4(a[mi][0], a[mi][1], a[mi][2], a[mi][3], addr);
            }
#pragma unroll
            for (int np = 0; np < 2; np++) {
                uint32_t r0, r1, r2, r3;
                uint32_t addr = bs_base +
                    ((s * BM + wn + np * 16 + q_row) * STR + kk + q_col) * 2;
                LDSM4(r0, r1, r2, r3, addr);
                b[2 * np][0] = r0; b[2 * np + 1][0] = r1;
                b[2 * np][1] = r2; b[2 * np + 1][1] = r3;
            }
#pragma unroll
            for (int mi = 0; mi < 4; mi++)
#pragma unroll
                for (int ni = 0; ni < 4; ni++)
                    mma_f16(acc[mi][ni], a[mi], b[ni]);
        }
    };

    const int NIT = K / BK;
#pragma unroll
    for (int s = 0; s < S - 1; s++) {
        if (s < NIT) prefetch(s, s * BK);
        cp_commit();
    }
    for (int it = 0; it < NIT; ++it) {
        cp_wait<S - 2>();
        __syncthreads();
        int nf = it + S - 1;
        if (nf < NIT) prefetch(nf % S, nf * BK);
        cp_commit();
        compute(it % S);
    }

    // Epilogue
#pragma unroll
    for (int mi = 0; mi < 4; mi++) {
        long r0 = bm0 + wm + mi * 16 + lr;
#pragma unroll
        for (int ni = 0; ni < 4; ni++) {
            long c0 = bn0 + wn + ni * 8 + lc * 2;
            if (GELU) {
                __half* C = (__half*)Cv;
                long j = c0 >> 1;
                C[r0 * (long)ldc + j] =
                    __float2half(gelu_exact(acc[mi][ni][0]) * acc[mi][ni][1]);
                C[(r0 + 8) * (long)ldc + j] =
                    __float2half(gelu_exact(acc[mi][ni][2]) * acc[mi][ni][3]);
            } else if (OUTH) {
                __half* C = (__half*)Cv;
                *(__half2*)(C + r0 * (long)ldc + c0) =
                    __floats2half2_rn(acc[mi][ni][0], acc[mi][ni][1]);
                *(__half2*)(C + (r0 + 8) * (long)ldc + c0) =
                    __floats2half2_rn(acc[mi][ni][2], acc[mi][ni][3]);
            } else {
                float* C = (float*)Cv;
                float2* p0 = (float2*)(C + r0 * (long)ldc + c0);
                float2* p1 = (float2*)(C + (r0 + 8) * (long)ldc + c0);
                float b0 = 0.f, b1 = 0.f;
                if (BIAS) { b0 = bias[c0]; b1 = bias[c0 + 1]; }
                if (ACC) {
                    float2 v0 = *p0, v1 = *p1;
                    v0.x += acc[mi][ni][0] + b0; v0.y += acc[mi][ni][1] + b1;
                    v1.x += acc[mi][ni][2] + b0; v1.y += acc[mi][ni][3] + b1;
                    *p0 = v0; *p1 = v1;
                } else {
                    *p0 = make_float2(acc[mi][ni][0] + b0, acc[mi][ni][1] + b1);
                    *p1 = make_float2(acc[mi][ni][2] + b0, acc[mi][ni][3] + b1);
                }
            }
        }
    }
}

// ---------------------------------------------------------------------------
// Persistent fused sLSTM scan kernel, fp16 GEMM (m16n8k16), BK=64.
// 128 CTAs: (mt = bid>>5 in [0,4): 64 batch rows; ht = bid&31: 32 h).
// B = Rt [n][k] rows gathered per ht. State (c,n,m) fp32 in registers;
// y fp16 double-buffered in scratch.
#define SC_CTAS 128

// Race-free monotonic grid barrier (ticket / epoch; no reset, no phase word).
__device__ __forceinline__ void grid_bar()
{
    __syncthreads();
    __threadfence();
    if (threadIdx.x == 0) {
        unsigned my = atomicAdd(&g_bar_cnt, 1u);
        unsigned target = (my / SC_CTAS + 1u) * SC_CTAS;
        while (*((volatile unsigned*)&g_bar_cnt) < target) { }
    }
    __syncthreads();
    __threadfence();
}

__global__ void __launch_bounds__(256)
scan_kernel(const __half* __restrict__ Wx, const __half* __restrict__ Rt,
            const float* __restrict__ cb,
            __half* __restrict__ yb0, __half* __restrict__ yb1,
            float* __restrict__ yseq)
{
    extern __shared__ __half smh[];
    constexpr int STR = 72, BK = 64, RSTR = 132;
    __half* As = smh;                     // [2][64][72]  =  9,216 halfs
    __half* Bs = smh + 2 * 64 * STR;      // [2][128][72] = 18,432 halfs
    float*  rawS = (float*)smh;           // [64][132] fp32 = 33,792 B (aliases
                                          //  As/Bs after GEMM; smem covers both)

    const int tid  = threadIdx.x;
    const int lane = tid & 31;
    const int warp = tid >> 5;
    const int wm = (warp >> 2) * 32;      // 2 m-warps x 32
    const int wn = (warp & 3) * 32;       // 4 n-warps x 32
    const int lr = lane >> 2;
    const int lc = lane & 3;
    const int mt = blockIdx.x >> 5;
    const int ht = blockIdx.x & 31;

    const int q_row = (lane & 7) + ((lane >> 3) & 1) * 8;
    const int q_col = (lane >> 4) * 8;
    const uint32_t as_base = (uint32_t)__cvta_generic_to_shared(As);
    const uint32_t bs_base = (uint32_t)__cvta_generic_to_shared(Bs);

    const int hl = tid & 31;
    const int rg = tid >> 5;
    const int h  = ht * 32 + hl;
    const long acol = (long)mt * 64;

    float cbv[4];
#pragma unroll
    for (int g = 0; g < 4; g++) cbv[g] = cb[g * 1024 + h];

    float stc[8], stn[8], stm[8];
#pragma unroll
    for (int j = 0; j < 8; j++) { stc[j] = 0.f; stn[j] = 0.f; stm[j] = 0.f; }

    // zero this CTA's slice of yb0 (2048 halfs = 256 threads x 16B)
    {
        uint4 z = make_uint4(0u, 0u, 0u, 0u);
        *(uint4*)(yb0 + (size_t)blockIdx.x * 2048 + tid * 8) = z;
    }
    grid_bar();

    for (int s = 0; s < SS; s++) {
        const __half* ycur = (s & 1) ? yb1 : yb0;
        __half*       ynxt = (s & 1) ? yb0 : yb1;

        float acc[2][4][4];
#pragma unroll
        for (int mi = 0; mi < 2; mi++)
#pragma unroll
            for (int ni = 0; ni < 4; ni++)
#pragma unroll
                for (int t = 0; t < 4; t++) acc[mi][ni][t] = 0.f;

        auto prefetch = [&](int buf, int k0) {
            // A: 64 rows x 64 halfs = 512 chunks (2/thread)
#pragma unroll
            for (int j = 0; j < 2; j++) {
                int i = tid + j * 256;
                int row = i >> 3, off = (i & 7) * 8;
                cp16(&As[(buf * 64 + row) * STR + off],
                     ycur + (acol + row) * 1024 + k0 + off);
            }
            // B: 128 gathered n-rows x 64 halfs = 1024 chunks (4/thread)
#pragma unroll
            for (int j = 0; j < 4; j++) {
                int i = tid + j * 256;
                int nt = i >> 3, off = (i & 7) * 8;
                long nglob = (long)(nt >> 5) * 1024 + ht * 32 + (nt & 31);
                cp16(&Bs[(buf * 128 + nt) * STR + off],
                     Rt + nglob * 1024 + k0 + off);
            }
        };

        auto compute = [&](int buf) {
#pragma unroll
            for (int kk = 0; kk < BK; kk += 16) {
                uint32_t a[2][4], b[4][2];
#pragma unroll
                for (int mi = 0; mi < 2; mi++) {
                    uint32_t addr = as_base +
                        ((buf * 64 + wm + mi * 16 + q_row) * STR + kk + q_col) * 2;
                    LDSM4(a[mi][0], a[mi][1], a[mi][2], a[mi][3], addr);
                }
#pragma unroll
                for (int np = 0; np < 2; np++) {
                    uint32_t r0, r1, r2, r3;
                    uint32_t addr = bs_base +
                        ((buf * 128 + wn + np * 16 + q_row) * STR + kk + q_col) * 2;
                    LDSM4(r0, r1, r2, r3, addr);
                    b[2 * np][0] = r0; b[2 * np + 1][0] = r1;
                    b[2 * np][1] = r2; b[2 * np + 1][1] = r3;
                }
#pragma unroll
                for (int mi = 0; mi < 2; mi++)
#pragma unroll
                    for (int ni = 0; ni < 4; ni++)
                        mma_f16(acc[mi][ni], a[mi], b[ni]);
            }
        };

        constexpr int NIT = 1024 / BK;   // 16
        prefetch(0, 0);
        cp_commit();
        for (int it = 0; it < NIT; ++it) {
            if (it + 1 < NIT) {
                prefetch((it + 1) & 1, (it + 1) * BK);
                cp_commit();
                cp_wait<1>();
            } else {
                cp_wait<0>();
            }
            __syncthreads();
            compute(it & 1);
            __syncthreads();
        }

        // stage raw tile to smem (aliases As/Bs; GEMM done)
#pragma unroll
        for (int mi = 0; mi < 2; mi++) {
            int r0 = wm + mi * 16 + lr;
#pragma unroll
            for (int ni = 0; ni < 4; ni++) {
                int c0 = wn + ni * 8 + lc * 2;
                *(float2*)&rawS[r0 * RSTR + c0] =
                    make_float2(acc[mi][ni][0], acc[mi][ni][1]);
                *(float2*)&rawS[(r0 + 8) * RSTR + c0] =
                    make_float2(acc[mi][ni][2], acc[mi][ni][3]);
            }
        }
        __syncthreads();

        // fused gate update: 8 (b,h) pairs per thread, state in registers
#pragma unroll
        for (int j = 0; j < 8; j++) {
            int row = rg * 8 + j;
            long bb = acol + row;
            const __half* wx = Wx + ((bb * SS + s) << 12) + h;

            float ir  = rawS[row * RSTR + hl]      + __half2float(wx[0])    + cbv[0];
            float fr  = rawS[row * RSTR + 32 + hl] + __half2float(wx[1024]) + cbv[1];
            float zr  = rawS[row * RSTR + 64 + hl] + __half2float(wx[2048]) + cbv[2];
            float orr = rawS[row * RSTR + 96 + hl] + __half2float(wx[3072]) + cbv[3];

            float logsig = (fr >= 0.f) ? -log1pf(__expf(-fr))
                                       : (fr - log1pf(__expf(fr)));
            float lfm  = stm[j] + logsig;
            float mnew = (stn[j] == 0.f) ? ir : fmaxf(ir, lfm);
            float ig   = __expf(ir  - mnew);
            float fg   = __expf(lfm - mnew);
            float ez   = __expf(-2.f * fabsf(zr));
            float tz   = copysignf((1.f - ez) / (1.f + ez), zr);
            float cnew = fg * stc[j] + ig * tz;
            float nnew = fg * stn[j] + ig;
            float og   = 1.f / (1.f + __expf(-orr));
            float ynew = og * cnew / nnew;

            stc[j] = cnew;
            stn[j] = nnew;
            stm[j] = mnew;
            ynxt[bb * 1024 + h] = __float2half(ynew);
            yseq[(bb * SS + s) * 1024 + h] = ynew;
        }

        grid_bar();
    }
}

// ---------------------------------------------------------------------------
// fp32 SIMT GEMM (fc only).
template<int BM, int BN, int BK, int TM, int TN>
__global__ void __launch_bounds__(256)
gemm_fc_kernel(const float* __restrict__ A, int lda,
               const float* __restrict__ B, int ldb,
               float* __restrict__ C, int ldc,
               const float* __restrict__ bias, int K)
{
    constexpr int TX = BN / TN;
    constexpr int TY = BM / TM;
    constexpr int NT = TX * TY;

    __shared__ float As[BK][BM + 4];
    __shared__ float Bs[BK][BN + 4];

    const int tid = threadIdx.x;
    const int tx = tid % TX;
    const int ty = tid / TX;
    const long bm0 = (long)blockIdx.y * BM;
    const long bn0 = (long)blockIdx.x * BN;

    float acc[TM][TN];
#pragma unroll
    for (int i = 0; i < TM; i++)
#pragma unroll
        for (int j = 0; j < TN; j++) acc[i][j] = 0.f;

    for (int k0 = 0; k0 < K; k0 += BK) {
#pragma unroll
        for (int i = tid * 4; i < BM * BK; i += NT * 4) {
            int r = i / BK, kk = i % BK;
            float4 v = *(const float4*)(A + (bm0 + r) * (long)lda + (k0 + kk));
            As[kk + 0][r] = v.x; As[kk + 1][r] = v.y;
            As[kk + 2][r] = v.z; As[kk + 3][r] = v.w;
        }
#pragma unroll
        for (int i = tid * 4; i < BN * BK; i += NT * 4) {
            int r = i / BK, kk = i % BK;
            float4 v = *(const float4*)(B + (bn0 + r) * (long)ldb + (k0 + kk));
            Bs[kk + 0][r] = v.x; Bs[kk + 1][r] = v.y;
            Bs[kk + 2][r] = v.z; Bs[kk + 3][r] = v.w;
        }
        __syncthreads();

#pragma unroll
        for (int kk = 0; kk < BK; kk++) {
            float a[TM], b[TN];
#pragma unroll
            for (int i = 0; i < TM; i += 4)
                *(float4*)&a[i] = *(const float4*)&As[kk][ty * TM + i];
#pragma unroll
            for (int j = 0; j < TN; j += 4)
                *(float4*)&b[j] = *(const float4*)&Bs[kk][tx * TN + j];
#pragma unroll
            for (int i = 0; i < TM; i++)
#pragma unroll
                for (int j = 0; j < TN; j++)
                    acc[i][j] = fmaf(a[i], b[j], acc[i][j]);
        }
        __syncthreads();
    }

#pragma unroll
    for (int i = 0; i < TM; i++) {
        long row = bm0 + ty * TM + i;
#pragma unroll
        for (int j = 0; j < TN; j++) {
            long col = bn0 + tx * TN + j;
            C[row * (long)ldc + col] = acc[i][j] + bias[col];
        }
    }
}

// ---------------------------------------------------------------------------
__device__ __forceinline__ void warp_reduce2(float& s, float& ss)
{
#pragma unroll
    for (int o = 16; o > 0; o >>= 1) {
        s  += __shfl_xor_sync(0xFFFFFFFFu, s,  o);
        ss += __shfl_xor_sync(0xFFFFFFFFu, ss, o);
    }
}

// out = LN(x)*w ; OUTH: write halfs, else floats. Warp-per-row (1024 wide).
template<bool OUTH>
__global__ void ln_warp_kernel(const float* __restrict__ x, size_t xs,
                               const float* __restrict__ w,
                               void* __restrict__ outv, size_t os)
{
    int warp = threadIdx.x >> 5, lane = threadIdx.x & 31;
    size_t row = (size_t)blockIdx.x * 8 + warp;
    const float* xr = x + row * xs;
    float4 v[8];
    float s = 0.f, ss = 0.f;
#pragma unroll
    for (int i = 0; i < 8; i++) {
        v[i] = *(const float4*)(xr + i * 128 + lane * 4);
        s  += v[i].x + v[i].y + v[i].z + v[i].w;
        ss += v[i].x * v[i].x + v[i].y * v[i].y + v[i].z * v[i].z + v[i].w * v[i].w;
    }
    warp_reduce2(s, ss);
    float mu  = s * (1.f / 1024.f);
    float var = fmaxf(ss * (1.f / 1024.f) - mu * mu, 0.f);
    float rs  = rsqrtf(var + 1e-5f);
#pragma unroll
    for (int i = 0; i < 8; i++) {
        int c = i * 128 + lane * 4;
        float4 wv = *(const float4*)(w + c);
        float o0 = (v[i].x - mu) * rs * wv.x;
        float o1 = (v[i].y - mu) * rs * wv.y;
        float o2 = (v[i].z - mu) * rs * wv.z;
        float o3 = (v[i].w - mu) * rs * wv.w;
        if (OUTH) {
            __half2* op = (__half2*)((__half*)outv + row * os + c);
            op[0] = __floats2half2_rn(o0, o1);
            op[1] = __floats2half2_rn(o2, o3);
        } else {
            *(float4*)((float*)outv + row * os + c) = make_float4(o0, o1, o2, o3);
        }
    }
}

// Fused: h += LN(yseq)*gn ; fn = LN(h_new)*ln2 (half out). Warp-per-row.
__global__ void lnadd_ln2_kernel(const float* __restrict__ yseq,
                                 const float* __restrict__ gn,
                                 const float* __restrict__ ln2,
                                 float* __restrict__ h,
                                 __half* __restrict__ fn)
{
    int warp = threadIdx.x >> 5, lane = threadIdx.x & 31;
    size_t row = (size_t)blockIdx.x * 8 + warp;
    const float* yr = yseq + row * HH;
    float* hr = h + row * HH;
    float4 v[8], hv[8];
    float s = 0.f, ss = 0.f;
#pragma unroll
    for (int i = 0; i < 8; i++) {
        v[i] = *(const float4*)(yr + i * 128 + lane * 4);
        s  += v[i].x + v[i].y + v[i].z + v[i].w;
        ss += v[i].x * v[i].x + v[i].y * v[i].y + v[i].z * v[i].z + v[i].w * v[i].w;
    }
    warp_reduce2(s, ss);
    float mu  = s * (1.f / 1024.f);
    float var = fmaxf(ss * (1.f / 1024.f) - mu * mu, 0.f);
    float rs  = rsqrtf(var + 1e-5f);
    float s2 = 0.f, ss2 = 0.f;
#pragma unroll
    for (int i = 0; i < 8; i++) {
        int c = i * 128 + lane * 4;
        float4 gv = *(const float4*)(gn + c);
        hv[i] = *(float4*)(hr + c);
        hv[i].x += (v[i].x - mu) * rs * gv.x;
        hv[i].y += (v[i].y - mu) * rs * gv.y;
        hv[i].z += (v[i].z - mu) * rs * gv.z;
        hv[i].w += (v[i].w - mu) * rs * gv.w;
        *(float4*)(hr + c) = hv[i];
        s2  += hv[i].x + hv[i].y + hv[i].z + hv[i].w;
        ss2 += hv[i].x * hv[i].x + hv[i].y * hv[i].y
             + hv[i].z * hv[i].z + hv[i].w * hv[i].w;
    }
    warp_reduce2(s2, ss2);
    float mu2  = s2 * (1.f / 1024.f);
    float var2 = fmaxf(ss2 * (1.f / 1024.f) - mu2 * mu2, 0.f);
    float rs2  = rsqrtf(var2 + 1e-5f);
#pragma unroll
    for (int i = 0; i < 8; i++) {
        int c = i * 128 + lane * 4;
        float4 wv = *(const float4*)(ln2 + c);
        __half2* op = (__half2*)(fn + row * HH + c);
        op[0] = __floats2half2_rn((hv[i].x - mu2) * rs2 * wv.x,
                                  (hv[i].y - mu2) * rs2 * wv.y);
        op[1] = __floats2half2_rn((hv[i].z - mu2) * rs2 * wv.z,
                                  (hv[i].w - mu2) * rs2 * wv.w);
    }
}

// ---------------------------------------------------------------------------
// Depthwise causal conv (K=4) + SiLU; fp16 in/out, fp32 math.
__global__ void conv_silu_kernel(const __half* __restrict__ xn,
                                 const float* __restrict__ cw,
                                 const float* __restrict__ cb,
                                 __half* __restrict__ xc)
{
    size_t q = (size_t)blockIdx.x * blockDim.x + threadIdx.x; // < NTOK*H/4
    int hq = (int)(q & 255);
    size_t t = q >> 8;
    int s = (int)(t % SS);
    int h = hq * 4;
    size_t base = t * HH + h;

    float4 w0 = *(const float4*)(cw + (size_t)h * 4);
    float4 w1 = *(const float4*)(cw + (size_t)(h + 1) * 4);
    float4 w2 = *(const float4*)(cw + (size_t)(h + 2) * 4);
    float4 w3 = *(const float4*)(cw + (size_t)(h + 3) * 4);
    float4 bv = *(const float4*)(cb + h);
    float a0 = bv.x, a1 = bv.y, a2 = bv.z, a3 = bv.w;

#pragma unroll
    for (int k = 0; k < 4; k++) {
        int sp = s - 3 + k;
        if (sp >= 0) {
            const __half2* xp = (const __half2*)(xn + base + (long)(k - 3) * HH);
            float2 x01 = __half22float2(xp[0]);
            float2 x23 = __half22float2(xp[1]);
            a0 = fmaf(x01.x, ((const float*)&w0)[k], a0);
            a1 = fmaf(x01.y, ((const float*)&w1)[k], a1);
            a2 = fmaf(x23.x, ((const float*)&w2)[k], a2);
            a3 = fmaf(x23.y, ((const float*)&w3)[k], a3);
        }
    }
    __half2* op = (__half2*)(xc + base);
    op[0] = __floats2half2_rn(a0 / (1.f + __expf(-a0)), a1 / (1.f + __expf(-a1)));
    op[1] = __floats2half2_rn(a2 / (1.f + __expf(-a2)), a3 / (1.f + __expf(-a3)));
}

// ---------------------------------------------------------------------------
// One-shot prep: convert all weights to fp16 (stack i/f and z/o, transpose R
// to [n][k], interleave ff_up g/v rows, copy emb_w) and convert x to fp16.
__global__ void prep_kernel(const float* __restrict__ Wi,
                            const float* __restrict__ Wf,
                            const float* __restrict__ Wz,
                            const float* __restrict__ Wo,
                            const float* __restrict__ R,
                            const float* __restrict__ up,
                            const float* __restrict__ dn,
                            const float* __restrict__ embw,
                            const float* __restrict__ x,
                            __half* __restrict__ wdst,
                            __half* __restrict__ xdst)
{
    size_t i = (size_t)blockIdx.x * 256 + threadIdx.x;
    if (i >= PREP_N) return;
    const size_t HHHH = (size_t)HH * HH;
    if (i >= W_TOT) {                      // x conversion
        size_t j = i - W_TOT;
        xdst[j] = __float2half(x[j]);
        return;
    }
    float v;
    if (i < W_IFS) {
        size_t l = i / (2 * HHHH), r = i % (2 * HHHH);
        v = (r < HHHH ? Wi : Wf)[l * HHHH + (r % HHHH)];
    } else if (i < 2 * W_IFS) {
        size_t j = i - W_IFS;
        size_t l = j / (2 * HHHH), r = j % (2 * HHHH);
        v = (r < HHHH ? Wz : Wo)[l * HHHH + (r % HHHH)];
    } else if (i < 2 * W_IFS + W_RT) {
        size_t j = i - 2 * W_IFS;
        size_t l = j / ((size_t)H4 * HH);
        size_t rem = j % ((size_t)H4 * HH);
        size_t n = rem / HH, k = rem % HH;       // dst [n][k]
        v = R[l * (size_t)HH * H4 + k * H4 + n]; // src [k][n]
    } else if (i < 2 * W_IFS + W_RT + W_UP) {
        size_t j = i - 2 * W_IFS - W_RT;
        size_t l = j / ((size_t)U2 * HH);
        size_t rem = j % ((size_t)U2 * HH);
        size_t row = rem / HH, col = rem % HH;
        size_t u = row >> 1, half = row & 1;     // even rows = g, odd = v
        v = up[l * (size_t)U2 * HH + (half * UU + u) * HH + col];
    } else if (i < 2 * W_IFS + W_RT + W_UP + W_DN) {
        v = dn[i - 2 * W_IFS - W_RT - W_UP];
    } else {
        v = embw[i - 2 * W_IFS - W_RT - W_UP - W_DN];
    }
    wdst[i] = __float2half(v);
}

// ---------------------------------------------------------------------------
extern "C" void kernel_launch(void* const* d_in, const int* in_sizes, int n_in,
                              void* d_out, int out_size)
{
    (void)in_sizes; (void)n_in; (void)out_size;

    const float* x      = (const float*)d_in[0];
    const float* emb_w  = (const float*)d_in[1];
    const float* emb_b  = (const float*)d_in[2];
    const float* conv_w = (const float*)d_in[3];
    const float* conv_b = (const float*)d_in[4];
    const float* Wi     = (const float*)d_in[5];
    const float* Wf     = (const float*)d_in[6];
    const float* Wz     = (const float*)d_in[7];
    const float* Wo     = (const float*)d_in[8];
    const float* R      = (const float*)d_in[9];
    const float* cell_b = (const float*)d_in[10];
    const float* gn_w   = (const float*)d_in[11];
    const float* ln1_w  = (const float*)d_in[12];
    const float* ln2_w  = (const float*)d_in[13];
    const float* ff_up  = (const float*)d_in[14];
    const float* ff_dn  = (const float*)d_in[15];
    const float* post_w = (const float*)d_in[16];
    const float* fc_w   = (const float*)d_in[17];
    const float* fc_b   = (const float*)d_in[18];
    float* out = (float*)d_out;

    float* S_;
    cudaGetSymbolAddress((void**)&S_, g_scratch);
    float* g_h    = S_;
    float* g_yseq = g_h    + (size_t)NTOK * HH;
    float* g_last = g_yseq + (size_t)NTOK * HH;
    __half* H_    = (__half*)(g_last + (size_t)BB * HH);

    __half* x_h  = H_;
    __half* xn_h = x_h  + (size_t)NTOK * II;
    __half* xc_h = xn_h + (size_t)NTOK * HH;
    __half* Wx_h = xc_h + (size_t)NTOK * HH;    // act_h aliases
    __half* yb0  = Wx_h + (size_t)NTOK * H4;
    __half* yb1  = yb0  + (size_t)BB * HH;
    __half* w_h  = yb1  + (size_t)BB * HH;

    __half* w_if  = w_h;
    __half* w_zo  = w_if + W_IFS;
    __half* w_rt  = w_zo + W_IFS;
    __half* w_up  = w_rt + W_RT;
    __half* w_dn  = w_up + W_UP;
    __half* w_emb = w_dn + W_DN;
    __half* act_h = Wx_h;   // alias

    // scan smem: max(fp16 GEMM tiles (2*64*72 + 2*128*72)*2 = 55,296 B,
    //                fp32 rawS [64][132]*4 = 33,792 B)
    const int SCAN_SMEM = (2 * 64 * 72 + 2 * 128 * 72) * 2;  // 55,296 B
    const int GEMM_SMEM = 2 * 4 * 128 * 40 * 2;              // 81,920 B (4 stages)
    cudaFuncSetAttribute(scan_kernel,
                         cudaFuncAttributeMaxDynamicSharedMemorySize, SCAN_SMEM);
    cudaFuncSetAttribute(gemm_f16_kernel<true,false,false,false>,
                         cudaFuncAttributeMaxDynamicSharedMemorySize, GEMM_SMEM);
    cudaFuncSetAttribute(gemm_f16_kernel<true,false,false,true>,
                         cudaFuncAttributeMaxDynamicSharedMemorySize, GEMM_SMEM);
    cudaFuncSetAttribute(gemm_f16_kernel<false,false,true,false>,
                         cudaFuncAttributeMaxDynamicSharedMemorySize, GEMM_SMEM);
    cudaFuncSetAttribute(gemm_f16_kernel<false,true,false,false>,
                         cudaFuncAttributeMaxDynamicSharedMemorySize, GEMM_SMEM);

    // 0: one-shot conversions
    prep_kernel<<<(unsigned)((PREP_N + 255) / 256), 256>>>(
        Wi, Wf, Wz, Wo, R, ff_up, ff_dn, emb_w, x, w_h, x_h);

    // 1: h = x_h @ emb_w^T + emb_b (fp32 out)
    gemm_f16_kernel<false,false,true,false>
        <<<dim3(HH/128, NTOK/128), 256, GEMM_SMEM>>>(x_h, II, w_emb, II,
                                                     g_h, HH, emb_b, II);

    for (int l = 0; l < LL; l++) {
        // xn = LN(h)*ln1_w  (half out)
        ln_warp_kernel<true><<<NTOK/8, 256>>>(g_h, HH, ln1_w + (size_t)l*HH,
                                              xn_h, HH);
        // Wx cols [2048,4096) = [z|o] = xn @ [Wz;Wo]^T
        gemm_f16_kernel<true,false,false,false>
            <<<dim3(16, 200), 256, GEMM_SMEM>>>(xn_h, HH,
                                                w_zo + (size_t)l*2*HH*HH, HH,
                                                Wx_h + 2048, H4, nullptr, HH);
        // xc = silu(causal_conv(xn))
        conv_silu_kernel<<<(NTOK*HH/4)/256, 256>>>(xn_h,
            conv_w + (size_t)l*HH*KK, conv_b + (size_t)l*HH, xc_h);
        // Wx cols [0,2048) = [i|f] = xc @ [Wi;Wf]^T
        gemm_f16_kernel<true,false,false,false>
            <<<dim3(16, 200), 256, GEMM_SMEM>>>(xc_h, HH,
                                                w_if + (size_t)l*2*HH*HH, HH,
                                                Wx_h, H4, nullptr, HH);

        // persistent fused scan: all 100 steps in one launch
        scan_kernel<<<SC_CTAS, 256, SCAN_SMEM>>>(
            Wx_h, w_rt + (size_t)l*H4*HH, cell_b + (size_t)l*H4,
            yb0, yb1, g_yseq);

        // fused: h += LN(yseq)*gn ; fn = LN(h)*ln2 (half out, into xn_h)
        lnadd_ln2_kernel<<<NTOK/8, 256>>>(g_yseq, gn_w + (size_t)l*HH,
                                          ln2_w + (size_t)l*HH, g_h, xn_h);

        // FFN: act = gelu(g)*v fused in up-GEMM epilogue ; h += act @ ff_dn^T
        gemm_f16_kernel<true,false,false,true>
            <<<dim3(U2/128, 200), 256, GEMM_SMEM>>>(xn_h, HH,
                                                    w_up + (size_t)l*U2*HH, HH,
                                                    act_h, UU, nullptr, HH);
        gemm_f16_kernel<false,true,false,false>
            <<<dim3(8, 200), 256, GEMM_SMEM>>>(act_h, UU,
                                               w_dn + (size_t)l*HH*UU, UU,
                                               g_h, HH, nullptr, UU);
    }

    // post-LN only needed for last timestep (fp32 out)
    ln_warp_kernel<false><<<BB/8, 256>>>(g_h + (size_t)(SS-1)*HH, (size_t)SS*HH,
                                         post_w, g_last, HH);
    // out = last @ fc_w^T + fc_b
    gemm_fc_kernel<64,128,16,4,8>
        <<<dim3(OO/128, BB/64), 256>>>(g_last, HH, fc_w, HH,
                                       out, OO, fc_b, HH);
}

// round 13
// speedup vs baseline: 1.1956x; 1.0078x over previous
#include <cuda_runtime.h>
#include <cuda_fp16.h>
#include <cstddef>
#include <cstdint>

// Problem constants
#define BB   256
#define SS   100
#define II   128
#define HH   1024
#define OO   128
#define LL   2
#define UU   1344
#define KK   4
#define NTOK (BB * SS)          // 25600
#define H4   (4 * HH)           // 4096
#define U2   (2 * UU)           // 2688

// ---------------------------------------------------------------------------
// Scratch layout (identical to round 10/12).
#define W_IFS  ((size_t)LL * 2 * HH * HH)   // 4,194,304
#define W_RT   ((size_t)LL * H4 * HH)       // 8,388,608 (transposed [l][n][k])
#define W_UP   ((size_t)LL * U2 * HH)       // 5,505,024 (g/v row-interleaved)
#define W_DN   ((size_t)LL * HH * UU)       // 2,752,512
#define W_EMB  ((size_t)HH * II)            // 131,072
#define W_TOT  (2 * W_IFS + W_RT + W_UP + W_DN + W_EMB)
#define PREP_N (W_TOT + (size_t)NTOK * II)  // + x conversion
#define SCRATCH_FLOATS 146000000ULL
__device__ float g_scratch[SCRATCH_FLOATS];

// monotonic grid-barrier counter (never reset; race-free).
__device__ unsigned g_bar_cnt = 0;

// ---------------------------------------------------------------------------
__device__ __forceinline__ void cp16(void* s, const void* g)
{
    uint32_t sa = (uint32_t)__cvta_generic_to_shared(s);
    asm volatile("cp.async.cg.shared.global [%0], [%1], 16;\n" :: "r"(sa), "l"(g));
}
__device__ __forceinline__ void cp_commit()
{
    asm volatile("cp.async.commit_group;\n" ::);
}
template<int N>
__device__ __forceinline__ void cp_wait()
{
    asm volatile("cp.async.wait_group %0;\n" :: "n"(N));
}

__device__ __forceinline__ void mma_f16(float* d, const uint32_t* a, const uint32_t* b)
{
    asm volatile(
        "mma.sync.aligned.m16n8k16.row.col.f32.f16.f16.f32 "
        "{%0,%1,%2,%3},{%4,%5,%6,%7},{%8,%9},{%0,%1,%2,%3};"
        : "+f"(d[0]), "+f"(d[1]), "+f"(d[2]), "+f"(d[3])
        : "r"(a[0]), "r"(a[1]), "r"(a[2]), "r"(a[3]),
          "r"(b[0]), "r"(b[1]));
}

#define LDSM4(r0, r1, r2, r3, addr) \
    asm volatile("ldmatrix.sync.aligned.m8n8.x4.shared.b16 {%0,%1,%2,%3}, [%4];" \
                 : "=r"(r0), "=r"(r1), "=r"(r2), "=r"(r3) : "r"(addr))

__device__ __forceinline__ float gelu_exact(float g)
{
    return 0.5f * g * (1.f + erff(g * 0.7071067811865476f));
}

// ---------------------------------------------------------------------------
// fp16 tensor-core GEMM.  C[M,N] = A[M,K] * B^T, B stored [N,K] (halfs).
// 128x128x32 tiles, 256 threads, 4-stage cp.async pipeline, ldmatrix m16n8k16.
// (Measured-best config: no min-blocks cap — 95 regs, 2 CTAs/SM. DO NOT add a
//  min-blocks launch bound: round 11 showed it spills accumulators.)
// OUTH: C is half. GELU (implies OUTH): adjacent col pairs (g,v) ->
//   gelu(g)*v into half-width C (ldc = N/2). BIAS/ACC: fp32 C paths.
template<bool OUTH, bool ACC, bool BIAS, bool GELU>
__global__ void __launch_bounds__(256)
gemm_f16_kernel(const __half* __restrict__ A, int lda,
                const __half* __restrict__ B, int ldb,
                void* __restrict__ Cv, int ldc,
                const float* __restrict__ bias, int K)
{
    constexpr int BM = 128, BK = 32, STR = 40, S = 4;
    extern __shared__ __half smh[];
    __half* As = smh;                     // [S][128][40]
    __half* Bs = smh + S * BM * STR;      // [S][128][40]

    const int tid  = threadIdx.x;
    const int lane = tid & 31;
    const int warp = tid >> 5;
    const int wm = (warp >> 2) * 64;
    const int wn = (warp & 3) * 32;
    const int lr = lane >> 2;
    const int lc = lane & 3;
    const long bm0 = (long)blockIdx.y * BM;
    const long bn0 = (long)blockIdx.x * 128;

    const int q_row = (lane & 7) + ((lane >> 3) & 1) * 8;
    const int q_col = (lane >> 4) * 8;    // halfs
    const uint32_t as_base = (uint32_t)__cvta_generic_to_shared(As);
    const uint32_t bs_base = (uint32_t)__cvta_generic_to_shared(Bs);

    float acc[4][4][4];
#pragma unroll
    for (int mi = 0; mi < 4; mi++)
#pragma unroll
        for (int ni = 0; ni < 4; ni++)
#pragma unroll
            for (int t = 0; t < 4; t++) acc[mi][ni][t] = 0.f;

    auto prefetch = [&](int s, int k0) {
        __half* as = As + s * BM * STR;
        __half* bs = Bs + s * BM * STR;
#pragma unroll
        for (int j = 0; j < 2; j++) {
            int i = tid + j * 256;
            int row = i >> 2, off = (i & 3) * 8;
            cp16(as + row * STR + off, A + (bm0 + row) * (long)lda + k0 + off);
        }
#pragma unroll
        for (int j = 0; j < 2; j++) {
            int i = tid + j * 256;
            int row = i >> 2, off = (i & 3) * 8;
            cp16(bs + row * STR + off, B + (bn0 + row) * (long)ldb + k0 + off);
        }
    };

    auto compute = [&](int s) {
#pragma unroll
        for (int kk = 0; kk < BK; kk += 16) {
            uint32_t a[4][4], b[4][2];
#pragma unroll
            for (int mi = 0; mi < 4; mi++) {
                uint32_t addr = as_base +
                    ((s * BM + wm + mi * 16 + q_row) * STR + kk + q_col) * 2;
                LDSM4(a[mi][0], a[mi][1], a[mi][2], a[mi][3], addr);
            }
#pragma unroll
            for (int np = 0; np < 2; np++) {
                uint32_t r0, r1, r2, r3;
                uint32_t addr = bs_base +
                    ((s * BM + wn + np * 16 + q_row) * STR + kk + q_col) * 2;
                LDSM4(r0, r1, r2, r3, addr);
                b[2 * np][0] = r0; b[2 * np + 1][0] = r1;
                b[2 * np][1] = r2; b[2 * np + 1][1] = r3;
            }
#pragma unroll
            for (int mi = 0; mi < 4; mi++)
#pragma unroll
                for (int ni = 0; ni < 4; ni++)
                    mma_f16(acc[mi][ni], a[mi], b[ni]);
        }
    };

    const int NIT = K / BK;
#pragma unroll
    for (int s = 0; s < S - 1; s++) {
        if (s < NIT) prefetch(s, s * BK);
        cp_commit();
    }
    for (int it = 0; it < NIT; ++it) {
        cp_wait<S - 2>();
        __syncthreads();
        int nf = it + S - 1;
        if (nf < NIT) prefetch(nf % S, nf * BK);
        cp_commit();
        compute(it % S);
    }

    // Epilogue
#pragma unroll
    for (int mi = 0; mi < 4; mi++) {
        long r0 = bm0 + wm + mi * 16 + lr;
#pragma unroll
        for (int ni = 0; ni < 4; ni++) {
            long c0 = bn0 + wn + ni * 8 + lc * 2;
            if (GELU) {
                __half* C = (__half*)Cv;
                long j = c0 >> 1;
                C[r0 * (long)ldc + j] =
                    __float2half(gelu_exact(acc[mi][ni][0]) * acc[mi][ni][1]);
                C[(r0 + 8) * (long)ldc + j] =
                    __float2half(gelu_exact(acc[mi][ni][2]) * acc[mi][ni][3]);
            } else if (OUTH) {
                __half* C = (__half*)Cv;
                *(__half2*)(C + r0 * (long)ldc + c0) =
                    __floats2half2_rn(acc[mi][ni][0], acc[mi][ni][1]);
                *(__half2*)(C + (r0 + 8) * (long)ldc + c0) =
                    __floats2half2_rn(acc[mi][ni][2], acc[mi][ni][3]);
            } else {
                float* C = (float*)Cv;
                float2* p0 = (float2*)(C + r0 * (long)ldc + c0);
                float2* p1 = (float2*)(C + (r0 + 8) * (long)ldc + c0);
                float b0 = 0.f, b1 = 0.f;
                if (BIAS) { b0 = bias[c0]; b1 = bias[c0 + 1]; }
                if (ACC) {
                    float2 v0 = *p0, v1 = *p1;
                    v0.x += acc[mi][ni][0] + b0; v0.y += acc[mi][ni][1] + b1;
                    v1.x += acc[mi][ni][2] + b0; v1.y += acc[mi][ni][3] + b1;
                    *p0 = v0; *p1 = v1;
                } else {
                    *p0 = make_float2(acc[mi][ni][0] + b0, acc[mi][ni][1] + b1);
                    *p1 = make_float2(acc[mi][ni][2] + b0, acc[mi][ni][3] + b1);
                }
            }
        }
    }
}

// ---------------------------------------------------------------------------
// Persistent fused sLSTM scan kernel, fp16 GEMM (m16n8k16), BK=64,
// 3-stage cp.async pipeline (ONE __syncthreads per k-iter, DMA overlapped
// with mma — same proven pattern as the main GEMM).
// 128 CTAs: (mt = bid>>5 in [0,4): 64 batch rows; ht = bid&31: 32 h).
// B = Rt [n][k] rows gathered per ht. State (c,n,m) fp32 in registers;
// y fp16 double-buffered in scratch.
#define SC_CTAS 128

// Race-free monotonic grid barrier (ticket / epoch; no reset, no phase word).
__device__ __forceinline__ void grid_bar()
{
    __syncthreads();
    __threadfence();
    if (threadIdx.x == 0) {
        unsigned my = atomicAdd(&g_bar_cnt, 1u);
        unsigned target = (my / SC_CTAS + 1u) * SC_CTAS;
        while (*((volatile unsigned*)&g_bar_cnt) < target) { }
    }
    __syncthreads();
    __threadfence();
}

__global__ void __launch_bounds__(256)
scan_kernel(const __half* __restrict__ Wx, const __half* __restrict__ Rt,
            const float* __restrict__ cb,
            __half* __restrict__ yb0, __half* __restrict__ yb1,
            float* __restrict__ yseq)
{
    extern __shared__ __half smh[];
    constexpr int STR = 72, BK = 64, RSTR = 132, S = 3;
    // per stage: A 64x72 + B 128x72 = 13,824 halfs; 3 stages = 41,472 halfs
    __half* As = smh;                     // [S][64][72]
    __half* Bs = smh + S * 64 * STR;      // [S][128][72]
    float*  rawS = (float*)smh;           // [64][132] fp32 = 33,792 B (aliases
                                          //  As/Bs after GEMM; smem covers both)

    const int tid  = threadIdx.x;
    const int lane = tid & 31;
    const int warp = tid >> 5;
    const int wm = (warp >> 2) * 32;      // 2 m-warps x 32
    const int wn = (warp & 3) * 32;       // 4 n-warps x 32
    const int lr = lane >> 2;
    const int lc = lane & 3;
    const int mt = blockIdx.x >> 5;
    const int ht = blockIdx.x & 31;

    const int q_row = (lane & 7) + ((lane >> 3) & 1) * 8;
    const int q_col = (lane >> 4) * 8;
    const uint32_t as_base = (uint32_t)__cvta_generic_to_shared(As);
    const uint32_t bs_base = (uint32_t)__cvta_generic_to_shared(Bs);

    const int hl = tid & 31;
    const int rg = tid >> 5;
    const int h  = ht * 32 + hl;
    const long acol = (long)mt * 64;

    float cbv[4];
#pragma unroll
    for (int g = 0; g < 4; g++) cbv[g] = cb[g * 1024 + h];

    float stc[8], stn[8], stm[8];
#pragma unroll
    for (int j = 0; j < 8; j++) { stc[j] = 0.f; stn[j] = 0.f; stm[j] = 0.f; }

    // zero this CTA's slice of yb0 (2048 halfs = 256 threads x 16B)
    {
        uint4 z = make_uint4(0u, 0u, 0u, 0u);
        *(uint4*)(yb0 + (size_t)blockIdx.x * 2048 + tid * 8) = z;
    }
    grid_bar();

    for (int s = 0; s < SS; s++) {
        const __half* ycur = (s & 1) ? yb1 : yb0;
        __half*       ynxt = (s & 1) ? yb0 : yb1;

        float acc[2][4][4];
#pragma unroll
        for (int mi = 0; mi < 2; mi++)
#pragma unroll
            for (int ni = 0; ni < 4; ni++)
#pragma unroll
                for (int t = 0; t < 4; t++) acc[mi][ni][t] = 0.f;

        auto prefetch = [&](int buf, int k0) {
            // A: 64 rows x 64 halfs = 512 chunks (2/thread)
#pragma unroll
            for (int j = 0; j < 2; j++) {
                int i = tid + j * 256;
                int row = i >> 3, off = (i & 7) * 8;
                cp16(&As[(buf * 64 + row) * STR + off],
                     ycur + (acol + row) * 1024 + k0 + off);
            }
            // B: 128 gathered n-rows x 64 halfs = 1024 chunks (4/thread)
#pragma unroll
            for (int j = 0; j < 4; j++) {
                int i = tid + j * 256;
                int nt = i >> 3, off = (i & 7) * 8;
                long nglob = (long)(nt >> 5) * 1024 + ht * 32 + (nt & 31);
                cp16(&Bs[(buf * 128 + nt) * STR + off],
                     Rt + nglob * 1024 + k0 + off);
            }
        };

        auto compute = [&](int buf) {
#pragma unroll
            for (int kk = 0; kk < BK; kk += 16) {
                uint32_t a[2][4], b[4][2];
#pragma unroll
                for (int mi = 0; mi < 2; mi++) {
                    uint32_t addr = as_base +
                        ((buf * 64 + wm + mi * 16 + q_row) * STR + kk + q_col) * 2;
                    LDSM4(a[mi][0], a[mi][1], a[mi][2], a[mi][3], addr);
                }
#pragma unroll
                for (int np = 0; np < 2; np++) {
                    uint32_t r0, r1, r2, r3;
                    uint32_t addr = bs_base +
                        ((buf * 128 + wn + np * 16 + q_row) * STR + kk + q_col) * 2;
                    LDSM4(r0, r1, r2, r3, addr);
                    b[2 * np][0] = r0; b[2 * np + 1][0] = r1;
                    b[2 * np][1] = r2; b[2 * np + 1][1] = r3;
                }
#pragma unroll
                for (int mi = 0; mi < 2; mi++)
#pragma unroll
                    for (int ni = 0; ni < 4; ni++)
                        mma_f16(acc[mi][ni], a[mi], b[ni]);
            }
        };

        constexpr int NIT = 1024 / BK;   // 16
#pragma unroll
        for (int p = 0; p < S - 1; p++) {
            prefetch(p, p * BK);
            cp_commit();
        }
        for (int it = 0; it < NIT; ++it) {
            cp_wait<S - 2>();
            __syncthreads();
            int nf = it + S - 1;
            if (nf < NIT) prefetch(nf % S, nf * BK);
            cp_commit();
            compute(it % S);
        }
        __syncthreads();   // all compute done before rawS aliases As/Bs

        // stage raw tile to smem (aliases As/Bs; GEMM done)
#pragma unroll
        for (int mi = 0; mi < 2; mi++) {
            int r0 = wm + mi * 16 + lr;
#pragma unroll
            for (int ni = 0; ni < 4; ni++) {
                int c0 = wn + ni * 8 + lc * 2;
                *(float2*)&rawS[r0 * RSTR + c0] =
                    make_float2(acc[mi][ni][0], acc[mi][ni][1]);
                *(float2*)&rawS[(r0 + 8) * RSTR + c0] =
                    make_float2(acc[mi][ni][2], acc[mi][ni][3]);
            }
        }
        __syncthreads();

        // fused gate update: 8 (b,h) pairs per thread, state in registers
#pragma unroll
        for (int j = 0; j < 8; j++) {
            int row = rg * 8 + j;
            long bb = acol + row;
            const __half* wx = Wx + ((bb * SS + s) << 12) + h;

            float ir  = rawS[row * RSTR + hl]      + __half2float(wx[0])    + cbv[0];
            float fr  = rawS[row * RSTR + 32 + hl] + __half2float(wx[1024]) + cbv[1];
            float zr  = rawS[row * RSTR + 64 + hl] + __half2float(wx[2048]) + cbv[2];
            float orr = rawS[row * RSTR + 96 + hl] + __half2float(wx[3072]) + cbv[3];

            float logsig = (fr >= 0.f) ? -log1pf(__expf(-fr))
                                       : (fr - log1pf(__expf(fr)));
            float lfm  = stm[j] + logsig;
            float mnew = (stn[j] == 0.f) ? ir : fmaxf(ir, lfm);
            float ig   = __expf(ir  - mnew);
            float fg   = __expf(lfm - mnew);
            float ez   = __expf(-2.f * fabsf(zr));
            float tz   = copysignf((1.f - ez) / (1.f + ez), zr);
            float cnew = fg * stc[j] + ig * tz;
            float nnew = fg * stn[j] + ig;
            float og   = 1.f / (1.f + __expf(-orr));
            float ynew = og * cnew / nnew;

            stc[j] = cnew;
            stn[j] = nnew;
            stm[j] = mnew;
            ynxt[bb * 1024 + h] = __float2half(ynew);
            yseq[(bb * SS + s) * 1024 + h] = ynew;
        }

        grid_bar();
    }
}

// ---------------------------------------------------------------------------
// fp32 SIMT GEMM (fc only).
template<int BM, int BN, int BK, int TM, int TN>
__global__ void __launch_bounds__(256)
gemm_fc_kernel(const float* __restrict__ A, int lda,
               const float* __restrict__ B, int ldb,
               float* __restrict__ C, int ldc,
               const float* __restrict__ bias, int K)
{
    constexpr int TX = BN / TN;
    constexpr int TY = BM / TM;
    constexpr int NT = TX * TY;

    __shared__ float As[BK][BM + 4];
    __shared__ float Bs[BK][BN + 4];

    const int tid = threadIdx.x;
    const int tx = tid % TX;
    const int ty = tid / TX;
    const long bm0 = (long)blockIdx.y * BM;
    const long bn0 = (long)blockIdx.x * BN;

    float acc[TM][TN];
#pragma unroll
    for (int i = 0; i < TM; i++)
#pragma unroll
        for (int j = 0; j < TN; j++) acc[i][j] = 0.f;

    for (int k0 = 0; k0 < K; k0 += BK) {
#pragma unroll
        for (int i = tid * 4; i < BM * BK; i += NT * 4) {
            int r = i / BK, kk = i % BK;
            float4 v = *(const float4*)(A + (bm0 + r) * (long)lda + (k0 + kk));
            As[kk + 0][r] = v.x; As[kk + 1][r] = v.y;
            As[kk + 2][r] = v.z; As[kk + 3][r] = v.w;
        }
#pragma unroll
        for (int i = tid * 4; i < BN * BK; i += NT * 4) {
            int r = i / BK, kk = i % BK;
            float4 v = *(const float4*)(B + (bn0 + r) * (long)ldb + (k0 + kk));
            Bs[kk + 0][r] = v.x; Bs[kk + 1][r] = v.y;
            Bs[kk + 2][r] = v.z; Bs[kk + 3][r] = v.w;
        }
        __syncthreads();

#pragma unroll
        for (int kk = 0; kk < BK; kk++) {
            float a[TM], b[TN];
#pragma unroll
            for (int i = 0; i < TM; i += 4)
                *(float4*)&a[i] = *(const float4*)&As[kk][ty * TM + i];
#pragma unroll
            for (int j = 0; j < TN; j += 4)
                *(float4*)&b[j] = *(const float4*)&Bs[kk][tx * TN + j];
#pragma unroll
            for (int i = 0; i < TM; i++)
#pragma unroll
                for (int j = 0; j < TN; j++)
                    acc[i][j] = fmaf(a[i], b[j], acc[i][j]);
        }
        __syncthreads();
    }

#pragma unroll
    for (int i = 0; i < TM; i++) {
        long row = bm0 + ty * TM + i;
#pragma unroll
        for (int j = 0; j < TN; j++) {
            long col = bn0 + tx * TN + j;
            C[row * (long)ldc + col] = acc[i][j] + bias[col];
        }
    }
}

// ---------------------------------------------------------------------------
__device__ __forceinline__ void warp_reduce2(float& s, float& ss)
{
#pragma unroll
    for (int o = 16; o > 0; o >>= 1) {
        s  += __shfl_xor_sync(0xFFFFFFFFu, s,  o);
        ss += __shfl_xor_sync(0xFFFFFFFFu, ss, o);
    }
}

// out = LN(x)*w ; OUTH: write halfs, else floats. Warp-per-row (1024 wide).
template<bool OUTH>
__global__ void ln_warp_kernel(const float* __restrict__ x, size_t xs,
                               const float* __restrict__ w,
                               void* __restrict__ outv, size_t os)
{
    int warp = threadIdx.x >> 5, lane = threadIdx.x & 31;
    size_t row = (size_t)blockIdx.x * 8 + warp;
    const float* xr = x + row * xs;
    float4 v[8];
    float s = 0.f, ss = 0.f;
#pragma unroll
    for (int i = 0; i < 8; i++) {
        v[i] = *(const float4*)(xr + i * 128 + lane * 4);
        s  += v[i].x + v[i].y + v[i].z + v[i].w;
        ss += v[i].x * v[i].x + v[i].y * v[i].y + v[i].z * v[i].z + v[i].w * v[i].w;
    }
    warp_reduce2(s, ss);
    float mu  = s * (1.f / 1024.f);
    float var = fmaxf(ss * (1.f / 1024.f) - mu * mu, 0.f);
    float rs  = rsqrtf(var + 1e-5f);
#pragma unroll
    for (int i = 0; i < 8; i++) {
        int c = i * 128 + lane * 4;
        float4 wv = *(const float4*)(w + c);
        float o0 = (v[i].x - mu) * rs * wv.x;
        float o1 = (v[i].y - mu) * rs * wv.y;
        float o2 = (v[i].z - mu) * rs * wv.z;
        float o3 = (v[i].w - mu) * rs * wv.w;
        if (OUTH) {
            __half2* op = (__half2*)((__half*)outv + row * os + c);
            op[0] = __floats2half2_rn(o0, o1);
            op[1] = __floats2half2_rn(o2, o3);
        } else {
            *(float4*)((float*)outv + row * os + c) = make_float4(o0, o1, o2, o3);
        }
    }
}

// Fused: h += LN(yseq)*gn ; fn = LN(h_new)*ln2 (half out). Warp-per-row.
__global__ void lnadd_ln2_kernel(const float* __restrict__ yseq,
                                 const float* __restrict__ gn,
                                 const float* __restrict__ ln2,
                                 float* __restrict__ h,
                                 __half* __restrict__ fn)
{
    int warp = threadIdx.x >> 5, lane = threadIdx.x & 31;
    size_t row = (size_t)blockIdx.x * 8 + warp;
    const float* yr = yseq + row * HH;
    float* hr = h + row * HH;
    float4 v[8], hv[8];
    float s = 0.f, ss = 0.f;
#pragma unroll
    for (int i = 0; i < 8; i++) {
        v[i] = *(const float4*)(yr + i * 128 + lane * 4);
        s  += v[i].x + v[i].y + v[i].z + v[i].w;
        ss += v[i].x * v[i].x + v[i].y * v[i].y + v[i].z * v[i].z + v[i].w * v[i].w;
    }
    warp_reduce2(s, ss);
    float mu  = s * (1.f / 1024.f);
    float var = fmaxf(ss * (1.f / 1024.f) - mu * mu, 0.f);
    float rs  = rsqrtf(var + 1e-5f);
    float s2 = 0.f, ss2 = 0.f;
#pragma unroll
    for (int i = 0; i < 8; i++) {
        int c = i * 128 + lane * 4;
        float4 gv = *(const float4*)(gn + c);
        hv[i] = *(float4*)(hr + c);
        hv[i].x += (v[i].x - mu) * rs * gv.x;
        hv[i].y += (v[i].y - mu) * rs * gv.y;
        hv[i].z += (v[i].z - mu) * rs * gv.z;
        hv[i].w += (v[i].w - mu) * rs * gv.w;
        *(float4*)(hr + c) = hv[i];
        s2  += hv[i].x + hv[i].y + hv[i].z + hv[i].w;
        ss2 += hv[i].x * hv[i].x + hv[i].y * hv[i].y
             + hv[i].z * hv[i].z + hv[i].w * hv[i].w;
    }
    warp_reduce2(s2, ss2);
    float mu2  = s2 * (1.f / 1024.f);
    float var2 = fmaxf(ss2 * (1.f / 1024.f) - mu2 * mu2, 0.f);
    float rs2  = rsqrtf(var2 + 1e-5f);
#pragma unroll
    for (int i = 0; i < 8; i++) {
        int c = i * 128 + lane * 4;
        float4 wv = *(const float4*)(ln2 + c);
        __half2* op = (__half2*)(fn + row * HH + c);
        op[0] = __floats2half2_rn((hv[i].x - mu2) * rs2 * wv.x,
                                  (hv[i].y - mu2) * rs2 * wv.y);
        op[1] = __floats2half2_rn((hv[i].z - mu2) * rs2 * wv.z,
                                  (hv[i].w - mu2) * rs2 * wv.w);
    }
}

// ---------------------------------------------------------------------------
// Depthwise causal conv (K=4) + SiLU; fp16 in/out, fp32 math.
__global__ void conv_silu_kernel(const __half* __restrict__ xn,
                                 const float* __restrict__ cw,
                                 const float* __restrict__ cb,
                                 __half* __restrict__ xc)
{
    size_t q = (size_t)blockIdx.x * blockDim.x + threadIdx.x; // < NTOK*H/4
    int hq = (int)(q & 255);
    size_t t = q >> 8;
    int s = (int)(t % SS);
    int h = hq * 4;
    size_t base = t * HH + h;

    float4 w0 = *(const float4*)(cw + (size_t)h * 4);
    float4 w1 = *(const float4*)(cw + (size_t)(h + 1) * 4);
    float4 w2 = *(const float4*)(cw + (size_t)(h + 2) * 4);
    float4 w3 = *(const float4*)(cw + (size_t)(h + 3) * 4);
    float4 bv = *(const float4*)(cb + h);
    float a0 = bv.x, a1 = bv.y, a2 = bv.z, a3 = bv.w;

#pragma unroll
    for (int k = 0; k < 4; k++) {
        int sp = s - 3 + k;
        if (sp >= 0) {
            const __half2* xp = (const __half2*)(xn + base + (long)(k - 3) * HH);
            float2 x01 = __half22float2(xp[0]);
            float2 x23 = __half22float2(xp[1]);
            a0 = fmaf(x01.x, ((const float*)&w0)[k], a0);
            a1 = fmaf(x01.y, ((const float*)&w1)[k], a1);
            a2 = fmaf(x23.x, ((const float*)&w2)[k], a2);
            a3 = fmaf(x23.y, ((const float*)&w3)[k], a3);
        }
    }
    __half2* op = (__half2*)(xc + base);
    op[0] = __floats2half2_rn(a0 / (1.f + __expf(-a0)), a1 / (1.f + __expf(-a1)));
    op[1] = __floats2half2_rn(a2 / (1.f + __expf(-a2)), a3 / (1.f + __expf(-a3)));
}

// ---------------------------------------------------------------------------
// One-shot prep: convert all weights to fp16 (stack i/f and z/o, transpose R
// to [n][k], interleave ff_up g/v rows, copy emb_w) and convert x to fp16.
__global__ void prep_kernel(const float* __restrict__ Wi,
                            const float* __restrict__ Wf,
                            const float* __restrict__ Wz,
                            const float* __restrict__ Wo,
                            const float* __restrict__ R,
                            const float* __restrict__ up,
                            const float* __restrict__ dn,
                            const float* __restrict__ embw,
                            const float* __restrict__ x,
                            __half* __restrict__ wdst,
                            __half* __restrict__ xdst)
{
    size_t i = (size_t)blockIdx.x * 256 + threadIdx.x;
    if (i >= PREP_N) return;
    const size_t HHHH = (size_t)HH * HH;
    if (i >= W_TOT) {                      // x conversion
        size_t j = i - W_TOT;
        xdst[j] = __float2half(x[j]);
        return;
    }
    float v;
    if (i < W_IFS) {
        size_t l = i / (2 * HHHH), r = i % (2 * HHHH);
        v = (r < HHHH ? Wi : Wf)[l * HHHH + (r % HHHH)];
    } else if (i < 2 * W_IFS) {
        size_t j = i - W_IFS;
        size_t l = j / (2 * HHHH), r = j % (2 * HHHH);
        v = (r < HHHH ? Wz : Wo)[l * HHHH + (r % HHHH)];
    } else if (i < 2 * W_IFS + W_RT) {
        size_t j = i - 2 * W_IFS;
        size_t l = j / ((size_t)H4 * HH);
        size_t rem = j % ((size_t)H4 * HH);
        size_t n = rem / HH, k = rem % HH;       // dst [n][k]
        v = R[l * (size_t)HH * H4 + k * H4 + n]; // src [k][n]
    } else if (i < 2 * W_IFS + W_RT + W_UP) {
        size_t j = i - 2 * W_IFS - W_RT;
        size_t l = j / ((size_t)U2 * HH);
        size_t rem = j % ((size_t)U2 * HH);
        size_t row = rem / HH, col = rem % HH;
        size_t u = row >> 1, half = row & 1;     // even rows = g, odd = v
        v = up[l * (size_t)U2 * HH + (half * UU + u) * HH + col];
    } else if (i < 2 * W_IFS + W_RT + W_UP + W_DN) {
        v = dn[i - 2 * W_IFS - W_RT - W_UP];
    } else {
        v = embw[i - 2 * W_IFS - W_RT - W_UP - W_DN];
    }
    wdst[i] = __float2half(v);
}

// ---------------------------------------------------------------------------
extern "C" void kernel_launch(void* const* d_in, const int* in_sizes, int n_in,
                              void* d_out, int out_size)
{
    (void)in_sizes; (void)n_in; (void)out_size;

    const float* x      = (const float*)d_in[0];
    const float* emb_w  = (const float*)d_in[1];
    const float* emb_b  = (const float*)d_in[2];
    const float* conv_w = (const float*)d_in[3];
    const float* conv_b = (const float*)d_in[4];
    const float* Wi     = (const float*)d_in[5];
    const float* Wf     = (const float*)d_in[6];
    const float* Wz     = (const float*)d_in[7];
    const float* Wo     = (const float*)d_in[8];
    const float* R      = (const float*)d_in[9];
    const float* cell_b = (const float*)d_in[10];
    const float* gn_w   = (const float*)d_in[11];
    const float* ln1_w  = (const float*)d_in[12];
    const float* ln2_w  = (const float*)d_in[13];
    const float* ff_up  = (const float*)d_in[14];
    const float* ff_dn  = (const float*)d_in[15];
    const float* post_w = (const float*)d_in[16];
    const float* fc_w   = (const float*)d_in[17];
    const float* fc_b   = (const float*)d_in[18];
    float* out = (float*)d_out;

    float* S_;
    cudaGetSymbolAddress((void**)&S_, g_scratch);
    float* g_h    = S_;
    float* g_yseq = g_h    + (size_t)NTOK * HH;
    float* g_last = g_yseq + (size_t)NTOK * HH;
    __half* H_    = (__half*)(g_last + (size_t)BB * HH);

    __half* x_h  = H_;
    __half* xn_h = x_h  + (size_t)NTOK * II;
    __half* xc_h = xn_h + (size_t)NTOK * HH;
    __half* Wx_h = xc_h + (size_t)NTOK * HH;    // act_h aliases
    __half* yb0  = Wx_h + (size_t)NTOK * H4;
    __half* yb1  = yb0  + (size_t)BB * HH;
    __half* w_h  = yb1  + (size_t)BB * HH;

    __half* w_if  = w_h;
    __half* w_zo  = w_if + W_IFS;
    __half* w_rt  = w_zo + W_IFS;
    __half* w_up  = w_rt + W_RT;
    __half* w_dn  = w_up + W_UP;
    __half* w_emb = w_dn + W_DN;
    __half* act_h = Wx_h;   // alias

    // scan smem: 3-stage fp16 tiles 3*(64*72 + 128*72)*2 = 82,944 B
    // (also covers the fp32 rawS alias region 33,792 B)
    const int SCAN_SMEM = 3 * (64 * 72 + 128 * 72) * 2;      // 82,944 B
    const int GEMM_SMEM = 2 * 4 * 128 * 40 * 2;              // 81,920 B (4 stages)
    cudaFuncSetAttribute(scan_kernel,
                         cudaFuncAttributeMaxDynamicSharedMemorySize, SCAN_SMEM);
    cudaFuncSetAttribute(gemm_f16_kernel<true,false,false,false>,
                         cudaFuncAttributeMaxDynamicSharedMemorySize, GEMM_SMEM);
    cudaFuncSetAttribute(gemm_f16_kernel<true,false,false,true>,
                         cudaFuncAttributeMaxDynamicSharedMemorySize, GEMM_SMEM);
    cudaFuncSetAttribute(gemm_f16_kernel<false,false,true,false>,
                         cudaFuncAttributeMaxDynamicSharedMemorySize, GEMM_SMEM);
    cudaFuncSetAttribute(gemm_f16_kernel<false,true,false,false>,
                         cudaFuncAttributeMaxDynamicSharedMemorySize, GEMM_SMEM);

    // 0: one-shot conversions
    prep_kernel<<<(unsigned)((PREP_N + 255) / 256), 256>>>(
        Wi, Wf, Wz, Wo, R, ff_up, ff_dn, emb_w, x, w_h, x_h);

    // 1: h = x_h @ emb_w^T + emb_b (fp32 out)
    gemm_f16_kernel<false,false,true,false>
        <<<dim3(HH/128, NTOK/128), 256, GEMM_SMEM>>>(x_h, II, w_emb, II,
                                                     g_h, HH, emb_b, II);

    for (int l = 0; l < LL; l++) {
        // xn = LN(h)*ln1_w  (half out)
        ln_warp_kernel<true><<<NTOK/8, 256>>>(g_h, HH, ln1_w + (size_t)l*HH,
                                              xn_h, HH);
        // Wx cols [2048,4096) = [z|o] = xn @ [Wz;Wo]^T
        gemm_f16_kernel<true,false,false,false>
            <<<dim3(16, 200), 256, GEMM_SMEM>>>(xn_h, HH,
                                                w_zo + (size_t)l*2*HH*HH, HH,
                                                Wx_h + 2048, H4, nullptr, HH);
        // xc = silu(causal_conv(xn))
        conv_silu_kernel<<<(NTOK*HH/4)/256, 256>>>(xn_h,
            conv_w + (size_t)l*HH*KK, conv_b + (size_t)l*HH, xc_h);
        // Wx cols [0,2048) = [i|f] = xc @ [Wi;Wf]^T
        gemm_f16_kernel<true,false,false,false>
            <<<dim3(16, 200), 256, GEMM_SMEM>>>(xc_h, HH,
                                                w_if + (size_t)l*2*HH*HH, HH,
                                                Wx_h, H4, nullptr, HH);

        // persistent fused scan: all 100 steps in one launch
        scan_kernel<<<SC_CTAS, 256, SCAN_SMEM>>>(
            Wx_h, w_rt + (size_t)l*H4*HH, cell_b + (size_t)l*H4,
            yb0, yb1, g_yseq);

        // fused: h += LN(yseq)*gn ; fn = LN(h)*ln2 (half out, into xn_h)
        lnadd_ln2_kernel<<<NTOK/8, 256>>>(g_yseq, gn_w + (size_t)l*HH,
                                          ln2_w + (size_t)l*HH, g_h, xn_h);

        // FFN: act = gelu(g)*v fused in up-GEMM epilogue ; h += act @ ff_dn^T
        gemm_f16_kernel<true,false,false,true>
            <<<dim3(U2/128, 200), 256, GEMM_SMEM>>>(xn_h, HH,
                                                    w_up + (size_t)l*U2*HH, HH,
                                                    act_h, UU, nullptr, HH);
        gemm_f16_kernel<false,true,false,false>
            <<<dim3(8, 200), 256, GEMM_SMEM>>>(act_h, UU,
                                               w_dn + (size_t)l*HH*UU, UU,
                                               g_h, HH, nullptr, UU);
    }

    // post-LN only needed for last timestep (fp32 out)
    ln_warp_kernel<false><<<BB/8, 256>>>(g_h + (size_t)(SS-1)*HH, (size_t)SS*HH,
                                         post_w, g_last, HH);
    // out = last @ fc_w^T + fc_b
    gemm_fc_kernel<64,128,16,4,8>
        <<<dim3(OO/128, BB/64), 256>>>(g_last, HH, fc_w, HH,
                                       out, OO, fc_b, HH);
}

// round 14
// speedup vs baseline: 1.2429x; 1.0395x over previous
#include <cuda_runtime.h>
#include <cuda_fp16.h>
#include <cstddef>
#include <cstdint>

// Problem constants
#define BB   256
#define SS   100
#define II   128
#define HH   1024
#define OO   128
#define LL   2
#define UU   1344
#define KK   4
#define NTOK (BB * SS)          // 25600
#define H4   (4 * HH)           // 4096
#define U2   (2 * UU)           // 2688

// ---------------------------------------------------------------------------
// Scratch layout (identical to round 10/12/13).
#define W_IFS  ((size_t)LL * 2 * HH * HH)   // 4,194,304
#define W_RT   ((size_t)LL * H4 * HH)       // 8,388,608 (transposed [l][n][k])
#define W_UP   ((size_t)LL * U2 * HH)       // 5,505,024 (g/v row-interleaved)
#define W_DN   ((size_t)LL * HH * UU)       // 2,752,512
#define W_EMB  ((size_t)HH * II)            // 131,072
#define W_TOT  (2 * W_IFS + W_RT + W_UP + W_DN + W_EMB)
#define PREP_N (W_TOT + (size_t)NTOK * II)  // + x conversion
#define SCRATCH_FLOATS 146000000ULL
__device__ float g_scratch[SCRATCH_FLOATS];

// monotonic grid-barrier counter (never reset; race-free).
__device__ unsigned g_bar_cnt = 0;

// ---------------------------------------------------------------------------
__device__ __forceinline__ void cp16(void* s, const void* g)
{
    uint32_t sa = (uint32_t)__cvta_generic_to_shared(s);
    asm volatile("cp.async.cg.shared.global [%0], [%1], 16;\n" :: "r"(sa), "l"(g));
}
__device__ __forceinline__ void cp_commit()
{
    asm volatile("cp.async.commit_group;\n" ::);
}
template<int N>
__device__ __forceinline__ void cp_wait()
{
    asm volatile("cp.async.wait_group %0;\n" :: "n"(N));
}

__device__ __forceinline__ void mma_f16(float* d, const uint32_t* a, const uint32_t* b)
{
    asm volatile(
        "mma.sync.aligned.m16n8k16.row.col.f32.f16.f16.f32 "
        "{%0,%1,%2,%3},{%4,%5,%6,%7},{%8,%9},{%0,%1,%2,%3};"
        : "+f"(d[0]), "+f"(d[1]), "+f"(d[2]), "+f"(d[3])
        : "r"(a[0]), "r"(a[1]), "r"(a[2]), "r"(a[3]),
          "r"(b[0]), "r"(b[1]));
}

#define LDSM4(r0, r1, r2, r3, addr) \
    asm volatile("ldmatrix.sync.aligned.m8n8.x4.shared.b16 {%0,%1,%2,%3}, [%4];" \
                 : "=r"(r0), "=r"(r1), "=r"(r2), "=r"(r3) : "r"(addr))

__device__ __forceinline__ float gelu_exact(float g)
{
    return 0.5f * g * (1.f + erff(g * 0.7071067811865476f));
}

// ---------------------------------------------------------------------------
// fp16 tensor-core GEMM.  C[M,N] = A[M,K] * B^T, B stored [N,K] (halfs).
// 128x128x32 tiles, 256 threads, 4-stage cp.async pipeline, ldmatrix m16n8k16.
// (Measured-best config: no min-blocks cap — 95 regs, 2 CTAs/SM. DO NOT add a
//  min-blocks launch bound: round 11 showed it spills accumulators.)
// OUTH: C is half. GELU (implies OUTH): adjacent col pairs (g,v) ->
//   gelu(g)*v into half-width C (ldc = N/2). BIAS/ACC: fp32 C paths.
template<bool OUTH, bool ACC, bool BIAS, bool GELU>
__global__ void __launch_bounds__(256)
gemm_f16_kernel(const __half* __restrict__ A, int lda,
                const __half* __restrict__ B, int ldb,
                void* __restrict__ Cv, int ldc,
                const float* __restrict__ bias, int K)
{
    constexpr int BM = 128, BK = 32, STR = 40, S = 4;
    extern __shared__ __half smh[];
    __half* As = smh;                     // [S][128][40]
    __half* Bs = smh + S * BM * STR;      // [S][128][40]

    const int tid  = threadIdx.x;
    const int lane = tid & 31;
    const int warp = tid >> 5;
    const int wm = (warp >> 2) * 64;
    const int wn = (warp & 3) * 32;
    const int lr = lane >> 2;
    const int lc = lane & 3;
    const long bm0 = (long)blockIdx.y * BM;
    const long bn0 = (long)blockIdx.x * 128;

    const int q_row = (lane & 7) + ((lane >> 3) & 1) * 8;
    const int q_col = (lane >> 4) * 8;    // halfs
    const uint32_t as_base = (uint32_t)__cvta_generic_to_shared(As);
    const uint32_t bs_base = (uint32_t)__cvta_generic_to_shared(Bs);

    float acc[4][4][4];
#pragma unroll
    for (int mi = 0; mi < 4; mi++)
#pragma unroll
        for (int ni = 0; ni < 4; ni++)
#pragma unroll
            for (int t = 0; t < 4; t++) acc[mi][ni][t] = 0.f;

    auto prefetch = [&](int s, int k0) {
        __half* as = As + s * BM * STR;
        __half* bs = Bs + s * BM * STR;
#pragma unroll
        for (int j = 0; j < 2; j++) {
            int i = tid + j * 256;
            int row = i >> 2, off = (i & 3) * 8;
            cp16(as + row * STR + off, A + (bm0 + row) * (long)lda + k0 + off);
        }
#pragma unroll
        for (int j = 0; j < 2; j++) {
            int i = tid + j * 256;
            int row = i >> 2, off = (i & 3) * 8;
            cp16(bs + row * STR + off, B + (bn0 + row) * (long)ldb + k0 + off);
        }
    };

    auto compute = [&](int s) {
#pragma unroll
        for (int kk = 0; kk < BK; kk += 16) {
            uint32_t a[4][4], b[4][2];
#pragma unroll
            for (int mi = 0; mi < 4; mi++) {
                uint32_t addr = as_base +
                    ((s * BM + wm + mi * 16 + q_row) * STR + kk + q_col) * 2;
                LDSM4(a[mi][0], a[mi][1], a[mi][2], a[mi][3], addr);
            }
#pragma unroll
            for (int np = 0; np < 2; np++) {
                uint32_t r0, r1, r2, r3;
                uint32_t addr = bs_base +
                    ((s * BM + wn + np * 16 + q_row) * STR + kk + q_col) * 2;
                LDSM4(r0, r1, r2, r3, addr);
                b[2 * np][0] = r0; b[2 * np + 1][0] = r1;
                b[2 * np][1] = r2; b[2 * np + 1][1] = r3;
            }
#pragma unroll
            for (int mi = 0; mi < 4; mi++)
#pragma unroll
                for (int ni = 0; ni < 4; ni++)
                    mma_f16(acc[mi][ni], a[mi], b[ni]);
        }
    };

    const int NIT = K / BK;
#pragma unroll
    for (int s = 0; s < S - 1; s++) {
        if (s < NIT) prefetch(s, s * BK);
        cp_commit();
    }
    for (int it = 0; it < NIT; ++it) {
        cp_wait<S - 2>();
        __syncthreads();
        int nf = it + S - 1;
        if (nf < NIT) prefetch(nf % S, nf * BK);
        cp_commit();
        compute(it % S);
    }

    // Epilogue
#pragma unroll
    for (int mi = 0; mi < 4; mi++) {
        long r0 = bm0 + wm + mi * 16 + lr;
#pragma unroll
        for (int ni = 0; ni < 4; ni++) {
            long c0 = bn0 + wn + ni * 8 + lc * 2;
            if (GELU) {
                __half* C = (__half*)Cv;
                long j = c0 >> 1;
                C[r0 * (long)ldc + j] =
                    __float2half(gelu_exact(acc[mi][ni][0]) * acc[mi][ni][1]);
                C[(r0 + 8) * (long)ldc + j] =
                    __float2half(gelu_exact(acc[mi][ni][2]) * acc[mi][ni][3]);
            } else if (OUTH) {
                __half* C = (__half*)Cv;
                *(__half2*)(C + r0 * (long)ldc + c0) =
                    __floats2half2_rn(acc[mi][ni][0], acc[mi][ni][1]);
                *(__half2*)(C + (r0 + 8) * (long)ldc + c0) =
                    __floats2half2_rn(acc[mi][ni][2], acc[mi][ni][3]);
            } else {
                float* C = (float*)Cv;
                float2* p0 = (float2*)(C + r0 * (long)ldc + c0);
                float2* p1 = (float2*)(C + (r0 + 8) * (long)ldc + c0);
                float b0 = 0.f, b1 = 0.f;
                if (BIAS) { b0 = bias[c0]; b1 = bias[c0 + 1]; }
                if (ACC) {
                    float2 v0 = *p0, v1 = *p1;
                    v0.x += acc[mi][ni][0] + b0; v0.y += acc[mi][ni][1] + b1;
                    v1.x += acc[mi][ni][2] + b0; v1.y += acc[mi][ni][3] + b1;
                    *p0 = v0; *p1 = v1;
                } else {
                    *p0 = make_float2(acc[mi][ni][0] + b0, acc[mi][ni][1] + b1);
                    *p1 = make_float2(acc[mi][ni][2] + b0, acc[mi][ni][3] + b1);
                }
            }
        }
    }
}

// ---------------------------------------------------------------------------
// Persistent fused sLSTM scan kernel — R-RESIDENT version.
// 128 CTAs: mt = bid>>6 in [0,2): 128 batch rows; ht = bid&63: 16 h.
// Each CTA's B operand (64 gathered Rt n-rows x 1024 k) lives in smem for the
// whole scan (loaded ONCE — kills the 32 MB/step L2 re-read of R).
// A (y_prev, 128 rows) is 3-stage cp.async pipelined per step.
// State (c,n,m) fp32 in registers; y fp16 double-buffered in scratch.
#define SC_CTAS 128

// Race-free monotonic grid barrier (ticket / epoch; no reset, no phase word).
__device__ __forceinline__ void grid_bar()
{
    __syncthreads();
    __threadfence();
    if (threadIdx.x == 0) {
        unsigned my = atomicAdd(&g_bar_cnt, 1u);
        unsigned target = (my / SC_CTAS + 1u) * SC_CTAS;
        while (*((volatile unsigned*)&g_bar_cnt) < target) { }
    }
    __syncthreads();
    __threadfence();
}

__global__ void __launch_bounds__(256)
scan_kernel(const __half* __restrict__ Wx, const __half* __restrict__ Rt,
            const float* __restrict__ cb,
            __half* __restrict__ yb0, __half* __restrict__ yb1,
            float* __restrict__ yseq)
{
    extern __shared__ __half smh[];
    constexpr int BSTR = 1032;            // resident B row stride (halfs)
    constexpr int ASTR = 72, BK = 64, RSTR = 66, S = 3;
    __half* Bs = smh;                     // [64][1032] = 66,048 halfs (132,096 B)
    __half* As = smh + 64 * BSTR;         // [S][128][72] = 27,648 halfs (55,296 B)
    float*  rawS = (float*)As;            // [128][66] fp32 = 33,792 B (aliases As
                                          //  after final sync; 55,296 B covers it)

    const int tid  = threadIdx.x;
    const int lane = tid & 31;
    const int warp = tid >> 5;
    const int wm = (warp & 3) * 32;       // 4 m-warps x 32 rows
    const int wn = (warp >> 2) * 32;      // 2 n-warps x 32 cols
    const int lr = lane >> 2;
    const int lc = lane & 3;
    const int mt = blockIdx.x >> 6;       // 0..1
    const int ht = blockIdx.x & 63;       // 0..63

    const int q_row = (lane & 7) + ((lane >> 3) & 1) * 8;
    const int q_col = (lane >> 4) * 8;
    const uint32_t as_base = (uint32_t)__cvta_generic_to_shared(As);
    const uint32_t bs_base = (uint32_t)__cvta_generic_to_shared(Bs);

    const int hl = tid & 15;              // h within CTA's 16
    const int rg = tid >> 4;              // 0..15, 8 rows each
    const int h  = ht * 16 + hl;
    const long acol = (long)mt * 128;     // batch-row offset

    float cbv[4];
#pragma unroll
    for (int g = 0; g < 4; g++) cbv[g] = cb[g * 1024 + h];

    float stc[8], stn[8], stm[8];
#pragma unroll
    for (int j = 0; j < 8; j++) { stc[j] = 0.f; stn[j] = 0.f; stm[j] = 0.f; }

    // zero this CTA's slice of yb0 (2048 halfs = 256 threads x 16B)
    {
        uint4 z = make_uint4(0u, 0u, 0u, 0u);
        *(uint4*)(yb0 + (size_t)blockIdx.x * 2048 + tid * 8) = z;
    }

    // one-time resident B load: 64 gathered n-rows x 1024 halfs
    // row nt -> Rt row (nt>>4)*1024 + ht*16 + (nt&15)
#pragma unroll
    for (int j = 0; j < 32; j++) {
        int i = tid + j * 256;            // 0..8191 chunks
        int nt  = i >> 7;                 // 128 chunks per row
        int off = (i & 127) * 8;
        long nglob = (long)(nt >> 4) * 1024 + ht * 16 + (nt & 15);
        cp16(&Bs[nt * BSTR + off], Rt + nglob * 1024 + off);
    }
    cp_commit();
    cp_wait<0>();
    grid_bar();   // covers yb0 zeroing + B residency

    for (int s = 0; s < SS; s++) {
        const __half* ycur = (s & 1) ? yb1 : yb0;
        __half*       ynxt = (s & 1) ? yb0 : yb1;

        float acc[2][4][4];
#pragma unroll
        for (int mi = 0; mi < 2; mi++)
#pragma unroll
            for (int ni = 0; ni < 4; ni++)
#pragma unroll
                for (int t = 0; t < 4; t++) acc[mi][ni][t] = 0.f;

        auto prefetch = [&](int buf, int k0) {
            // A: 128 rows x 64 halfs = 1024 chunks (4/thread)
#pragma unroll
            for (int j = 0; j < 4; j++) {
                int i = tid + j * 256;
                int row = i >> 3, off = (i & 7) * 8;
                cp16(&As[(buf * 128 + row) * ASTR + off],
                     ycur + (acol + row) * 1024 + k0 + off);
            }
        };

        auto compute = [&](int buf, int k0) {
#pragma unroll
            for (int kk = 0; kk < BK; kk += 16) {
                uint32_t a[2][4], b[4][2];
#pragma unroll
                for (int mi = 0; mi < 2; mi++) {
                    uint32_t addr = as_base +
                        ((buf * 128 + wm + mi * 16 + q_row) * ASTR + kk + q_col) * 2;
                    LDSM4(a[mi][0], a[mi][1], a[mi][2], a[mi][3], addr);
                }
#pragma unroll
                for (int np = 0; np < 2; np++) {
                    uint32_t r0, r1, r2, r3;
                    uint32_t addr = bs_base +
                        ((wn + np * 16 + q_row) * BSTR + k0 + kk + q_col) * 2;
                    LDSM4(r0, r1, r2, r3, addr);
                    b[2 * np][0] = r0; b[2 * np + 1][0] = r1;
                    b[2 * np][1] = r2; b[2 * np + 1][1] = r3;
                }
#pragma unroll
                for (int mi = 0; mi < 2; mi++)
#pragma unroll
                    for (int ni = 0; ni < 4; ni++)
                        mma_f16(acc[mi][ni], a[mi], b[ni]);
            }
        };

        constexpr int NIT = 1024 / BK;    // 16
#pragma unroll
        for (int p = 0; p < S - 1; p++) {
            prefetch(p, p * BK);
            cp_commit();
        }
        for (int it = 0; it < NIT; ++it) {
            cp_wait<S - 2>();
            __syncthreads();
            int nf = it + S - 1;
            if (nf < NIT) prefetch(nf % S, nf * BK);
            cp_commit();
            compute(it % S, it * BK);
        }
        __syncthreads();   // all compute done before rawS aliases As

        // stage raw tile to smem (aliases As; GEMM done)
#pragma unroll
        for (int mi = 0; mi < 2; mi++) {
            int r0 = wm + mi * 16 + lr;
#pragma unroll
            for (int ni = 0; ni < 4; ni++) {
                int c0 = wn + ni * 8 + lc * 2;
                *(float2*)&rawS[r0 * RSTR + c0] =
                    make_float2(acc[mi][ni][0], acc[mi][ni][1]);
                *(float2*)&rawS[(r0 + 8) * RSTR + c0] =
                    make_float2(acc[mi][ni][2], acc[mi][ni][3]);
            }
        }
        __syncthreads();

        // fused gate update: 8 (b,h) pairs per thread, state in registers
        // rawS col layout: gate g at g*16 + hl
#pragma unroll
        for (int j = 0; j < 8; j++) {
            int row = rg * 8 + j;         // 0..127
            long bb = acol + row;
            const __half* wx = Wx + ((bb * SS + s) << 12) + h;

            float ir  = rawS[row * RSTR + hl]      + __half2float(wx[0])    + cbv[0];
            float fr  = rawS[row * RSTR + 16 + hl] + __half2float(wx[1024]) + cbv[1];
            float zr  = rawS[row * RSTR + 32 + hl] + __half2float(wx[2048]) + cbv[2];
            float orr = rawS[row * RSTR + 48 + hl] + __half2float(wx[3072]) + cbv[3];

            float logsig = (fr >= 0.f) ? -log1pf(__expf(-fr))
                                       : (fr - log1pf(__expf(fr)));
            float lfm  = stm[j] + logsig;
            float mnew = (stn[j] == 0.f) ? ir : fmaxf(ir, lfm);
            float ig   = __expf(ir  - mnew);
            float fg   = __expf(lfm - mnew);
            float ez   = __expf(-2.f * fabsf(zr));
            float tz   = copysignf((1.f - ez) / (1.f + ez), zr);
            float cnew = fg * stc[j] + ig * tz;
            float nnew = fg * stn[j] + ig;
            float og   = 1.f / (1.f + __expf(-orr));
            float ynew = og * cnew / nnew;

            stc[j] = cnew;
            stn[j] = nnew;
            stm[j] = mnew;
            ynxt[bb * 1024 + h] = __float2half(ynew);
            yseq[(bb * SS + s) * 1024 + h] = ynew;
        }

        grid_bar();
    }
}

// ---------------------------------------------------------------------------
// fp32 SIMT GEMM (fc only).
template<int BM, int BN, int BK, int TM, int TN>
__global__ void __launch_bounds__(256)
gemm_fc_kernel(const float* __restrict__ A, int lda,
               const float* __restrict__ B, int ldb,
               float* __restrict__ C, int ldc,
               const float* __restrict__ bias, int K)
{
    constexpr int TX = BN / TN;
    constexpr int TY = BM / TM;
    constexpr int NT = TX * TY;

    __shared__ float As[BK][BM + 4];
    __shared__ float Bs[BK][BN + 4];

    const int tid = threadIdx.x;
    const int tx = tid % TX;
    const int ty = tid / TX;
    const long bm0 = (long)blockIdx.y * BM;
    const long bn0 = (long)blockIdx.x * BN;

    float acc[TM][TN];
#pragma unroll
    for (int i = 0; i < TM; i++)
#pragma unroll
        for (int j = 0; j < TN; j++) acc[i][j] = 0.f;

    for (int k0 = 0; k0 < K; k0 += BK) {
#pragma unroll
        for (int i = tid * 4; i < BM * BK; i += NT * 4) {
            int r = i / BK, kk = i % BK;
            float4 v = *(const float4*)(A + (bm0 + r) * (long)lda + (k0 + kk));
            As[kk + 0][r] = v.x; As[kk + 1][r] = v.y;
            As[kk + 2][r] = v.z; As[kk + 3][r] = v.w;
        }
#pragma unroll
        for (int i = tid * 4; i < BN * BK; i += NT * 4) {
            int r = i / BK, kk = i % BK;
            float4 v = *(const float4*)(B + (bn0 + r) * (long)ldb + (k0 + kk));
            Bs[kk + 0][r] = v.x; Bs[kk + 1][r] = v.y;
            Bs[kk + 2][r] = v.z; Bs[kk + 3][r] = v.w;
        }
        __syncthreads();

#pragma unroll
        for (int kk = 0; kk < BK; kk++) {
            float a[TM], b[TN];
#pragma unroll
            for (int i = 0; i < TM; i += 4)
                *(float4*)&a[i] = *(const float4*)&As[kk][ty * TM + i];
#pragma unroll
            for (int j = 0; j < TN; j += 4)
                *(float4*)&b[j] = *(const float4*)&Bs[kk][tx * TN + j];
#pragma unroll
            for (int i = 0; i < TM; i++)
#pragma unroll
                for (int j = 0; j < TN; j++)
                    acc[i][j] = fmaf(a[i], b[j], acc[i][j]);
        }
        __syncthreads();
    }

#pragma unroll
    for (int i = 0; i < TM; i++) {
        long row = bm0 + ty * TM + i;
#pragma unroll
        for (int j = 0; j < TN; j++) {
            long col = bn0 + tx * TN + j;
            C[row * (long)ldc + col] = acc[i][j] + bias[col];
        }
    }
}

// ---------------------------------------------------------------------------
__device__ __forceinline__ void warp_reduce2(float& s, float& ss)
{
#pragma unroll
    for (int o = 16; o > 0; o >>= 1) {
        s  += __shfl_xor_sync(0xFFFFFFFFu, s,  o);
        ss += __shfl_xor_sync(0xFFFFFFFFu, ss, o);
    }
}

// out = LN(x)*w ; OUTH: write halfs, else floats. Warp-per-row (1024 wide).
template<bool OUTH>
__global__ void ln_warp_kernel(const float* __restrict__ x, size_t xs,
                               const float* __restrict__ w,
                               void* __restrict__ outv, size_t os)
{
    int warp = threadIdx.x >> 5, lane = threadIdx.x & 31;
    size_t row = (size_t)blockIdx.x * 8 + warp;
    const float* xr = x + row * xs;
    float4 v[8];
    float s = 0.f, ss = 0.f;
#pragma unroll
    for (int i = 0; i < 8; i++) {
        v[i] = *(const float4*)(xr + i * 128 + lane * 4);
        s  += v[i].x + v[i].y + v[i].z + v[i].w;
        ss += v[i].x * v[i].x + v[i].y * v[i].y + v[i].z * v[i].z + v[i].w * v[i].w;
    }
    warp_reduce2(s, ss);
    float mu  = s * (1.f / 1024.f);
    float var = fmaxf(ss * (1.f / 1024.f) - mu * mu, 0.f);
    float rs  = rsqrtf(var + 1e-5f);
#pragma unroll
    for (int i = 0; i < 8; i++) {
        int c = i * 128 + lane * 4;
        float4 wv = *(const float4*)(w + c);
        float o0 = (v[i].x - mu) * rs * wv.x;
        float o1 = (v[i].y - mu) * rs * wv.y;
        float o2 = (v[i].z - mu) * rs * wv.z;
        float o3 = (v[i].w - mu) * rs * wv.w;
        if (OUTH) {
            __half2* op = (__half2*)((__half*)outv + row * os + c);
            op[0] = __floats2half2_rn(o0, o1);
            op[1] = __floats2half2_rn(o2, o3);
        } else {
            *(float4*)((float*)outv + row * os + c) = make_float4(o0, o1, o2, o3);
        }
    }
}

// Fused: h += LN(yseq)*gn ; fn = LN(h_new)*ln2 (half out). Warp-per-row.
__global__ void lnadd_ln2_kernel(const float* __restrict__ yseq,
                                 const float* __restrict__ gn,
                                 const float* __restrict__ ln2,
                                 float* __restrict__ h,
                                 __half* __restrict__ fn)
{
    int warp = threadIdx.x >> 5, lane = threadIdx.x & 31;
    size_t row = (size_t)blockIdx.x * 8 + warp;
    const float* yr = yseq + row * HH;
    float* hr = h + row * HH;
    float4 v[8], hv[8];
    float s = 0.f, ss = 0.f;
#pragma unroll
    for (int i = 0; i < 8; i++) {
        v[i] = *(const float4*)(yr + i * 128 + lane * 4);
        s  += v[i].x + v[i].y + v[i].z + v[i].w;
        ss += v[i].x * v[i].x + v[i].y * v[i].y + v[i].z * v[i].z + v[i].w * v[i].w;
    }
    warp_reduce2(s, ss);
    float mu  = s * (1.f / 1024.f);
    float var = fmaxf(ss * (1.f / 1024.f) - mu * mu, 0.f);
    float rs  = rsqrtf(var + 1e-5f);
    float s2 = 0.f, ss2 = 0.f;
#pragma unroll
    for (int i = 0; i < 8; i++) {
        int c = i * 128 + lane * 4;
        float4 gv = *(const float4*)(gn + c);
        hv[i] = *(float4*)(hr + c);
        hv[i].x += (v[i].x - mu) * rs * gv.x;
        hv[i].y += (v[i].y - mu) * rs * gv.y;
        hv[i].z += (v[i].z - mu) * rs * gv.z;
        hv[i].w += (v[i].w - mu) * rs * gv.w;
        *(float4*)(hr + c) = hv[i];
        s2  += hv[i].x + hv[i].y + hv[i].z + hv[i].w;
        ss2 += hv[i].x * hv[i].x + hv[i].y * hv[i].y
             + hv[i].z * hv[i].z + hv[i].w * hv[i].w;
    }
    warp_reduce2(s2, ss2);
    float mu2  = s2 * (1.f / 1024.f);
    float var2 = fmaxf(ss2 * (1.f / 1024.f) - mu2 * mu2, 0.f);
    float rs2  = rsqrtf(var2 + 1e-5f);
#pragma unroll
    for (int i = 0; i < 8; i++) {
        int c = i * 128 + lane * 4;
        float4 wv = *(const float4*)(ln2 + c);
        __half2* op = (__half2*)(fn + row * HH + c);
        op[0] = __floats2half2_rn((hv[i].x - mu2) * rs2 * wv.x,
                                  (hv[i].y - mu2) * rs2 * wv.y);
        op[1] = __floats2half2_rn((hv[i].z - mu2) * rs2 * wv.z,
                                  (hv[i].w - mu2) * rs2 * wv.w);
    }
}

// ---------------------------------------------------------------------------
// Depthwise causal conv (K=4) + SiLU; fp16 in/out, fp32 math.
__global__ void conv_silu_kernel(const __half* __restrict__ xn,
                                 const float* __restrict__ cw,
                                 const float* __restrict__ cb,
                                 __half* __restrict__ xc)
{
    size_t q = (size_t)blockIdx.x * blockDim.x + threadIdx.x; // < NTOK*H/4
    int hq = (int)(q & 255);
    size_t t = q >> 8;
    int s = (int)(t % SS);
    int h = hq * 4;
    size_t base = t * HH + h;

    float4 w0 = *(const float4*)(cw + (size_t)h * 4);
    float4 w1 = *(const float4*)(cw + (size_t)(h + 1) * 4);
    float4 w2 = *(const float4*)(cw + (size_t)(h + 2) * 4);
    float4 w3 = *(const float4*)(cw + (size_t)(h + 3) * 4);
    float4 bv = *(const float4*)(cb + h);
    float a0 = bv.x, a1 = bv.y, a2 = bv.z, a3 = bv.w;

#pragma unroll
    for (int k = 0; k < 4; k++) {
        int sp = s - 3 + k;
        if (sp >= 0) {
            const __half2* xp = (const __half2*)(xn + base + (long)(k - 3) * HH);
            float2 x01 = __half22float2(xp[0]);
            float2 x23 = __half22float2(xp[1]);
            a0 = fmaf(x01.x, ((const float*)&w0)[k], a0);
            a1 = fmaf(x01.y, ((const float*)&w1)[k], a1);
            a2 = fmaf(x23.x, ((const float*)&w2)[k], a2);
            a3 = fmaf(x23.y, ((const float*)&w3)[k], a3);
        }
    }
    __half2* op = (__half2*)(xc + base);
    op[0] = __floats2half2_rn(a0 / (1.f + __expf(-a0)), a1 / (1.f + __expf(-a1)));
    op[1] = __floats2half2_rn(a2 / (1.f + __expf(-a2)), a3 / (1.f + __expf(-a3)));
}

// ---------------------------------------------------------------------------
// One-shot prep: convert all weights to fp16 (stack i/f and z/o, transpose R
// to [n][k], interleave ff_up g/v rows, copy emb_w) and convert x to fp16.
__global__ void prep_kernel(const float* __restrict__ Wi,
                            const float* __restrict__ Wf,
                            const float* __restrict__ Wz,
                            const float* __restrict__ Wo,
                            const float* __restrict__ R,
                            const float* __restrict__ up,
                            const float* __restrict__ dn,
                            const float* __restrict__ embw,
                            const float* __restrict__ x,
                            __half* __restrict__ wdst,
                            __half* __restrict__ xdst)
{
    size_t i = (size_t)blockIdx.x * 256 + threadIdx.x;
    if (i >= PREP_N) return;
    const size_t HHHH = (size_t)HH * HH;
    if (i >= W_TOT) {                      // x conversion
        size_t j = i - W_TOT;
        xdst[j] = __float2half(x[j]);
        return;
    }
    float v;
    if (i < W_IFS) {
        size_t l = i / (2 * HHHH), r = i % (2 * HHHH);
        v = (r < HHHH ? Wi : Wf)[l * HHHH + (r % HHHH)];
    } else if (i < 2 * W_IFS) {
        size_t j = i - W_IFS;
        size_t l = j / (2 * HHHH), r = j % (2 * HHHH);
        v = (r < HHHH ? Wz : Wo)[l * HHHH + (r % HHHH)];
    } else if (i < 2 * W_IFS + W_RT) {
        size_t j = i - 2 * W_IFS;
        size_t l = j / ((size_t)H4 * HH);
        size_t rem = j % ((size_t)H4 * HH);
        size_t n = rem / HH, k = rem % HH;       // dst [n][k]
        v = R[l * (size_t)HH * H4 + k * H4 + n]; // src [k][n]
    } else if (i < 2 * W_IFS + W_RT + W_UP) {
        size_t j = i - 2 * W_IFS - W_RT;
        size_t l = j / ((size_t)U2 * HH);
        size_t rem = j % ((size_t)U2 * HH);
        size_t row = rem / HH, col = rem % HH;
        size_t u = row >> 1, half = row & 1;     // even rows = g, odd = v
        v = up[l * (size_t)U2 * HH + (half * UU + u) * HH + col];
    } else if (i < 2 * W_IFS + W_RT + W_UP + W_DN) {
        v = dn[i - 2 * W_IFS - W_RT - W_UP];
    } else {
        v = embw[i - 2 * W_IFS - W_RT - W_UP - W_DN];
    }
    wdst[i] = __float2half(v);
}

// ---------------------------------------------------------------------------
extern "C" void kernel_launch(void* const* d_in, const int* in_sizes, int n_in,
                              void* d_out, int out_size)
{
    (void)in_sizes; (void)n_in; (void)out_size;

    const float* x      = (const float*)d_in[0];
    const float* emb_w  = (const float*)d_in[1];
    const float* emb_b  = (const float*)d_in[2];
    const float* conv_w = (const float*)d_in[3];
    const float* conv_b = (const float*)d_in[4];
    const float* Wi     = (const float*)d_in[5];
    const float* Wf     = (const float*)d_in[6];
    const float* Wz     = (const float*)d_in[7];
    const float* Wo     = (const float*)d_in[8];
    const float* R      = (const float*)d_in[9];
    const float* cell_b = (const float*)d_in[10];
    const float* gn_w   = (const float*)d_in[11];
    const float* ln1_w  = (const float*)d_in[12];
    const float* ln2_w  = (const float*)d_in[13];
    const float* ff_up  = (const float*)d_in[14];
    const float* ff_dn  = (const float*)d_in[15];
    const float* post_w = (const float*)d_in[16];
    const float* fc_w   = (const float*)d_in[17];
    const float* fc_b   = (const float*)d_in[18];
    float* out = (float*)d_out;

    float* S_;
    cudaGetSymbolAddress((void**)&S_, g_scratch);
    float* g_h    = S_;
    float* g_yseq = g_h    + (size_t)NTOK * HH;
    float* g_last = g_yseq + (size_t)NTOK * HH;
    __half* H_    = (__half*)(g_last + (size_t)BB * HH);

    __half* x_h  = H_;
    __half* xn_h = x_h  + (size_t)NTOK * II;
    __half* xc_h = xn_h + (size_t)NTOK * HH;
    __half* Wx_h = xc_h + (size_t)NTOK * HH;    // act_h aliases
    __half* yb0  = Wx_h + (size_t)NTOK * H4;
    __half* yb1  = yb0  + (size_t)BB * HH;
    __half* w_h  = yb1  + (size_t)BB * HH;

    __half* w_if  = w_h;
    __half* w_zo  = w_if + W_IFS;
    __half* w_rt  = w_zo + W_IFS;
    __half* w_up  = w_rt + W_RT;
    __half* w_dn  = w_up + W_UP;
    __half* w_emb = w_dn + W_DN;
    __half* act_h = Wx_h;   // alias

    // scan smem: resident B 64*1032*2 = 132,096 B + A stages 3*128*72*2 =
    // 55,296 B -> 187,392 B total (rawS 33,792 B aliases the A stages).
    const int SCAN_SMEM = 64 * 1032 * 2 + 3 * 128 * 72 * 2; // 187,392 B
    const int GEMM_SMEM = 2 * 4 * 128 * 40 * 2;             // 81,920 B (4 stages)
    cudaFuncSetAttribute(scan_kernel,
                         cudaFuncAttributeMaxDynamicSharedMemorySize, SCAN_SMEM);
    cudaFuncSetAttribute(gemm_f16_kernel<true,false,false,false>,
                         cudaFuncAttributeMaxDynamicSharedMemorySize, GEMM_SMEM);
    cudaFuncSetAttribute(gemm_f16_kernel<true,false,false,true>,
                         cudaFuncAttributeMaxDynamicSharedMemorySize, GEMM_SMEM);
    cudaFuncSetAttribute(gemm_f16_kernel<false,false,true,false>,
                         cudaFuncAttributeMaxDynamicSharedMemorySize, GEMM_SMEM);
    cudaFuncSetAttribute(gemm_f16_kernel<false,true,false,false>,
                         cudaFuncAttributeMaxDynamicSharedMemorySize, GEMM_SMEM);

    // 0: one-shot conversions
    prep_kernel<<<(unsigned)((PREP_N + 255) / 256), 256>>>(
        Wi, Wf, Wz, Wo, R, ff_up, ff_dn, emb_w, x, w_h, x_h);

    // 1: h = x_h @ emb_w^T + emb_b (fp32 out)
    gemm_f16_kernel<false,false,true,false>
        <<<dim3(HH/128, NTOK/128), 256, GEMM_SMEM>>>(x_h, II, w_emb, II,
                                                     g_h, HH, emb_b, II);

    for (int l = 0; l < LL; l++) {
        // xn = LN(h)*ln1_w  (half out)
        ln_warp_kernel<true><<<NTOK/8, 256>>>(g_h, HH, ln1_w + (size_t)l*HH,
                                              xn_h, HH);
        // Wx cols [2048,4096) = [z|o] = xn @ [Wz;Wo]^T
        gemm_f16_kernel<true,false,false,false>
            <<<dim3(16, 200), 256, GEMM_SMEM>>>(xn_h, HH,
                                                w_zo + (size_t)l*2*HH*HH, HH,
                                                Wx_h + 2048, H4, nullptr, HH);
        // xc = silu(causal_conv(xn))
        conv_silu_kernel<<<(NTOK*HH/4)/256, 256>>>(xn_h,
            conv_w + (size_t)l*HH*KK, conv_b + (size_t)l*HH, xc_h);
        // Wx cols [0,2048) = [i|f] = xc @ [Wi;Wf]^T
        gemm_f16_kernel<true,false,false,false>
            <<<dim3(16, 200), 256, GEMM_SMEM>>>(xc_h, HH,
                                                w_if + (size_t)l*2*HH*HH, HH,
                                                Wx_h, H4, nullptr, HH);

        // persistent fused scan: all 100 steps in one launch
        scan_kernel<<<SC_CTAS, 256, SCAN_SMEM>>>(
            Wx_h, w_rt + (size_t)l*H4*HH, cell_b + (size_t)l*H4,
            yb0, yb1, g_yseq);

        // fused: h += LN(yseq)*gn ; fn = LN(h)*ln2 (half out, into xn_h)
        lnadd_ln2_kernel<<<NTOK/8, 256>>>(g_yseq, gn_w + (size_t)l*HH,
                                          ln2_w + (size_t)l*HH, g_h, xn_h);

        // FFN: act = gelu(g)*v fused in up-GEMM epilogue ; h += act @ ff_dn^T
        gemm_f16_kernel<true,false,false,true>
            <<<dim3(U2/128, 200), 256, GEMM_SMEM>>>(xn_h, HH,
                                                    w_up + (size_t)l*U2*HH, HH,
                                                    act_h, UU, nullptr, HH);
        gemm_f16_kernel<false,true,false,false>
            <<<dim3(8, 200), 256, GEMM_SMEM>>>(act_h, UU,
                                               w_dn + (size_t)l*HH*UU, UU,
                                               g_h, HH, nullptr, UU);
    }

    // post-LN only needed for last timestep (fp32 out)
    ln_warp_kernel<false><<<BB/8, 256>>>(g_h + (size_t)(SS-1)*HH, (size_t)SS*HH,
                                         post_w, g_last, HH);
    // out = last @ fc_w^T + fc_b
    gemm_fc_kernel<64,128,16,4,8>
        <<<dim3(OO/128, BB/64), 256>>>(g_last, HH, fc_w, HH,
                                       out, OO, fc_b, HH);
}

// round 15
// speedup vs baseline: 1.3520x; 1.0878x over previous
#include <cuda_runtime.h>
#include <cuda_fp16.h>
#include <cstddef>
#include <cstdint>

// Problem constants
#define BB   256
#define SS   100
#define II   128
#define HH   1024
#define OO   128
#define LL   2
#define UU   1344
#define KK   4
#define NTOK (BB * SS)          // 25600
#define H4   (4 * HH)           // 4096
#define U2   (2 * UU)           // 2688

// ---------------------------------------------------------------------------
// Scratch layout (identical to round 10/12/13/14).
#define W_IFS  ((size_t)LL * 2 * HH * HH)   // 4,194,304
#define W_RT   ((size_t)LL * H4 * HH)       // 8,388,608 (transposed [l][n][k])
#define W_UP   ((size_t)LL * U2 * HH)       // 5,505,024 (g/v row-interleaved)
#define W_DN   ((size_t)LL * HH * UU)       // 2,752,512
#define W_EMB  ((size_t)HH * II)            // 131,072
#define W_TOT  (2 * W_IFS + W_RT + W_UP + W_DN + W_EMB)
#define PREP_N (W_TOT + (size_t)NTOK * II)  // + x conversion
#define SCRATCH_FLOATS 146000000ULL
__device__ float g_scratch[SCRATCH_FLOATS];

// monotonic grid-barrier counter (never reset; race-free).
__device__ unsigned g_bar_cnt = 0;

// ---------------------------------------------------------------------------
__device__ __forceinline__ void cp16(void* s, const void* g)
{
    uint32_t sa = (uint32_t)__cvta_generic_to_shared(s);
    asm volatile("cp.async.cg.shared.global [%0], [%1], 16;\n" :: "r"(sa), "l"(g));
}
__device__ __forceinline__ void cp_commit()
{
    asm volatile("cp.async.commit_group;\n" ::);
}
template<int N>
__device__ __forceinline__ void cp_wait()
{
    asm volatile("cp.async.wait_group %0;\n" :: "n"(N));
}

__device__ __forceinline__ void mma_f16(float* d, const uint32_t* a, const uint32_t* b)
{
    asm volatile(
        "mma.sync.aligned.m16n8k16.row.col.f32.f16.f16.f32 "
        "{%0,%1,%2,%3},{%4,%5,%6,%7},{%8,%9},{%0,%1,%2,%3};"
        : "+f"(d[0]), "+f"(d[1]), "+f"(d[2]), "+f"(d[3])
        : "r"(a[0]), "r"(a[1]), "r"(a[2]), "r"(a[3]),
          "r"(b[0]), "r"(b[1]));
}

#define LDSM4(r0, r1, r2, r3, addr) \
    asm volatile("ldmatrix.sync.aligned.m8n8.x4.shared.b16 {%0,%1,%2,%3}, [%4];" \
                 : "=r"(r0), "=r"(r1), "=r"(r2), "=r"(r3) : "r"(addr))

__device__ __forceinline__ float gelu_exact(float g)
{
    return 0.5f * g * (1.f + erff(g * 0.7071067811865476f));
}

// ---------------------------------------------------------------------------
// fp16 tensor-core GEMM.  C[M,N] = A[M,K] * B^T, B stored [N,K] (halfs).
// 128x128x32 tiles, 256 threads, 4-stage cp.async pipeline, ldmatrix m16n8k16.
// (Measured-best config: no min-blocks cap — 95 regs, 2 CTAs/SM. DO NOT add a
//  min-blocks launch bound: round 11 showed it spills accumulators.)
// OUTH: C is half. GELU (implies OUTH): adjacent col pairs (g,v) ->
//   gelu(g)*v into half-width C (ldc = N/2). BIAS/ACC: fp32 C paths.
template<bool OUTH, bool ACC, bool BIAS, bool GELU>
__global__ void __launch_bounds__(256)
gemm_f16_kernel(const __half* __restrict__ A, int lda,
                const __half* __restrict__ B, int ldb,
                void* __restrict__ Cv, int ldc,
                const float* __restrict__ bias, int K)
{
    constexpr int BM = 128, BK = 32, STR = 40, S = 4;
    extern __shared__ __half smh[];
    __half* As = smh;                     // [S][128][40]
    __half* Bs = smh + S * BM * STR;      // [S][128][40]

    const int tid  = threadIdx.x;
    const int lane = tid & 31;
    const int warp = tid >> 5;
    const int wm = (warp >> 2) * 64;
    const int wn = (warp & 3) * 32;
    const int lr = lane >> 2;
    const int lc = lane & 3;
    const long bm0 = (long)blockIdx.y * BM;
    const long bn0 = (long)blockIdx.x * 128;

    const int q_row = (lane & 7) + ((lane >> 3) & 1) * 8;
    const int q_col = (lane >> 4) * 8;    // halfs
    const uint32_t as_base = (uint32_t)__cvta_generic_to_shared(As);
    const uint32_t bs_base = (uint32_t)__cvta_generic_to_shared(Bs);

    float acc[4][4][4];
#pragma unroll
    for (int mi = 0; mi < 4; mi++)
#pragma unroll
        for (int ni = 0; ni < 4; ni++)
#pragma unroll
            for (int t = 0; t < 4; t++) acc[mi][ni][t] = 0.f;

    auto prefetch = [&](int s, int k0) {
        __half* as = As + s * BM * STR;
        __half* bs = Bs + s * BM * STR;
#pragma unroll
        for (int j = 0; j < 2; j++) {
            int i = tid + j * 256;
            int row = i >> 2, off = (i & 3) * 8;
            cp16(as + row * STR + off, A + (bm0 + row) * (long)lda + k0 + off);
        }
#pragma unroll
        for (int j = 0; j < 2; j++) {
            int i = tid + j * 256;
            int row = i >> 2, off = (i & 3) * 8;
            cp16(bs + row * STR + off, B + (bn0 + row) * (long)ldb + k0 + off);
        }
    };

    auto compute = [&](int s) {
#pragma unroll
        for (int kk = 0; kk < BK; kk += 16) {
            uint32_t a[4][4], b[4][2];
#pragma unroll
            for (int mi = 0; mi < 4; mi++) {
                uint32_t addr = as_base +
                    ((s * BM + wm + mi * 16 + q_row) * STR + kk + q_col) * 2;
                LDSM4(a[mi][0], a[mi][1], a[mi][2], a[mi][3], addr);
            }
#pragma unroll
            for (int np = 0; np < 2; np++) {
                uint32_t r0, r1, r2, r3;
                uint32_t addr = bs_base +
                    ((s * BM + wn + np * 16 + q_row) * STR + kk + q_col) * 2;
                LDSM4(r0, r1, r2, r3, addr);
                b[2 * np][0] = r0; b[2 * np + 1][0] = r1;
                b[2 * np][1] = r2; b[2 * np + 1][1] = r3;
            }
#pragma unroll
            for (int mi = 0; mi < 4; mi++)
#pragma unroll
                for (int ni = 0; ni < 4; ni++)
                    mma_f16(acc[mi][ni], a[mi], b[ni]);
        }
    };

    const int NIT = K / BK;
#pragma unroll
    for (int s = 0; s < S - 1; s++) {
        if (s < NIT) prefetch(s, s * BK);
        cp_commit();
    }
    for (int it = 0; it < NIT; ++it) {
        cp_wait<S - 2>();
        __syncthreads();
        int nf = it + S - 1;
        if (nf < NIT) prefetch(nf % S, nf * BK);
        cp_commit();
        compute(it % S);
    }

    // Epilogue
#pragma unroll
    for (int mi = 0; mi < 4; mi++) {
        long r0 = bm0 + wm + mi * 16 + lr;
#pragma unroll
        for (int ni = 0; ni < 4; ni++) {
            long c0 = bn0 + wn + ni * 8 + lc * 2;
            if (GELU) {
                __half* C = (__half*)Cv;
                long j = c0 >> 1;
                C[r0 * (long)ldc + j] =
                    __float2half(gelu_exact(acc[mi][ni][0]) * acc[mi][ni][1]);
                C[(r0 + 8) * (long)ldc + j] =
                    __float2half(gelu_exact(acc[mi][ni][2]) * acc[mi][ni][3]);
            } else if (OUTH) {
                __half* C = (__half*)Cv;
                *(__half2*)(C + r0 * (long)ldc + c0) =
                    __floats2half2_rn(acc[mi][ni][0], acc[mi][ni][1]);
                *(__half2*)(C + (r0 + 8) * (long)ldc + c0) =
                    __floats2half2_rn(acc[mi][ni][2], acc[mi][ni][3]);
            } else {
                float* C = (float*)Cv;
                float2* p0 = (float2*)(C + r0 * (long)ldc + c0);
                float2* p1 = (float2*)(C + (r0 + 8) * (long)ldc + c0);
                float b0 = 0.f, b1 = 0.f;
                if (BIAS) { b0 = bias[c0]; b1 = bias[c0 + 1]; }
                if (ACC) {
                    float2 v0 = *p0, v1 = *p1;
                    v0.x += acc[mi][ni][0] + b0; v0.y += acc[mi][ni][1] + b1;
                    v1.x += acc[mi][ni][2] + b0; v1.y += acc[mi][ni][3] + b1;
                    *p0 = v0; *p1 = v1;
                } else {
                    *p0 = make_float2(acc[mi][ni][0] + b0, acc[mi][ni][1] + b1);
                    *p1 = make_float2(acc[mi][ni][2] + b0, acc[mi][ni][3] + b1);
                }
            }
        }
    }
}

// ---------------------------------------------------------------------------
// Persistent fused sLSTM scan kernel — R-resident + Wx-prefetch version.
// 128 CTAs: mt = bid>>6 in [0,2): 128 batch rows; ht = bid&63: 16 h.
// B operand (64 gathered Rt n-rows x 1024 k) resident in smem (loaded once).
// A (y_prev) 3-stage cp.async pipelined per step. The per-step Wx tile
// (128 rows x 64 gathered gate cols, 16 KB) rides in the FIRST cp.async
// group of each step so the gate update reads smem, not scattered gmem.
// State (c,n,m) fp32 in registers; y fp16 double-buffered in scratch.
#define SC_CTAS 128

// Race-free monotonic grid barrier (ticket / epoch; no reset, no phase word).
__device__ __forceinline__ void grid_bar()
{
    __syncthreads();
    __threadfence();
    if (threadIdx.x == 0) {
        unsigned my = atomicAdd(&g_bar_cnt, 1u);
        unsigned target = (my / SC_CTAS + 1u) * SC_CTAS;
        while (*((volatile unsigned*)&g_bar_cnt) < target) { }
    }
    __syncthreads();
    __threadfence();
}

__global__ void __launch_bounds__(256)
scan_kernel(const __half* __restrict__ Wx, const __half* __restrict__ Rt,
            const float* __restrict__ cb,
            __half* __restrict__ yb0, __half* __restrict__ yb1,
            float* __restrict__ yseq)
{
    extern __shared__ __half smh[];
    constexpr int BSTR = 1032;            // resident B row stride (halfs)
    constexpr int ASTR = 72, BK = 64, RSTR = 66, S = 3;
    constexpr int WSTR = 72;              // Wx tile row stride (144 B, 16B-mult)
    __half* Bs  = smh;                    // [64][1032] = 66,048 halfs (132,096 B)
    __half* As  = smh + 64 * BSTR;        // [S][128][72] = 27,648 halfs (55,296 B)
    __half* WxS = As + S * 128 * ASTR;    // [128][72] = 9,216 halfs (18,432 B)
    float*  rawS = (float*)As;            // [128][66] fp32 = 33,792 B (aliases As
                                          //  after final sync; 55,296 B covers it)

    const int tid  = threadIdx.x;
    const int lane = tid & 31;
    const int warp = tid >> 5;
    const int wm = (warp & 3) * 32;       // 4 m-warps x 32 rows
    const int wn = (warp >> 2) * 32;      // 2 n-warps x 32 cols
    const int lr = lane >> 2;
    const int lc = lane & 3;
    const int mt = blockIdx.x >> 6;       // 0..1
    const int ht = blockIdx.x & 63;       // 0..63

    const int q_row = (lane & 7) + ((lane >> 3) & 1) * 8;
    const int q_col = (lane >> 4) * 8;
    const uint32_t as_base = (uint32_t)__cvta_generic_to_shared(As);
    const uint32_t bs_base = (uint32_t)__cvta_generic_to_shared(Bs);

    const int hl = tid & 15;              // h within CTA's 16
    const int rg = tid >> 4;              // 0..15, 8 rows each
    const int h  = ht * 16 + hl;
    const long acol = (long)mt * 128;     // batch-row offset

    float cbv[4];
#pragma unroll
    for (int g = 0; g < 4; g++) cbv[g] = cb[g * 1024 + h];

    float stc[8], stn[8], stm[8];
#pragma unroll
    for (int j = 0; j < 8; j++) { stc[j] = 0.f; stn[j] = 0.f; stm[j] = 0.f; }

    // zero this CTA's slice of yb0 (2048 halfs = 256 threads x 16B)
    {
        uint4 z = make_uint4(0u, 0u, 0u, 0u);
        *(uint4*)(yb0 + (size_t)blockIdx.x * 2048 + tid * 8) = z;
    }

    // one-time resident B load: 64 gathered n-rows x 1024 halfs
    // row nt -> Rt row (nt>>4)*1024 + ht*16 + (nt&15)
#pragma unroll
    for (int j = 0; j < 32; j++) {
        int i = tid + j * 256;            // 0..8191 chunks
        int nt  = i >> 7;                 // 128 chunks per row
        int off = (i & 127) * 8;
        long nglob = (long)(nt >> 4) * 1024 + ht * 16 + (nt & 15);
        cp16(&Bs[nt * BSTR + off], Rt + nglob * 1024 + off);
    }
    cp_commit();
    cp_wait<0>();
    grid_bar();   // covers yb0 zeroing + B residency

    for (int s = 0; s < SS; s++) {
        const __half* ycur = (s & 1) ? yb1 : yb0;
        __half*       ynxt = (s & 1) ? yb0 : yb1;

        float acc[2][4][4];
#pragma unroll
        for (int mi = 0; mi < 2; mi++)
#pragma unroll
            for (int ni = 0; ni < 4; ni++)
#pragma unroll
                for (int t = 0; t < 4; t++) acc[mi][ni][t] = 0.f;

        auto prefetch = [&](int buf, int k0) {
            // A: 128 rows x 64 halfs = 1024 chunks (4/thread)
#pragma unroll
            for (int j = 0; j < 4; j++) {
                int i = tid + j * 256;
                int row = i >> 3, off = (i & 7) * 8;
                cp16(&As[(buf * 128 + row) * ASTR + off],
                     ycur + (acol + row) * 1024 + k0 + off);
            }
        };

        auto compute = [&](int buf, int k0) {
#pragma unroll
            for (int kk = 0; kk < BK; kk += 16) {
                uint32_t a[2][4], b[4][2];
#pragma unroll
                for (int mi = 0; mi < 2; mi++) {
                    uint32_t addr = as_base +
                        ((buf * 128 + wm + mi * 16 + q_row) * ASTR + kk + q_col) * 2;
                    LDSM4(a[mi][0], a[mi][1], a[mi][2], a[mi][3], addr);
                }
#pragma unroll
                for (int np = 0; np < 2; np++) {
                    uint32_t r0, r1, r2, r3;
                    uint32_t addr = bs_base +
                        ((wn + np * 16 + q_row) * BSTR + k0 + kk + q_col) * 2;
                    LDSM4(r0, r1, r2, r3, addr);
                    b[2 * np][0] = r0; b[2 * np + 1][0] = r1;
                    b[2 * np][1] = r2; b[2 * np + 1][1] = r3;
                }
#pragma unroll
                for (int mi = 0; mi < 2; mi++)
#pragma unroll
                    for (int ni = 0; ni < 4; ni++)
                        mma_f16(acc[mi][ni], a[mi], b[ni]);
            }
        };

        constexpr int NIT = 1024 / BK;    // 16
        // group 0: A stage 0 + the step's Wx tile (consumed in the epilogue,
        // complete by it=0's wait — fully hidden behind the GEMM phase)
        prefetch(0, 0);
        {
            // Wx tile: 128 rows x 4 gates x 16 halfs = 1024 16B-chunks
#pragma unroll
            for (int j = 0; j < 4; j++) {
                int i = tid + j * 256;
                int row = i >> 3, g = (i >> 1) & 3, hf = i & 1;
                cp16(&WxS[row * WSTR + g * 16 + hf * 8],
                     Wx + ((acol + row) * SS + s) * (long)4096
                        + g * 1024 + ht * 16 + hf * 8);
            }
        }
        cp_commit();
        prefetch(1, BK);
        cp_commit();
        for (int it = 0; it < NIT; ++it) {
            cp_wait<S - 2>();
            __syncthreads();
            int nf = it + S - 1;
            if (nf < NIT) prefetch(nf % S, nf * BK);
            cp_commit();
            compute(it % S, it * BK);
        }
        __syncthreads();   // all compute done before rawS aliases As

        // stage raw tile to smem (aliases As; GEMM done)
#pragma unroll
        for (int mi = 0; mi < 2; mi++) {
            int r0 = wm + mi * 16 + lr;
#pragma unroll
            for (int ni = 0; ni < 4; ni++) {
                int c0 = wn + ni * 8 + lc * 2;
                *(float2*)&rawS[r0 * RSTR + c0] =
                    make_float2(acc[mi][ni][0], acc[mi][ni][1]);
                *(float2*)&rawS[(r0 + 8) * RSTR + c0] =
                    make_float2(acc[mi][ni][2], acc[mi][ni][3]);
            }
        }
        __syncthreads();

        // fused gate update: 8 (b,h) pairs per thread, state in registers.
        // rawS col layout: gate g at g*16 + hl ; WxS same gathered layout.
#pragma unroll
        for (int j = 0; j < 8; j++) {
            int row = rg * 8 + j;         // 0..127
            long bb = acol + row;
            const __half* ws = WxS + row * WSTR;

            float ir  = rawS[row * RSTR + hl]      + __half2float(ws[hl])      + cbv[0];
            float fr  = rawS[row * RSTR + 16 + hl] + __half2float(ws[16 + hl]) + cbv[1];
            float zr  = rawS[row * RSTR + 32 + hl] + __half2float(ws[32 + hl]) + cbv[2];
            float orr = rawS[row * RSTR + 48 + hl] + __half2float(ws[48 + hl]) + cbv[3];

            float logsig = (fr >= 0.f) ? -log1pf(__expf(-fr))
                                       : (fr - log1pf(__expf(fr)));
            float lfm  = stm[j] + logsig;
            float mnew = (stn[j] == 0.f) ? ir : fmaxf(ir, lfm);
            float ig   = __expf(ir  - mnew);
            float fg   = __expf(lfm - mnew);
            float ez   = __expf(-2.f * fabsf(zr));
            float tz   = copysignf((1.f - ez) / (1.f + ez), zr);
            float cnew = fg * stc[j] + ig * tz;
            float nnew = fg * stn[j] + ig;
            float og   = 1.f / (1.f + __expf(-orr));
            float ynew = og * cnew / nnew;

            stc[j] = cnew;
            stn[j] = nnew;
            stm[j] = mnew;
            ynxt[bb * 1024 + h] = __float2half(ynew);
            yseq[(bb * SS + s) * 1024 + h] = ynew;
        }

        grid_bar();
    }
}

// ---------------------------------------------------------------------------
// fp32 SIMT GEMM (fc only).
template<int BM, int BN, int BK, int TM, int TN>
__global__ void __launch_bounds__(256)
gemm_fc_kernel(const float* __restrict__ A, int lda,
               const float* __restrict__ B, int ldb,
               float* __restrict__ C, int ldc,
               const float* __restrict__ bias, int K)
{
    constexpr int TX = BN / TN;
    constexpr int TY = BM / TM;
    constexpr int NT = TX * TY;

    __shared__ float As[BK][BM + 4];
    __shared__ float Bs[BK][BN + 4];

    const int tid = threadIdx.x;
    const int tx = tid % TX;
    const int ty = tid / TX;
    const long bm0 = (long)blockIdx.y * BM;
    const long bn0 = (long)blockIdx.x * BN;

    float acc[TM][TN];
#pragma unroll
    for (int i = 0; i < TM; i++)
#pragma unroll
        for (int j = 0; j < TN; j++) acc[i][j] = 0.f;

    for (int k0 = 0; k0 < K; k0 += BK) {
#pragma unroll
        for (int i = tid * 4; i < BM * BK; i += NT * 4) {
            int r = i / BK, kk = i % BK;
            float4 v = *(const float4*)(A + (bm0 + r) * (long)lda + (k0 + kk));
            As[kk + 0][r] = v.x; As[kk + 1][r] = v.y;
            As[kk + 2][r] = v.z; As[kk + 3][r] = v.w;
        }
#pragma unroll
        for (int i = tid * 4; i < BN * BK; i += NT * 4) {
            int r = i / BK, kk = i % BK;
            float4 v = *(const float4*)(B + (bn0 + r) * (long)ldb + (k0 + kk));
            Bs[kk + 0][r] = v.x; Bs[kk + 1][r] = v.y;
            Bs[kk + 2][r] = v.z; Bs[kk + 3][r] = v.w;
        }
        __syncthreads();

#pragma unroll
        for (int kk = 0; kk < BK; kk++) {
            float a[TM], b[TN];
#pragma unroll
            for (int i = 0; i < TM; i += 4)
                *(float4*)&a[i] = *(const float4*)&As[kk][ty * TM + i];
#pragma unroll
            for (int j = 0; j < TN; j += 4)
                *(float4*)&b[j] = *(const float4*)&Bs[kk][tx * TN + j];
#pragma unroll
            for (int i = 0; i < TM; i++)
#pragma unroll
                for (int j = 0; j < TN; j++)
                    acc[i][j] = fmaf(a[i], b[j], acc[i][j]);
        }
        __syncthreads();
    }

#pragma unroll
    for (int i = 0; i < TM; i++) {
        long row = bm0 + ty * TM + i;
#pragma unroll
        for (int j = 0; j < TN; j++) {
            long col = bn0 + tx * TN + j;
            C[row * (long)ldc + col] = acc[i][j] + bias[col];
        }
    }
}

// ---------------------------------------------------------------------------
__device__ __forceinline__ void warp_reduce2(float& s, float& ss)
{
#pragma unroll
    for (int o = 16; o > 0; o >>= 1) {
        s  += __shfl_xor_sync(0xFFFFFFFFu, s,  o);
        ss += __shfl_xor_sync(0xFFFFFFFFu, ss, o);
    }
}

// out = LN(x)*w ; OUTH: write halfs, else floats. Warp-per-row (1024 wide).
template<bool OUTH>
__global__ void ln_warp_kernel(const float* __restrict__ x, size_t xs,
                               const float* __restrict__ w,
                               void* __restrict__ outv, size_t os)
{
    int warp = threadIdx.x >> 5, lane = threadIdx.x & 31;
    size_t row = (size_t)blockIdx.x * 8 + warp;
    const float* xr = x + row * xs;
    float4 v[8];
    float s = 0.f, ss = 0.f;
#pragma unroll
    for (int i = 0; i < 8; i++) {
        v[i] = *(const float4*)(xr + i * 128 + lane * 4);
        s  += v[i].x + v[i].y + v[i].z + v[i].w;
        ss += v[i].x * v[i].x + v[i].y * v[i].y + v[i].z * v[i].z + v[i].w * v[i].w;
    }
    warp_reduce2(s, ss);
    float mu  = s * (1.f / 1024.f);
    float var = fmaxf(ss * (1.f / 1024.f) - mu * mu, 0.f);
    float rs  = rsqrtf(var + 1e-5f);
#pragma unroll
    for (int i = 0; i < 8; i++) {
        int c = i * 128 + lane * 4;
        float4 wv = *(const float4*)(w + c);
        float o0 = (v[i].x - mu) * rs * wv.x;
        float o1 = (v[i].y - mu) * rs * wv.y;
        float o2 = (v[i].z - mu) * rs * wv.z;
        float o3 = (v[i].w - mu) * rs * wv.w;
        if (OUTH) {
            __half2* op = (__half2*)((__half*)outv + row * os + c);
            op[0] = __floats2half2_rn(o0, o1);
            op[1] = __floats2half2_rn(o2, o3);
        } else {
            *(float4*)((float*)outv + row * os + c) = make_float4(o0, o1, o2, o3);
        }
    }
}

// Fused: h += LN(yseq)*gn ; fn = LN(h_new)*ln2 (half out). Warp-per-row.
__global__ void lnadd_ln2_kernel(const float* __restrict__ yseq,
                                 const float* __restrict__ gn,
                                 const float* __restrict__ ln2,
                                 float* __restrict__ h,
                                 __half* __restrict__ fn)
{
    int warp = threadIdx.x >> 5, lane = threadIdx.x & 31;
    size_t row = (size_t)blockIdx.x * 8 + warp;
    const float* yr = yseq + row * HH;
    float* hr = h + row * HH;
    float4 v[8], hv[8];
    float s = 0.f, ss = 0.f;
#pragma unroll
    for (int i = 0; i < 8; i++) {
        v[i] = *(const float4*)(yr + i * 128 + lane * 4);
        s  += v[i].x + v[i].y + v[i].z + v[i].w;
        ss += v[i].x * v[i].x + v[i].y * v[i].y + v[i].z * v[i].z + v[i].w * v[i].w;
    }
    warp_reduce2(s, ss);
    float mu  = s * (1.f / 1024.f);
    float var = fmaxf(ss * (1.f / 1024.f) - mu * mu, 0.f);
    float rs  = rsqrtf(var + 1e-5f);
    float s2 = 0.f, ss2 = 0.f;
#pragma unroll
    for (int i = 0; i < 8; i++) {
        int c = i * 128 + lane * 4;
        float4 gv = *(const float4*)(gn + c);
        hv[i] = *(float4*)(hr + c);
        hv[i].x += (v[i].x - mu) * rs * gv.x;
        hv[i].y += (v[i].y - mu) * rs * gv.y;
        hv[i].z += (v[i].z - mu) * rs * gv.z;
        hv[i].w += (v[i].w - mu) * rs * gv.w;
        *(float4*)(hr + c) = hv[i];
        s2  += hv[i].x + hv[i].y + hv[i].z + hv[i].w;
        ss2 += hv[i].x * hv[i].x + hv[i].y * hv[i].y
             + hv[i].z * hv[i].z + hv[i].w * hv[i].w;
    }
    warp_reduce2(s2, ss2);
    float mu2  = s2 * (1.f / 1024.f);
    float var2 = fmaxf(ss2 * (1.f / 1024.f) - mu2 * mu2, 0.f);
    float rs2  = rsqrtf(var2 + 1e-5f);
#pragma unroll
    for (int i = 0; i < 8; i++) {
        int c = i * 128 + lane * 4;
        float4 wv = *(const float4*)(ln2 + c);
        __half2* op = (__half2*)(fn + row * HH + c);
        op[0] = __floats2half2_rn((hv[i].x - mu2) * rs2 * wv.x,
                                  (hv[i].y - mu2) * rs2 * wv.y);
        op[1] = __floats2half2_rn((hv[i].z - mu2) * rs2 * wv.z,
                                  (hv[i].w - mu2) * rs2 * wv.w);
    }
}

// ---------------------------------------------------------------------------
// Depthwise causal conv (K=4) + SiLU; fp16 in/out, fp32 math.
__global__ void conv_silu_kernel(const __half* __restrict__ xn,
                                 const float* __restrict__ cw,
                                 const float* __restrict__ cb,
                                 __half* __restrict__ xc)
{
    size_t q = (size_t)blockIdx.x * blockDim.x + threadIdx.x; // < NTOK*H/4
    int hq = (int)(q & 255);
    size_t t = q >> 8;
    int s = (int)(t % SS);
    int h = hq * 4;
    size_t base = t * HH + h;

    float4 w0 = *(const float4*)(cw + (size_t)h * 4);
    float4 w1 = *(const float4*)(cw + (size_t)(h + 1) * 4);
    float4 w2 = *(const float4*)(cw + (size_t)(h + 2) * 4);
    float4 w3 = *(const float4*)(cw + (size_t)(h + 3) * 4);
    float4 bv = *(const float4*)(cb + h);
    float a0 = bv.x, a1 = bv.y, a2 = bv.z, a3 = bv.w;

#pragma unroll
    for (int k = 0; k < 4; k++) {
        int sp = s - 3 + k;
        if (sp >= 0) {
            const __half2* xp = (const __half2*)(xn + base + (long)(k - 3) * HH);
            float2 x01 = __half22float2(xp[0]);
            float2 x23 = __half22float2(xp[1]);
            a0 = fmaf(x01.x, ((const float*)&w0)[k], a0);
            a1 = fmaf(x01.y, ((const float*)&w1)[k], a1);
            a2 = fmaf(x23.x, ((const float*)&w2)[k], a2);
            a3 = fmaf(x23.y, ((const float*)&w3)[k], a3);
        }
    }
    __half2* op = (__half2*)(xc + base);
    op[0] = __floats2half2_rn(a0 / (1.f + __expf(-a0)), a1 / (1.f + __expf(-a1)));
    op[1] = __floats2half2_rn(a2 / (1.f + __expf(-a2)), a3 / (1.f + __expf(-a3)));
}

// ---------------------------------------------------------------------------
// One-shot prep: convert all weights to fp16 (stack i/f and z/o, transpose R
// to [n][k], interleave ff_up g/v rows, copy emb_w) and convert x to fp16.
__global__ void prep_kernel(const float* __restrict__ Wi,
                            const float* __restrict__ Wf,
                            const float* __restrict__ Wz,
                            const float* __restrict__ Wo,
                            const float* __restrict__ R,
                            const float* __restrict__ up,
                            const float* __restrict__ dn,
                            const float* __restrict__ embw,
                            const float* __restrict__ x,
                            __half* __restrict__ wdst,
                            __half* __restrict__ xdst)
{
    size_t i = (size_t)blockIdx.x * 256 + threadIdx.x;
    if (i >= PREP_N) return;
    const size_t HHHH = (size_t)HH * HH;
    if (i >= W_TOT) {                      // x conversion
        size_t j = i - W_TOT;
        xdst[j] = __float2half(x[j]);
        return;
    }
    float v;
    if (i < W_IFS) {
        size_t l = i / (2 * HHHH), r = i % (2 * HHHH);
        v = (r < HHHH ? Wi : Wf)[l * HHHH + (r % HHHH)];
    } else if (i < 2 * W_IFS) {
        size_t j = i - W_IFS;
        size_t l = j / (2 * HHHH), r = j % (2 * HHHH);
        v = (r < HHHH ? Wz : Wo)[l * HHHH + (r % HHHH)];
    } else if (i < 2 * W_IFS + W_RT) {
        size_t j = i - 2 * W_IFS;
        size_t l = j / ((size_t)H4 * HH);
        size_t rem = j % ((size_t)H4 * HH);
        size_t n = rem / HH, k = rem % HH;       // dst [n][k]
        v = R[l * (size_t)HH * H4 + k * H4 + n]; // src [k][n]
    } else if (i < 2 * W_IFS + W_RT + W_UP) {
        size_t j = i - 2 * W_IFS - W_RT;
        size_t l = j / ((size_t)U2 * HH);
        size_t rem = j % ((size_t)U2 * HH);
        size_t row = rem / HH, col = rem % HH;
        size_t u = row >> 1, half = row & 1;     // even rows = g, odd = v
        v = up[l * (size_t)U2 * HH + (half * UU + u) * HH + col];
    } else if (i < 2 * W_IFS + W_RT + W_UP + W_DN) {
        v = dn[i - 2 * W_IFS - W_RT - W_UP];
    } else {
        v = embw[i - 2 * W_IFS - W_RT - W_UP - W_DN];
    }
    wdst[i] = __float2half(v);
}

// ---------------------------------------------------------------------------
extern "C" void kernel_launch(void* const* d_in, const int* in_sizes, int n_in,
                              void* d_out, int out_size)
{
    (void)in_sizes; (void)n_in; (void)out_size;

    const float* x      = (const float*)d_in[0];
    const float* emb_w  = (const float*)d_in[1];
    const float* emb_b  = (const float*)d_in[2];
    const float* conv_w = (const float*)d_in[3];
    const float* conv_b = (const float*)d_in[4];
    const float* Wi     = (const float*)d_in[5];
    const float* Wf     = (const float*)d_in[6];
    const float* Wz     = (const float*)d_in[7];
    const float* Wo     = (const float*)d_in[8];
    const float* R      = (const float*)d_in[9];
    const float* cell_b = (const float*)d_in[10];
    const float* gn_w   = (const float*)d_in[11];
    const float* ln1_w  = (const float*)d_in[12];
    const float* ln2_w  = (const float*)d_in[13];
    const float* ff_up  = (const float*)d_in[14];
    const float* ff_dn  = (const float*)d_in[15];
    const float* post_w = (const float*)d_in[16];
    const float* fc_w   = (const float*)d_in[17];
    const float* fc_b   = (const float*)d_in[18];
    float* out = (float*)d_out;

    float* S_;
    cudaGetSymbolAddress((void**)&S_, g_scratch);
    float* g_h    = S_;
    float* g_yseq = g_h    + (size_t)NTOK * HH;
    float* g_last = g_yseq + (size_t)NTOK * HH;
    __half* H_    = (__half*)(g_last + (size_t)BB * HH);

    __half* x_h  = H_;
    __half* xn_h = x_h  + (size_t)NTOK * II;
    __half* xc_h = xn_h + (size_t)NTOK * HH;
    __half* Wx_h = xc_h + (size_t)NTOK * HH;    // act_h aliases
    __half* yb0  = Wx_h + (size_t)NTOK * H4;
    __half* yb1  = yb0  + (size_t)BB * HH;
    __half* w_h  = yb1  + (size_t)BB * HH;

    __half* w_if  = w_h;
    __half* w_zo  = w_if + W_IFS;
    __half* w_rt  = w_zo + W_IFS;
    __half* w_up  = w_rt + W_RT;
    __half* w_dn  = w_up + W_UP;
    __half* w_emb = w_dn + W_DN;
    __half* act_h = Wx_h;   // alias

    // scan smem: resident B 132,096 + A stages 55,296 + Wx tile 18,432
    //          = 205,824 B (rawS 33,792 B aliases the A stages).
    const int SCAN_SMEM = 64 * 1032 * 2 + 3 * 128 * 72 * 2 + 128 * 72 * 2;
    const int GEMM_SMEM = 2 * 4 * 128 * 40 * 2;             // 81,920 B (4 stages)
    cudaFuncSetAttribute(scan_kernel,
                         cudaFuncAttributeMaxDynamicSharedMemorySize, SCAN_SMEM);
    cudaFuncSetAttribute(gemm_f16_kernel<true,false,false,false>,
                         cudaFuncAttributeMaxDynamicSharedMemorySize, GEMM_SMEM);
    cudaFuncSetAttribute(gemm_f16_kernel<true,false,false,true>,
                         cudaFuncAttributeMaxDynamicSharedMemorySize, GEMM_SMEM);
    cudaFuncSetAttribute(gemm_f16_kernel<false,false,true,false>,
                         cudaFuncAttributeMaxDynamicSharedMemorySize, GEMM_SMEM);
    cudaFuncSetAttribute(gemm_f16_kernel<false,true,false,false>,
                         cudaFuncAttributeMaxDynamicSharedMemorySize, GEMM_SMEM);

    // 0: one-shot conversions
    prep_kernel<<<(unsigned)((PREP_N + 255) / 256), 256>>>(
        Wi, Wf, Wz, Wo, R, ff_up, ff_dn, emb_w, x, w_h, x_h);

    // 1: h = x_h @ emb_w^T + emb_b (fp32 out)
    gemm_f16_kernel<false,false,true,false>
        <<<dim3(HH/128, NTOK/128), 256, GEMM_SMEM>>>(x_h, II, w_emb, II,
                                                     g_h, HH, emb_b, II);

    for (int l = 0; l < LL; l++) {
        // xn = LN(h)*ln1_w  (half out)
        ln_warp_kernel<true><<<NTOK/8, 256>>>(g_h, HH, ln1_w + (size_t)l*HH,
                                              xn_h, HH);
        // Wx cols [2048,4096) = [z|o] = xn @ [Wz;Wo]^T
        gemm_f16_kernel<true,false,false,false>
            <<<dim3(16, 200), 256, GEMM_SMEM>>>(xn_h, HH,
                                                w_zo + (size_t)l*2*HH*HH, HH,
                                                Wx_h + 2048, H4, nullptr, HH);
        // xc = silu(causal_conv(xn))
        conv_silu_kernel<<<(NTOK*HH/4)/256, 256>>>(xn_h,
            conv_w + (size_t)l*HH*KK, conv_b + (size_t)l*HH, xc_h);
        // Wx cols [0,2048) = [i|f] = xc @ [Wi;Wf]^T
        gemm_f16_kernel<true,false,false,false>
            <<<dim3(16, 200), 256, GEMM_SMEM>>>(xc_h, HH,
                                                w_if + (size_t)l*2*HH*HH, HH,
                                                Wx_h, H4, nullptr, HH);

        // persistent fused scan: all 100 steps in one launch
        scan_kernel<<<SC_CTAS, 256, SCAN_SMEM>>>(
            Wx_h, w_rt + (size_t)l*H4*HH, cell_b + (size_t)l*H4,
            yb0, yb1, g_yseq);

        // fused: h += LN(yseq)*gn ; fn = LN(h)*ln2 (half out, into xn_h)
        lnadd_ln2_kernel<<<NTOK/8, 256>>>(g_yseq, gn_w + (size_t)l*HH,
                                          ln2_w + (size_t)l*HH, g_h, xn_h);

        // FFN: act = gelu(g)*v fused in up-GEMM epilogue ; h += act @ ff_dn^T
        gemm_f16_kernel<true,false,false,true>
            <<<dim3(U2/128, 200), 256, GEMM_SMEM>>>(xn_h, HH,
                                                    w_up + (size_t)l*U2*HH, HH,
                                                    act_h, UU, nullptr, HH);
        gemm_f16_kernel<false,true,false,false>
            <<<dim3(8, 200), 256, GEMM_SMEM>>>(act_h, UU,
                                               w_dn + (size_t)l*HH*UU, UU,
                                               g_h, HH, nullptr, UU);
    }

    // post-LN only needed for last timestep (fp32 out)
    ln_warp_kernel<false><<<BB/8, 256>>>(g_h + (size_t)(SS-1)*HH, (size_t)SS*HH,
                                         post_w, g_last, HH);
    // out = last @ fc_w^T + fc_b
    gemm_fc_kernel<64,128,16,4,8>
        <<<dim3(OO/128, BB/64), 256>>>(g_last, HH, fc_w, HH,
                                       out, OO, fc_b, HH);
}

// round 16
// speedup vs baseline: 1.4723x; 1.0890x over previous
#include <cuda_runtime.h>
#include <cuda_fp16.h>
#include <cstddef>
#include <cstdint>

// Problem constants
#define BB   256
#define SS   100
#define II   128
#define HH   1024
#define OO   128
#define LL   2
#define UU   1344
#define KK   4
#define NTOK (BB * SS)          // 25600
#define H4   (4 * HH)           // 4096
#define U2   (2 * UU)           // 2688

// ---------------------------------------------------------------------------
// Scratch layout (identical to rounds 10-15).
#define W_IFS  ((size_t)LL * 2 * HH * HH)   // 4,194,304
#define W_RT   ((size_t)LL * H4 * HH)       // 8,388,608 (transposed [l][n][k])
#define W_UP   ((size_t)LL * U2 * HH)       // 5,505,024 (g/v row-interleaved)
#define W_DN   ((size_t)LL * HH * UU)       // 2,752,512
#define W_EMB  ((size_t)HH * II)            // 131,072
#define W_TOT  (2 * W_IFS + W_RT + W_UP + W_DN + W_EMB)
#define PREP_N (W_TOT + (size_t)NTOK * II)  // + x conversion
#define SCRATCH_FLOATS 146000000ULL
__device__ float g_scratch[SCRATCH_FLOATS];

// monotonic grid-barrier counter (never reset; race-free).
__device__ unsigned g_bar_cnt = 0;

// ---------------------------------------------------------------------------
__device__ __forceinline__ void cp16(void* s, const void* g)
{
    uint32_t sa = (uint32_t)__cvta_generic_to_shared(s);
    asm volatile("cp.async.cg.shared.global [%0], [%1], 16;\n" :: "r"(sa), "l"(g));
}
__device__ __forceinline__ void cp_commit()
{
    asm volatile("cp.async.commit_group;\n" ::);
}
template<int N>
__device__ __forceinline__ void cp_wait()
{
    asm volatile("cp.async.wait_group %0;\n" :: "n"(N));
}

__device__ __forceinline__ void mma_f16(float* d, const uint32_t* a, const uint32_t* b)
{
    asm volatile(
        "mma.sync.aligned.m16n8k16.row.col.f32.f16.f16.f32 "
        "{%0,%1,%2,%3},{%4,%5,%6,%7},{%8,%9},{%0,%1,%2,%3};"
        : "+f"(d[0]), "+f"(d[1]), "+f"(d[2]), "+f"(d[3])
        : "r"(a[0]), "r"(a[1]), "r"(a[2]), "r"(a[3]),
          "r"(b[0]), "r"(b[1]));
}

#define LDSM4(r0, r1, r2, r3, addr) \
    asm volatile("ldmatrix.sync.aligned.m8n8.x4.shared.b16 {%0,%1,%2,%3}, [%4];" \
                 : "=r"(r0), "=r"(r1), "=r"(r2), "=r"(r3) : "r"(addr))

__device__ __forceinline__ float gelu_exact(float g)
{
    return 0.5f * g * (1.f + erff(g * 0.7071067811865476f));
}

// ---------------------------------------------------------------------------
// fp16 tensor-core GEMM.  C[M,N] = A[M,K] * B^T, B stored [N,K] (halfs).
// 128x128x64 tiles, 256 threads, 2-stage cp.async pipeline (16 k-iters for
// K=1024 — half the syncs of the BK=32 version; stage smem 36,864 B, 2 stages
// = 73,728 B keeps 2 CTAs/SM at 95 regs).
// (DO NOT add a min-blocks launch bound: round 11 showed it spills.)
// OUTH: C is half. GELU (implies OUTH): adjacent col pairs (g,v) ->
//   gelu(g)*v into half-width C (ldc = N/2). BIAS/ACC: fp32 C paths.
template<bool OUTH, bool ACC, bool BIAS, bool GELU>
__global__ void __launch_bounds__(256)
gemm_f16_kernel(const __half* __restrict__ A, int lda,
                const __half* __restrict__ B, int ldb,
                void* __restrict__ Cv, int ldc,
                const float* __restrict__ bias, int K)
{
    constexpr int BM = 128, BK = 64, STR = 72, S = 2;
    extern __shared__ __half smh[];
    __half* As = smh;                     // [S][128][72]
    __half* Bs = smh + S * BM * STR;      // [S][128][72]

    const int tid  = threadIdx.x;
    const int lane = tid & 31;
    const int warp = tid >> 5;
    const int wm = (warp >> 2) * 64;
    const int wn = (warp & 3) * 32;
    const int lr = lane >> 2;
    const int lc = lane & 3;
    const long bm0 = (long)blockIdx.y * BM;
    const long bn0 = (long)blockIdx.x * 128;

    const int q_row = (lane & 7) + ((lane >> 3) & 1) * 8;
    const int q_col = (lane >> 4) * 8;    // halfs
    const uint32_t as_base = (uint32_t)__cvta_generic_to_shared(As);
    const uint32_t bs_base = (uint32_t)__cvta_generic_to_shared(Bs);

    float acc[4][4][4];
#pragma unroll
    for (int mi = 0; mi < 4; mi++)
#pragma unroll
        for (int ni = 0; ni < 4; ni++)
#pragma unroll
            for (int t = 0; t < 4; t++) acc[mi][ni][t] = 0.f;

    auto prefetch = [&](int s, int k0) {
        __half* as = As + s * BM * STR;
        __half* bs = Bs + s * BM * STR;
        // 128 rows x 64 halfs = 1024 16B-chunks each for A and B (4/thread)
#pragma unroll
        for (int j = 0; j < 4; j++) {
            int i = tid + j * 256;
            int row = i >> 3, off = (i & 7) * 8;
            cp16(as + row * STR + off, A + (bm0 + row) * (long)lda + k0 + off);
        }
#pragma unroll
        for (int j = 0; j < 4; j++) {
            int i = tid + j * 256;
            int row = i >> 3, off = (i & 7) * 8;
            cp16(bs + row * STR + off, B + (bn0 + row) * (long)ldb + k0 + off);
        }
    };

    auto compute = [&](int s) {
#pragma unroll
        for (int kk = 0; kk < BK; kk += 16) {
            uint32_t a[4][4], b[4][2];
#pragma unroll
            for (int mi = 0; mi < 4; mi++) {
                uint32_t addr = as_base +
                    ((s * BM + wm + mi * 16 + q_row) * STR + kk + q_col) * 2;
                LDSM4(a[mi][0], a[mi][1], a[mi][2], a[mi][3], addr);
            }
#pragma unroll
            for (int np = 0; np < 2; np++) {
                uint32_t r0, r1, r2, r3;
                uint32_t addr = bs_base +
                    ((s * BM + wn + np * 16 + q_row) * STR + kk + q_col) * 2;
                LDSM4(r0, r1, r2, r3, addr);
                b[2 * np][0] = r0; b[2 * np + 1][0] = r1;
                b[2 * np][1] = r2; b[2 * np + 1][1] = r3;
            }
#pragma unroll
            for (int mi = 0; mi < 4; mi++)
#pragma unroll
                for (int ni = 0; ni < 4; ni++)
                    mma_f16(acc[mi][ni], a[mi], b[ni]);
        }
    };

    const int NIT = K / BK;
    prefetch(0, 0);
    cp_commit();
    for (int it = 0; it < NIT; ++it) {
        cp_wait<0>();
        __syncthreads();
        if (it + 1 < NIT) prefetch((it + 1) & 1, (it + 1) * BK);
        cp_commit();
        compute(it & 1);
    }

    // Epilogue
#pragma unroll
    for (int mi = 0; mi < 4; mi++) {
        long r0 = bm0 + wm + mi * 16 + lr;
#pragma unroll
        for (int ni = 0; ni < 4; ni++) {
            long c0 = bn0 + wn + ni * 8 + lc * 2;
            if (GELU) {
                __half* C = (__half*)Cv;
                long j = c0 >> 1;
                C[r0 * (long)ldc + j] =
                    __float2half(gelu_exact(acc[mi][ni][0]) * acc[mi][ni][1]);
                C[(r0 + 8) * (long)ldc + j] =
                    __float2half(gelu_exact(acc[mi][ni][2]) * acc[mi][ni][3]);
            } else if (OUTH) {
                __half* C = (__half*)Cv;
                *(__half2*)(C + r0 * (long)ldc + c0) =
                    __floats2half2_rn(acc[mi][ni][0], acc[mi][ni][1]);
                *(__half2*)(C + (r0 + 8) * (long)ldc + c0) =
                    __floats2half2_rn(acc[mi][ni][2], acc[mi][ni][3]);
            } else {
                float* C = (float*)Cv;
                float2* p0 = (float2*)(C + r0 * (long)ldc + c0);
                float2* p1 = (float2*)(C + (r0 + 8) * (long)ldc + c0);
                float b0 = 0.f, b1 = 0.f;
                if (BIAS) { b0 = bias[c0]; b1 = bias[c0 + 1]; }
                if (ACC) {
                    float2 v0 = *p0, v1 = *p1;
                    v0.x += acc[mi][ni][0] + b0; v0.y += acc[mi][ni][1] + b1;
                    v1.x += acc[mi][ni][2] + b0; v1.y += acc[mi][ni][3] + b1;
                    *p0 = v0; *p1 = v1;
                } else {
                    *p0 = make_float2(acc[mi][ni][0] + b0, acc[mi][ni][1] + b1);
                    *p1 = make_float2(acc[mi][ni][2] + b0, acc[mi][ni][3] + b1);
                }
            }
        }
    }
}

// ---------------------------------------------------------------------------
// Persistent fused sLSTM scan kernel — R-resident + Wx-prefetch (round-15
// measured-best; unchanged).
#define SC_CTAS 128

// Race-free monotonic grid barrier (ticket / epoch; no reset, no phase word).
__device__ __forceinline__ void grid_bar()
{
    __syncthreads();
    __threadfence();
    if (threadIdx.x == 0) {
        unsigned my = atomicAdd(&g_bar_cnt, 1u);
        unsigned target = (my / SC_CTAS + 1u) * SC_CTAS;
        while (*((volatile unsigned*)&g_bar_cnt) < target) { }
    }
    __syncthreads();
    __threadfence();
}

__global__ void __launch_bounds__(256)
scan_kernel(const __half* __restrict__ Wx, const __half* __restrict__ Rt,
            const float* __restrict__ cb,
            __half* __restrict__ yb0, __half* __restrict__ yb1,
            float* __restrict__ yseq)
{
    extern __shared__ __half smh[];
    constexpr int BSTR = 1032;            // resident B row stride (halfs)
    constexpr int ASTR = 72, BK = 64, RSTR = 66, S = 3;
    constexpr int WSTR = 72;              // Wx tile row stride (144 B, 16B-mult)
    __half* Bs  = smh;                    // [64][1032] = 66,048 halfs (132,096 B)
    __half* As  = smh + 64 * BSTR;        // [S][128][72] = 27,648 halfs (55,296 B)
    __half* WxS = As + S * 128 * ASTR;    // [128][72] = 9,216 halfs (18,432 B)
    float*  rawS = (float*)As;            // [128][66] fp32 = 33,792 B (aliases As
                                          //  after final sync; 55,296 B covers it)

    const int tid  = threadIdx.x;
    const int lane = tid & 31;
    const int warp = tid >> 5;
    const int wm = (warp & 3) * 32;       // 4 m-warps x 32 rows
    const int wn = (warp >> 2) * 32;      // 2 n-warps x 32 cols
    const int lr = lane >> 2;
    const int lc = lane & 3;
    const int mt = blockIdx.x >> 6;       // 0..1
    const int ht = blockIdx.x & 63;       // 0..63

    const int q_row = (lane & 7) + ((lane >> 3) & 1) * 8;
    const int q_col = (lane >> 4) * 8;
    const uint32_t as_base = (uint32_t)__cvta_generic_to_shared(As);
    const uint32_t bs_base = (uint32_t)__cvta_generic_to_shared(Bs);

    const int hl = tid & 15;              // h within CTA's 16
    const int rg = tid >> 4;              // 0..15, 8 rows each
    const int h  = ht * 16 + hl;
    const long acol = (long)mt * 128;     // batch-row offset

    float cbv[4];
#pragma unroll
    for (int g = 0; g < 4; g++) cbv[g] = cb[g * 1024 + h];

    float stc[8], stn[8], stm[8];
#pragma unroll
    for (int j = 0; j < 8; j++) { stc[j] = 0.f; stn[j] = 0.f; stm[j] = 0.f; }

    // zero this CTA's slice of yb0 (2048 halfs = 256 threads x 16B)
    {
        uint4 z = make_uint4(0u, 0u, 0u, 0u);
        *(uint4*)(yb0 + (size_t)blockIdx.x * 2048 + tid * 8) = z;
    }

    // one-time resident B load: 64 gathered n-rows x 1024 halfs
    // row nt -> Rt row (nt>>4)*1024 + ht*16 + (nt&15)
#pragma unroll
    for (int j = 0; j < 32; j++) {
        int i = tid + j * 256;            // 0..8191 chunks
        int nt  = i >> 7;                 // 128 chunks per row
        int off = (i & 127) * 8;
        long nglob = (long)(nt >> 4) * 1024 + ht * 16 + (nt & 15);
        cp16(&Bs[nt * BSTR + off], Rt + nglob * 1024 + off);
    }
    cp_commit();
    cp_wait<0>();
    grid_bar();   // covers yb0 zeroing + B residency

    for (int s = 0; s < SS; s++) {
        const __half* ycur = (s & 1) ? yb1 : yb0;
        __half*       ynxt = (s & 1) ? yb0 : yb1;

        float acc[2][4][4];
#pragma unroll
        for (int mi = 0; mi < 2; mi++)
#pragma unroll
            for (int ni = 0; ni < 4; ni++)
#pragma unroll
                for (int t = 0; t < 4; t++) acc[mi][ni][t] = 0.f;

        auto prefetch = [&](int buf, int k0) {
            // A: 128 rows x 64 halfs = 1024 chunks (4/thread)
#pragma unroll
            for (int j = 0; j < 4; j++) {
                int i = tid + j * 256;
                int row = i >> 3, off = (i & 7) * 8;
                cp16(&As[(buf * 128 + row) * ASTR + off],
                     ycur + (acol + row) * 1024 + k0 + off);
            }
        };

        auto compute = [&](int buf, int k0) {
#pragma unroll
            for (int kk = 0; kk < BK; kk += 16) {
                uint32_t a[2][4], b[4][2];
#pragma unroll
                for (int mi = 0; mi < 2; mi++) {
                    uint32_t addr = as_base +
                        ((buf * 128 + wm + mi * 16 + q_row) * ASTR + kk + q_col) * 2;
                    LDSM4(a[mi][0], a[mi][1], a[mi][2], a[mi][3], addr);
                }
#pragma unroll
                for (int np = 0; np < 2; np++) {
                    uint32_t r0, r1, r2, r3;
                    uint32_t addr = bs_base +
                        ((wn + np * 16 + q_row) * BSTR + k0 + kk + q_col) * 2;
                    LDSM4(r0, r1, r2, r3, addr);
                    b[2 * np][0] = r0; b[2 * np + 1][0] = r1;
                    b[2 * np][1] = r2; b[2 * np + 1][1] = r3;
                }
#pragma unroll
                for (int mi = 0; mi < 2; mi++)
#pragma unroll
                    for (int ni = 0; ni < 4; ni++)
                        mma_f16(acc[mi][ni], a[mi], b[ni]);
            }
        };

        constexpr int NIT = 1024 / BK;    // 16
        // group 0: A stage 0 + the step's Wx tile (consumed in the epilogue,
        // complete by it=0's wait — fully hidden behind the GEMM phase)
        prefetch(0, 0);
        {
            // Wx tile: 128 rows x 4 gates x 16 halfs = 1024 16B-chunks
#pragma unroll
            for (int j = 0; j < 4; j++) {
                int i = tid + j * 256;
                int row = i >> 3, g = (i >> 1) & 3, hf = i & 1;
                cp16(&WxS[row * WSTR + g * 16 + hf * 8],
                     Wx + ((acol + row) * SS + s) * (long)4096
                        + g * 1024 + ht * 16 + hf * 8);
            }
        }
        cp_commit();
        prefetch(1, BK);
        cp_commit();
        for (int it = 0; it < NIT; ++it) {
            cp_wait<S - 2>();
            __syncthreads();
            int nf = it + S - 1;
            if (nf < NIT) prefetch(nf % S, nf * BK);
            cp_commit();
            compute(it % S, it * BK);
        }
        __syncthreads();   // all compute done before rawS aliases As

        // stage raw tile to smem (aliases As; GEMM done)
#pragma unroll
        for (int mi = 0; mi < 2; mi++) {
            int r0 = wm + mi * 16 + lr;
#pragma unroll
            for (int ni = 0; ni < 4; ni++) {
                int c0 = wn + ni * 8 + lc * 2;
                *(float2*)&rawS[r0 * RSTR + c0] =
                    make_float2(acc[mi][ni][0], acc[mi][ni][1]);
                *(float2*)&rawS[(r0 + 8) * RSTR + c0] =
                    make_float2(acc[mi][ni][2], acc[mi][ni][3]);
            }
        }
        __syncthreads();

        // fused gate update: 8 (b,h) pairs per thread, state in registers.
        // rawS col layout: gate g at g*16 + hl ; WxS same gathered layout.
#pragma unroll
        for (int j = 0; j < 8; j++) {
            int row = rg * 8 + j;         // 0..127
            long bb = acol + row;
            const __half* ws = WxS + row * WSTR;

            float ir  = rawS[row * RSTR + hl]      + __half2float(ws[hl])      + cbv[0];
            float fr  = rawS[row * RSTR + 16 + hl] + __half2float(ws[16 + hl]) + cbv[1];
            float zr  = rawS[row * RSTR + 32 + hl] + __half2float(ws[32 + hl]) + cbv[2];
            float orr = rawS[row * RSTR + 48 + hl] + __half2float(ws[48 + hl]) + cbv[3];

            float logsig = (fr >= 0.f) ? -log1pf(__expf(-fr))
                                       : (fr - log1pf(__expf(fr)));
            float lfm  = stm[j] + logsig;
            float mnew = (stn[j] == 0.f) ? ir : fmaxf(ir, lfm);
            float ig   = __expf(ir  - mnew);
            float fg   = __expf(lfm - mnew);
            float ez   = __expf(-2.f * fabsf(zr));
            float tz   = copysignf((1.f - ez) / (1.f + ez), zr);
            float cnew = fg * stc[j] + ig * tz;
            float nnew = fg * stn[j] + ig;
            float og   = 1.f / (1.f + __expf(-orr));
            float ynew = og * cnew / nnew;

            stc[j] = cnew;
            stn[j] = nnew;
            stm[j] = mnew;
            ynxt[bb * 1024 + h] = __float2half(ynew);
            yseq[(bb * SS + s) * 1024 + h] = ynew;
        }

        grid_bar();
    }
}

// ---------------------------------------------------------------------------
// fp32 SIMT GEMM (fc only).
template<int BM, int BN, int BK, int TM, int TN>
__global__ void __launch_bounds__(256)
gemm_fc_kernel(const float* __restrict__ A, int lda,
               const float* __restrict__ B, int ldb,
               float* __restrict__ C, int ldc,
               const float* __restrict__ bias, int K)
{
    constexpr int TX = BN / TN;
    constexpr int TY = BM / TM;
    constexpr int NT = TX * TY;

    __shared__ float As[BK][BM + 4];
    __shared__ float Bs[BK][BN + 4];

    const int tid = threadIdx.x;
    const int tx = tid % TX;
    const int ty = tid / TX;
    const long bm0 = (long)blockIdx.y * BM;
    const long bn0 = (long)blockIdx.x * BN;

    float acc[TM][TN];
#pragma unroll
    for (int i = 0; i < TM; i++)
#pragma unroll
        for (int j = 0; j < TN; j++) acc[i][j] = 0.f;

    for (int k0 = 0; k0 < K; k0 += BK) {
#pragma unroll
        for (int i = tid * 4; i < BM * BK; i += NT * 4) {
            int r = i / BK, kk = i % BK;
            float4 v = *(const float4*)(A + (bm0 + r) * (long)lda + (k0 + kk));
            As[kk + 0][r] = v.x; As[kk + 1][r] = v.y;
            As[kk + 2][r] = v.z; As[kk + 3][r] = v.w;
        }
#pragma unroll
        for (int i = tid * 4; i < BN * BK; i += NT * 4) {
            int r = i / BK, kk = i % BK;
            float4 v = *(const float4*)(B + (bn0 + r) * (long)ldb + (k0 + kk));
            Bs[kk + 0][r] = v.x; Bs[kk + 1][r] = v.y;
            Bs[kk + 2][r] = v.z; Bs[kk + 3][r] = v.w;
        }
        __syncthreads();

#pragma unroll
        for (int kk = 0; kk < BK; kk++) {
            float a[TM], b[TN];
#pragma unroll
            for (int i = 0; i < TM; i += 4)
                *(float4*)&a[i] = *(const float4*)&As[kk][ty * TM + i];
#pragma unroll
            for (int j = 0; j < TN; j += 4)
                *(float4*)&b[j] = *(const float4*)&Bs[kk][tx * TN + j];
#pragma unroll
            for (int i = 0; i < TM; i++)
#pragma unroll
                for (int j = 0; j < TN; j++)
                    acc[i][j] = fmaf(a[i], b[j], acc[i][j]);
        }
        __syncthreads();
    }

#pragma unroll
    for (int i = 0; i < TM; i++) {
        long row = bm0 + ty * TM + i;
#pragma unroll
        for (int j = 0; j < TN; j++) {
            long col = bn0 + tx * TN + j;
            C[row * (long)ldc + col] = acc[i][j] + bias[col];
        }
    }
}

// ---------------------------------------------------------------------------
__device__ __forceinline__ void warp_reduce2(float& s, float& ss)
{
#pragma unroll
    for (int o = 16; o > 0; o >>= 1) {
        s  += __shfl_xor_sync(0xFFFFFFFFu, s,  o);
        ss += __shfl_xor_sync(0xFFFFFFFFu, ss, o);
    }
}

// out = LN(x)*w ; OUTH: write halfs, else floats. Warp-per-row (1024 wide).
template<bool OUTH>
__global__ void ln_warp_kernel(const float* __restrict__ x, size_t xs,
                               const float* __restrict__ w,
                               void* __restrict__ outv, size_t os)
{
    int warp = threadIdx.x >> 5, lane = threadIdx.x & 31;
    size_t row = (size_t)blockIdx.x * 8 + warp;
    const float* xr = x + row * xs;
    float4 v[8];
    float s = 0.f, ss = 0.f;
#pragma unroll
    for (int i = 0; i < 8; i++) {
        v[i] = *(const float4*)(xr + i * 128 + lane * 4);
        s  += v[i].x + v[i].y + v[i].z + v[i].w;
        ss += v[i].x * v[i].x + v[i].y * v[i].y + v[i].z * v[i].z + v[i].w * v[i].w;
    }
    warp_reduce2(s, ss);
    float mu  = s * (1.f / 1024.f);
    float var = fmaxf(ss * (1.f / 1024.f) - mu * mu, 0.f);
    float rs  = rsqrtf(var + 1e-5f);
#pragma unroll
    for (int i = 0; i < 8; i++) {
        int c = i * 128 + lane * 4;
        float4 wv = *(const float4*)(w + c);
        float o0 = (v[i].x - mu) * rs * wv.x;
        float o1 = (v[i].y - mu) * rs * wv.y;
        float o2 = (v[i].z - mu) * rs * wv.z;
        float o3 = (v[i].w - mu) * rs * wv.w;
        if (OUTH) {
            __half2* op = (__half2*)((__half*)outv + row * os + c);
            op[0] = __floats2half2_rn(o0, o1);
            op[1] = __floats2half2_rn(o2, o3);
        } else {
            *(float4*)((float*)outv + row * os + c) = make_float4(o0, o1, o2, o3);
        }
    }
}

// Fused: h += LN(yseq)*gn ; fn = LN(h_new)*ln2 (half out). Warp-per-row.
__global__ void lnadd_ln2_kernel(const float* __restrict__ yseq,
                                 const float* __restrict__ gn,
                                 const float* __restrict__ ln2,
                                 float* __restrict__ h,
                                 __half* __restrict__ fn)
{
    int warp = threadIdx.x >> 5, lane = threadIdx.x & 31;
    size_t row = (size_t)blockIdx.x * 8 + warp;
    const float* yr = yseq + row * HH;
    float* hr = h + row * HH;
    float4 v[8], hv[8];
    float s = 0.f, ss = 0.f;
#pragma unroll
    for (int i = 0; i < 8; i++) {
        v[i] = *(const float4*)(yr + i * 128 + lane * 4);
        s  += v[i].x + v[i].y + v[i].z + v[i].w;
        ss += v[i].x * v[i].x + v[i].y * v[i].y + v[i].z * v[i].z + v[i].w * v[i].w;
    }
    warp_reduce2(s, ss);
    float mu  = s * (1.f / 1024.f);
    float var = fmaxf(ss * (1.f / 1024.f) - mu * mu, 0.f);
    float rs  = rsqrtf(var + 1e-5f);
    float s2 = 0.f, ss2 = 0.f;
#pragma unroll
    for (int i = 0; i < 8; i++) {
        int c = i * 128 + lane * 4;
        float4 gv = *(const float4*)(gn + c);
        hv[i] = *(float4*)(hr + c);
        hv[i].x += (v[i].x - mu) * rs * gv.x;
        hv[i].y += (v[i].y - mu) * rs * gv.y;
        hv[i].z += (v[i].z - mu) * rs * gv.z;
        hv[i].w += (v[i].w - mu) * rs * gv.w;
        *(float4*)(hr + c) = hv[i];
        s2  += hv[i].x + hv[i].y + hv[i].z + hv[i].w;
        ss2 += hv[i].x * hv[i].x + hv[i].y * hv[i].y
             + hv[i].z * hv[i].z + hv[i].w * hv[i].w;
    }
    warp_reduce2(s2, ss2);
    float mu2  = s2 * (1.f / 1024.f);
    float var2 = fmaxf(ss2 * (1.f / 1024.f) - mu2 * mu2, 0.f);
    float rs2  = rsqrtf(var2 + 1e-5f);
#pragma unroll
    for (int i = 0; i < 8; i++) {
        int c = i * 128 + lane * 4;
        float4 wv = *(const float4*)(ln2 + c);
        __half2* op = (__half2*)(fn + row * HH + c);
        op[0] = __floats2half2_rn((hv[i].x - mu2) * rs2 * wv.x,
                                  (hv[i].y - mu2) * rs2 * wv.y);
        op[1] = __floats2half2_rn((hv[i].z - mu2) * rs2 * wv.z,
                                  (hv[i].w - mu2) * rs2 * wv.w);
    }
}

// ---------------------------------------------------------------------------
// Depthwise causal conv (K=4) + SiLU; fp16 in/out, fp32 math.
__global__ void conv_silu_kernel(const __half* __restrict__ xn,
                                 const float* __restrict__ cw,
                                 const float* __restrict__ cb,
                                 __half* __restrict__ xc)
{
    size_t q = (size_t)blockIdx.x * blockDim.x + threadIdx.x; // < NTOK*H/4
    int hq = (int)(q & 255);
    size_t t = q >> 8;
    int s = (int)(t % SS);
    int h = hq * 4;
    size_t base = t * HH + h;

    float4 w0 = *(const float4*)(cw + (size_t)h * 4);
    float4 w1 = *(const float4*)(cw + (size_t)(h + 1) * 4);
    float4 w2 = *(const float4*)(cw + (size_t)(h + 2) * 4);
    float4 w3 = *(const float4*)(cw + (size_t)(h + 3) * 4);
    float4 bv = *(const float4*)(cb + h);
    float a0 = bv.x, a1 = bv.y, a2 = bv.z, a3 = bv.w;

#pragma unroll
    for (int k = 0; k < 4; k++) {
        int sp = s - 3 + k;
        if (sp >= 0) {
            const __half2* xp = (const __half2*)(xn + base + (long)(k - 3) * HH);
            float2 x01 = __half22float2(xp[0]);
            float2 x23 = __half22float2(xp[1]);
            a0 = fmaf(x01.x, ((const float*)&w0)[k], a0);
            a1 = fmaf(x01.y, ((const float*)&w1)[k], a1);
            a2 = fmaf(x23.x, ((const float*)&w2)[k], a2);
            a3 = fmaf(x23.y, ((const float*)&w3)[k], a3);
        }
    }
    __half2* op = (__half2*)(xc + base);
    op[0] = __floats2half2_rn(a0 / (1.f + __expf(-a0)), a1 / (1.f + __expf(-a1)));
    op[1] = __floats2half2_rn(a2 / (1.f + __expf(-a2)), a3 / (1.f + __expf(-a3)));
}

// ---------------------------------------------------------------------------
// One-shot prep: convert all weights to fp16 (stack i/f and z/o, transpose R
// to [n][k], interleave ff_up g/v rows, copy emb_w) and convert x to fp16.
__global__ void prep_kernel(const float* __restrict__ Wi,
                            const float* __restrict__ Wf,
                            const float* __restrict__ Wz,
                            const float* __restrict__ Wo,
                            const float* __restrict__ R,
                            const float* __restrict__ up,
                            const float* __restrict__ dn,
                            const float* __restrict__ embw,
                            const float* __restrict__ x,
                            __half* __restrict__ wdst,
                            __half* __restrict__ xdst)
{
    size_t i = (size_t)blockIdx.x * 256 + threadIdx.x;
    if (i >= PREP_N) return;
    const size_t HHHH = (size_t)HH * HH;
    if (i >= W_TOT) {                      // x conversion
        size_t j = i - W_TOT;
        xdst[j] = __float2half(x[j]);
        return;
    }
    float v;
    if (i < W_IFS) {
        size_t l = i / (2 * HHHH), r = i % (2 * HHHH);
        v = (r < HHHH ? Wi : Wf)[l * HHHH + (r % HHHH)];
    } else if (i < 2 * W_IFS) {
        size_t j = i - W_IFS;
        size_t l = j / (2 * HHHH), r = j % (2 * HHHH);
        v = (r < HHHH ? Wz : Wo)[l * HHHH + (r % HHHH)];
    } else if (i < 2 * W_IFS + W_RT) {
        size_t j = i - 2 * W_IFS;
        size_t l = j / ((size_t)H4 * HH);
        size_t rem = j % ((size_t)H4 * HH);
        size_t n = rem / HH, k = rem % HH;       // dst [n][k]
        v = R[l * (size_t)HH * H4 + k * H4 + n]; // src [k][n]
    } else if (i < 2 * W_IFS + W_RT + W_UP) {
        size_t j = i - 2 * W_IFS - W_RT;
        size_t l = j / ((size_t)U2 * HH);
        size_t rem = j % ((size_t)U2 * HH);
        size_t row = rem / HH, col = rem % HH;
        size_t u = row >> 1, half = row & 1;     // even rows = g, odd = v
        v = up[l * (size_t)U2 * HH + (half * UU + u) * HH + col];
    } else if (i < 2 * W_IFS + W_RT + W_UP + W_DN) {
        v = dn[i - 2 * W_IFS - W_RT - W_UP];
    } else {
        v = embw[i - 2 * W_IFS - W_RT - W_UP - W_DN];
    }
    wdst[i] = __float2half(v);
}

// ---------------------------------------------------------------------------
extern "C" void kernel_launch(void* const* d_in, const int* in_sizes, int n_in,
                              void* d_out, int out_size)
{
    (void)in_sizes; (void)n_in; (void)out_size;

    const float* x      = (const float*)d_in[0];
    const float* emb_w  = (const float*)d_in[1];
    const float* emb_b  = (const float*)d_in[2];
    const float* conv_w = (const float*)d_in[3];
    const float* conv_b = (const float*)d_in[4];
    const float* Wi     = (const float*)d_in[5];
    const float* Wf     = (const float*)d_in[6];
    const float* Wz     = (const float*)d_in[7];
    const float* Wo     = (const float*)d_in[8];
    const float* R      = (const float*)d_in[9];
    const float* cell_b = (const float*)d_in[10];
    const float* gn_w   = (const float*)d_in[11];
    const float* ln1_w  = (const float*)d_in[12];
    const float* ln2_w  = (const float*)d_in[13];
    const float* ff_up  = (const float*)d_in[14];
    const float* ff_dn  = (const float*)d_in[15];
    const float* post_w = (const float*)d_in[16];
    const float* fc_w   = (const float*)d_in[17];
    const float* fc_b   = (const float*)d_in[18];
    float* out = (float*)d_out;

    float* S_;
    cudaGetSymbolAddress((void**)&S_, g_scratch);
    float* g_h    = S_;
    float* g_yseq = g_h    + (size_t)NTOK * HH;
    float* g_last = g_yseq + (size_t)NTOK * HH;
    __half* H_    = (__half*)(g_last + (size_t)BB * HH);

    __half* x_h  = H_;
    __half* xn_h = x_h  + (size_t)NTOK * II;
    __half* xc_h = xn_h + (size_t)NTOK * HH;
    __half* Wx_h = xc_h + (size_t)NTOK * HH;    // act_h aliases
    __half* yb0  = Wx_h + (size_t)NTOK * H4;
    __half* yb1  = yb0  + (size_t)BB * HH;
    __half* w_h  = yb1  + (size_t)BB * HH;

    __half* w_if  = w_h;
    __half* w_zo  = w_if + W_IFS;
    __half* w_rt  = w_zo + W_IFS;
    __half* w_up  = w_rt + W_RT;
    __half* w_dn  = w_up + W_UP;
    __half* w_emb = w_dn + W_DN;
    __half* act_h = Wx_h;   // alias

    // scan smem: resident B 132,096 + A stages 55,296 + Wx tile 18,432
    //          = 205,824 B (rawS 33,792 B aliases the A stages).
    const int SCAN_SMEM = 64 * 1032 * 2 + 3 * 128 * 72 * 2 + 128 * 72 * 2;
    const int GEMM_SMEM = 2 * 2 * 128 * 72 * 2;             // 73,728 B (2-stage BK=64)
    cudaFuncSetAttribute(scan_kernel,
                         cudaFuncAttributeMaxDynamicSharedMemorySize, SCAN_SMEM);
    cudaFuncSetAttribute(gemm_f16_kernel<true,false,false,false>,
                         cudaFuncAttributeMaxDynamicSharedMemorySize, GEMM_SMEM);
    cudaFuncSetAttribute(gemm_f16_kernel<true,false,false,true>,
                         cudaFuncAttributeMaxDynamicSharedMemorySize, GEMM_SMEM);
    cudaFuncSetAttribute(gemm_f16_kernel<false,false,true,false>,
                         cudaFuncAttributeMaxDynamicSharedMemorySize, GEMM_SMEM);
    cudaFuncSetAttribute(gemm_f16_kernel<false,true,false,false>,
                         cudaFuncAttributeMaxDynamicSharedMemorySize, GEMM_SMEM);

    // 0: one-shot conversions
    prep_kernel<<<(unsigned)((PREP_N + 255) / 256), 256>>>(
        Wi, Wf, Wz, Wo, R, ff_up, ff_dn, emb_w, x, w_h, x_h);

    // 1: h = x_h @ emb_w^T + emb_b (fp32 out)
    gemm_f16_kernel<false,false,true,false>
        <<<dim3(HH/128, NTOK/128), 256, GEMM_SMEM>>>(x_h, II, w_emb, II,
                                                     g_h, HH, emb_b, II);

    for (int l = 0; l < LL; l++) {
        // xn = LN(h)*ln1_w  (half out)
        ln_warp_kernel<true><<<NTOK/8, 256>>>(g_h, HH, ln1_w + (size_t)l*HH,
                                              xn_h, HH);
        // Wx cols [2048,4096) = [z|o] = xn @ [Wz;Wo]^T
        gemm_f16_kernel<true,false,false,false>
            <<<dim3(16, 200), 256, GEMM_SMEM>>>(xn_h, HH,
                                                w_zo + (size_t)l*2*HH*HH, HH,
                                                Wx_h + 2048, H4, nullptr, HH);
        // xc = silu(causal_conv(xn))
        conv_silu_kernel<<<(NTOK*HH/4)/256, 256>>>(xn_h,
            conv_w + (size_t)l*HH*KK, conv_b + (size_t)l*HH, xc_h);
        // Wx cols [0,2048) = [i|f] = xc @ [Wi;Wf]^T
        gemm_f16_kernel<true,false,false,false>
            <<<dim3(16, 200), 256, GEMM_SMEM>>>(xc_h, HH,
                                                w_if + (size_t)l*2*HH*HH, HH,
                                                Wx_h, H4, nullptr, HH);

        // persistent fused scan: all 100 steps in one launch
        scan_kernel<<<SC_CTAS, 256, SCAN_SMEM>>>(
            Wx_h, w_rt + (size_t)l*H4*HH, cell_b + (size_t)l*H4,
            yb0, yb1, g_yseq);

        // fused: h += LN(yseq)*gn ; fn = LN(h)*ln2 (half out, into xn_h)
        lnadd_ln2_kernel<<<NTOK/8, 256>>>(g_yseq, gn_w + (size_t)l*HH,
                                          ln2_w + (size_t)l*HH, g_h, xn_h);

        // FFN: act = gelu(g)*v fused in up-GEMM epilogue ; h += act @ ff_dn^T
        gemm_f16_kernel<true,false,false,true>
            <<<dim3(U2/128, 200), 256, GEMM_SMEM>>>(xn_h, HH,
                                                    w_up + (size_t)l*U2*HH, HH,
                                                    act_h, UU, nullptr, HH);
        gemm_f16_kernel<false,true,false,false>
            <<<dim3(8, 200), 256, GEMM_SMEM>>>(act_h, UU,
                                               w_dn + (size_t)l*HH*UU, UU,
                                               g_h, HH, nullptr, UU);
    }

    // post-LN only needed for last timestep (fp32 out)
    ln_warp_kernel<false><<<BB/8, 256>>>(g_h + (size_t)(SS-1)*HH, (size_t)SS*HH,
                                         post_w, g_last, HH);
    // out = last @ fc_w^T + fc_b
    gemm_fc_kernel<64,128,16,4,8>
        <<<dim3(OO/128, BB/64), 256>>>(g_last, HH, fc_w, HH,
                                       out, OO, fc_b, HH);
}